// round 5
// baseline (speedup 1.0000x reference)
#include <cuda_runtime.h>
#include <cuda_bf16.h>
#include <cstdint>

// ---------------------------------------------------------------------------
// Problem constants
// ---------------------------------------------------------------------------
#define Bb   8
#define HIN  256
#define WIN  256
#define H2   128
#define W2   128
#define Nn   16
#define Mm   32
#define Ss   128
#define Tt   (Bb*H2*W2)          // 131072 tokens
#define ALPHA 1e-6f

// ---------------------------------------------------------------------------
// Scratch buffers (static device globals; no cudaMalloc allowed)
// ---------------------------------------------------------------------------
__device__ float g_a1n [Bb*Nn*HIN*WIN];
__device__ float g_a1s [(size_t)Bb*Ss*HIN*WIN];
__device__ float g_z   [(size_t)Tt*Nn];
__device__ float g_ts  [(size_t)Tt*Ss];
__device__ float g_w   [(size_t)Tt*Mm];
__device__ float g_part[(size_t)1024*32*160];
__device__ float g_gu  [32*160];
__device__ float g_vnew[Mm*Ss];
__device__ float g_d0m [(size_t)Bb*Ss*H2*W2];
__device__ float g_dec [(size_t)Bb*3*HIN*WIN];

// ---------------------------------------------------------------------------
// cp.async helpers
// ---------------------------------------------------------------------------
__device__ __forceinline__ void cp_async4(unsigned dst, const float* src, int sz) {
    asm volatile("cp.async.ca.shared.global [%0], [%1], 4, %2;\n"
                 :: "r"(dst), "l"(src), "r"(sz));
}
__device__ __forceinline__ void cp_async4u(unsigned dst, const float* src) {
    asm volatile("cp.async.ca.shared.global [%0], [%1], 4;\n"
                 :: "r"(dst), "l"(src));
}
__device__ __forceinline__ void cp_commit() {
    asm volatile("cp.async.commit_group;\n" ::: "memory");
}
__device__ __forceinline__ void cp_wait0() {
    asm volatile("cp.async.wait_group 0;\n" ::: "memory");
}

// ---------------------------------------------------------------------------
// Fast fused conv3x3 + bias + SiLU.  pad=1, stride in {1,2}.
// 256 threads -> 32x32 output tile; thread = 4 x-pixels x 8 channels.
// STRIDE=2: parity-split smem input tile (lane-contiguous LDS.128).
// Staging via cp.async (zfill OOB) in a ROLLED loop (register-lean ->
// 3 blocks/SM). Double buffered, one barrier per input channel.
// ---------------------------------------------------------------------------
template<int CIN, int OUTC, int STRIDE, bool TOKEN_OUT>
__global__ void __launch_bounds__(256, 3) convfast(
    const float* __restrict__ in, const float* __restrict__ wgt,
    const float* __restrict__ bias, float* __restrict__ out,
    int Hin, int Win, int Ho, int Wo)
{
    constexpr int COG  = 8;
    constexpr int ITX  = 31*STRIDE + 3;          // 65 (s2) / 34 (s1)
    constexpr int ITY  = ITX;
    constexpr int ODD  = 36;                     // odd-plane float offset (s2)
    constexpr int SRS  = (STRIDE==2) ? 72 : 36;  // smem row stride (floats)
    constexpr int ELEMS = ITY * ITX;             // 4225 / 1156
    constexpr int NIT  = (ELEMS + 255) / 256;    // 17 / 5

    __shared__ float sIn[2][ITY*SRS];
    __shared__ float sW[2][COG*9 + 8];

    const int tid = threadIdx.x;
    const int tx = tid & 7, ty = tid >> 3;
    const int groups = OUTC / COG;
    const int b = blockIdx.z / groups;
    const int cbase = (blockIdx.z % groups) * COG;
    const int X0 = blockIdx.x * 32, Y0 = blockIdx.y * 32;
    const int iy0 = Y0*STRIDE - 1, ix0 = X0*STRIDE - 1;
    const size_t HW = (size_t)Hin * Win;
    const float* inb = in + (size_t)b * CIN * HW;

    const int wc = tid / 9, wtap = tid - wc*9;   // weight stage slot (tid<72)

    // ---- staging: rolled loop, per-iteration magic-divide addressing.
    auto stage = [&](int buf, int cin) {
        const float* ic = inb + (size_t)cin * HW;
        unsigned sbase = (unsigned)__cvta_generic_to_shared(&sIn[buf][0]);
#pragma unroll 1
        for (int k = 0; k < NIT; k++) {
            int f = k*256 + tid;
            if (f < ELEMS) {
                int r = f / ITX;
                int c = f - r*ITX;
                int ih = iy0 + r, iw = ix0 + c;
                bool ok = ((unsigned)ih < (unsigned)Hin) &
                          ((unsigned)iw < (unsigned)Win);
                int sof;
                if (STRIDE == 2) sof = r*SRS + ((c & 1) ? ODD : 0) + (c >> 1);
                else             sof = r*SRS + c;
                const float* src = ic + (ok ? (ih*Win + iw) : 0);
                cp_async4(sbase + sof*4, src, ok ? 4 : 0);
            }
        }
        if (tid < COG*9) {
            unsigned dst = (unsigned)__cvta_generic_to_shared(
                               &sW[buf][wtap*COG + wc]);
            cp_async4u(dst, wgt + ((size_t)(cbase+wc)*CIN + cin)*9 + wtap);
        }
    };

    stage(0, 0);
    cp_commit();
    cp_wait0();
    __syncthreads();

    float acc[4][COG];
#pragma unroll
    for (int j = 0; j < 4; j++)
#pragma unroll
        for (int c = 0; c < COG; c++) acc[j][c] = 0.f;

    for (int cin = 0; cin < CIN; cin++) {
        const int cur = cin & 1;
        if (cin + 1 < CIN) { stage(cur^1, cin+1); cp_commit(); }

        const float* sc  = sIn[cur];
        const float* swp = sW[cur];
#pragma unroll
        for (int dy = 0; dy < 3; dy++) {
            float V[3][4];
            if (STRIDE == 2) {
                const float* rp = sc + (ty*2 + dy)*SRS;
                float4 E = *(const float4*)(rp + tx*4);
                float  e4 = rp[tx*4 + 4];
                float4 O = *(const float4*)(rp + ODD + tx*4);
                V[0][0]=E.x; V[0][1]=E.y; V[0][2]=E.z; V[0][3]=E.w;
                V[1][0]=O.x; V[1][1]=O.y; V[1][2]=O.z; V[1][3]=O.w;
                V[2][0]=E.y; V[2][1]=E.z; V[2][2]=E.w; V[2][3]=e4;
            } else {
                const float* rp = sc + (ty + dy)*SRS + tx*4;
                float4 A = *(const float4*)rp;
                float2 Bv = *(const float2*)(rp + 4);
                float iv6[6] = {A.x, A.y, A.z, A.w, Bv.x, Bv.y};
#pragma unroll
                for (int dx = 0; dx < 3; dx++)
#pragma unroll
                    for (int k = 0; k < 4; k++) V[dx][k] = iv6[k+dx];
            }
#pragma unroll
            for (int dx = 0; dx < 3; dx++) {
                float4 w0 = *(const float4*)(swp + (dy*3+dx)*COG);
                float4 w1 = *(const float4*)(swp + (dy*3+dx)*COG + 4);
#pragma unroll
                for (int j = 0; j < 4; j++) {
                    float v = V[dx][j];
                    acc[j][0] += v*w0.x; acc[j][1] += v*w0.y;
                    acc[j][2] += v*w0.z; acc[j][3] += v*w0.w;
                    acc[j][4] += v*w1.x; acc[j][5] += v*w1.y;
                    acc[j][6] += v*w1.z; acc[j][7] += v*w1.w;
                }
            }
        }
        if (cin + 1 < CIN) cp_wait0();
        __syncthreads();
    }

    // -------- epilogue: bias + SiLU + vectorized stores
    float bv[COG];
#pragma unroll
    for (int c = 0; c < COG; c++) bv[c] = __ldg(bias + cbase + c);

    const int oy = Y0 + ty;
    if (TOKEN_OUT) {
#pragma unroll
        for (int j = 0; j < 4; j++) {
            float vv[COG];
#pragma unroll
            for (int c = 0; c < COG; c++) {
                float v = acc[j][c] + bv[c];
                vv[c] = v / (1.f + __expf(-v));
            }
            size_t t = ((size_t)b*Ho + oy)*Wo + X0 + tx*4 + j;
            float4* op = (float4*)(out + t*OUTC + cbase);
            op[0] = make_float4(vv[0], vv[1], vv[2], vv[3]);
            op[1] = make_float4(vv[4], vv[5], vv[6], vv[7]);
        }
    } else {
#pragma unroll
        for (int c = 0; c < COG; c++) {
            float4 o;
            float* po = (float*)&o;
#pragma unroll
            for (int j = 0; j < 4; j++) {
                float v = acc[j][c] + bv[c];
                po[j] = v / (1.f + __expf(-v));
            }
            *(float4*)(out + (((size_t)b*OUTC + cbase + c)*Ho + oy)*Wo + X0 + tx*4) = o;
        }
    }
}

// ---------------------------------------------------------------------------
// Legacy conv (used only for the tiny 3->3 decoder conv)
// ---------------------------------------------------------------------------
template<int CIN, int OUTC, int COG, int STRIDE, bool TOKEN_OUT>
__global__ void __launch_bounds__(256) conv3x3(
    const float* __restrict__ in, const float* __restrict__ wgt,
    const float* __restrict__ bias, float* __restrict__ out,
    int Hin, int Win, int Ho, int Wo)
{
    constexpr int ITD = 15*STRIDE + 3;
    __shared__ float sW[COG*CIN*9];
    __shared__ float sIn[ITD*ITD];

    const int tid = threadIdx.x;
    const int groups = OUTC / COG;
    const int b  = blockIdx.z / groups;
    const int cg = blockIdx.z % groups;
    const int cbase = cg * COG;

    for (int i = tid; i < COG*CIN*9; i += 256)
        sW[i] = wgt[(size_t)cbase*CIN*9 + i];

    const int ty = tid >> 4, tx = tid & 15;
    const int oy = blockIdx.y*16 + ty;
    const int ox = blockIdx.x*16 + tx;

    float acc[COG];
#pragma unroll
    for (int c = 0; c < COG; c++) acc[c] = 0.f;

    const float* inb = in + (size_t)b * CIN * Hin * Win;
    const int iy0 = blockIdx.y*16*STRIDE - 1;
    const int ix0 = blockIdx.x*16*STRIDE - 1;
    const int base = (ty*STRIDE)*ITD + tx*STRIDE;

    for (int cin = 0; cin < CIN; cin++) {
        __syncthreads();
        const float* ic = inb + (size_t)cin * Hin * Win;
        for (int i = tid; i < ITD*ITD; i += 256) {
            int r = i / ITD, cc = i - r*ITD;
            int ih = iy0 + r, iw = ix0 + cc;
            float v = 0.f;
            if ((unsigned)ih < (unsigned)Hin && (unsigned)iw < (unsigned)Win)
                v = ic[ih*Win + iw];
            sIn[i] = v;
        }
        __syncthreads();
        const float* wp = sW + cin*9;
#pragma unroll
        for (int dy = 0; dy < 3; dy++)
#pragma unroll
            for (int dx = 0; dx < 3; dx++) {
                float iv = sIn[base + dy*ITD + dx];
#pragma unroll
                for (int c = 0; c < COG; c++)
                    acc[c] += iv * wp[c*CIN*9 + dy*3 + dx];
            }
    }

#pragma unroll
    for (int c = 0; c < COG; c++) {
        float v = acc[c] + bias[cbase + c];
        v = v / (1.f + __expf(-v));
        if (TOKEN_OUT) {
            size_t t = ((size_t)b*Ho + oy)*Wo + ox;
            out[t*OUTC + cbase + c] = v;
        } else {
            out[(((size_t)b*OUTC + cbase + c)*Ho + oy)*Wo + ox] = v;
        }
    }
}

// ---------------------------------------------------------------------------
// Memcell pass 1: w = softmax(z @ K^T / 4) per token.
// ---------------------------------------------------------------------------
__global__ void __launch_bounds__(256) memcell_softmax(
    const float* __restrict__ z, const float* __restrict__ ck,
    float* __restrict__ wout)
{
    __shared__ float sK[Mm*Nn];
    const int tid = threadIdx.x;
    for (int i = tid; i < Mm*Nn; i += 256) sK[i] = ck[i];
    __syncthreads();

    const int t = blockIdx.x*256 + tid;
    const float4* zp = (const float4*)(z + (size_t)t*Nn);
    float4 z0 = zp[0], z1 = zp[1], z2 = zp[2], z3 = zp[3];

    float s[Mm];
    float mx = -1e30f;
#pragma unroll
    for (int m = 0; m < Mm; m++) {
        const float* k = sK + m*Nn;
        float d = z0.x*k[0] + z0.y*k[1] + z0.z*k[2] + z0.w*k[3]
                + z1.x*k[4] + z1.y*k[5] + z1.z*k[6] + z1.w*k[7]
                + z2.x*k[8] + z2.y*k[9] + z2.z*k[10]+ z2.w*k[11]
                + z3.x*k[12]+ z3.y*k[13]+ z3.z*k[14]+ z3.w*k[15];
        d *= 0.25f;
        s[m] = d;
        mx = fmaxf(mx, d);
    }
    float sum = 0.f;
#pragma unroll
    for (int m = 0; m < Mm; m++) { s[m] = __expf(s[m]-mx); sum += s[m]; }
    float inv = 1.f / sum;
    float4* wo = (float4*)(wout + (size_t)t*Mm);
#pragma unroll
    for (int j = 0; j < Mm/4; j++) {
        float4 v; v.x = s[4*j]*inv; v.y = s[4*j+1]*inv;
        v.z = s[4*j+2]*inv; v.w = s[4*j+3]*inv;
        wo[j] = v;
    }
}

// ---------------------------------------------------------------------------
// Memcell pass 2: block partials of [G | U], G = W^T W, U = W^T t_star.
// ---------------------------------------------------------------------------
__global__ void __launch_bounds__(256) memcell_outer(
    const float* __restrict__ wmat, const float* __restrict__ ts,
    float* __restrict__ part)
{
    __shared__ float sv[8*160];
    const int tid = threadIdx.x;
    const int ti = tid >> 5;
    const int tj = tid & 31;
    float acc[4][5];
#pragma unroll
    for (int a = 0; a < 4; a++)
#pragma unroll
        for (int q = 0; q < 5; q++) acc[a][q] = 0.f;

    const int tokb = blockIdx.x * 128;
    for (int ch = 0; ch < 128; ch += 8) {
        __syncthreads();
#pragma unroll
        for (int l = 0; l < 5; l++) {
            int idx = l*256 + tid;
            int tk = idx / 160, f = idx - tk*160;
            int t = tokb + ch + tk;
            sv[tk*160 + f] = (f < 32) ? wmat[(size_t)t*32 + f]
                                      : ts[(size_t)t*128 + (f-32)];
        }
        __syncthreads();
#pragma unroll
        for (int tk = 0; tk < 8; tk++) {
            float wi[4], vj[5];
#pragma unroll
            for (int a = 0; a < 4; a++) wi[a] = sv[tk*160 + ti*4 + a];
#pragma unroll
            for (int q = 0; q < 5; q++) vj[q] = sv[tk*160 + tj*5 + q];
#pragma unroll
            for (int a = 0; a < 4; a++)
#pragma unroll
                for (int q = 0; q < 5; q++) acc[a][q] += wi[a]*vj[q];
        }
    }
    float* pp = part + (size_t)blockIdx.x * 5120;
#pragma unroll
    for (int a = 0; a < 4; a++)
#pragma unroll
        for (int q = 0; q < 5; q++)
            pp[(ti*4+a)*160 + tj*5 + q] = acc[a][q];
}

__global__ void __launch_bounds__(256) reduce_partials(
    const float* __restrict__ part, float* __restrict__ gu)
{
    int cell = blockIdx.x*256 + threadIdx.x;
    float s = 0.f;
#pragma unroll 8
    for (int p = 0; p < 1024; p++) s += part[(size_t)p*5120 + cell];
    gu[cell] = s;
}

__global__ void __launch_bounds__(256) cell_update(
    const float* __restrict__ gu, const float* __restrict__ cv,
    float* __restrict__ vnew)
{
    __shared__ float sG[Mm*Mm];
    __shared__ float sV[Mm*Ss];
    const int tid = threadIdx.x;
    for (int i = tid; i < Mm*Mm; i += 256) {
        int m = i >> 5, j = i & 31;
        sG[i] = gu[m*160 + j];
    }
    for (int i = tid; i < Mm*Ss; i += 256) sV[i] = cv[i];
    __syncthreads();
    for (int k = 0; k < 16; k++) {
        int cell = k*256 + tid;
        int m = cell >> 7, s0 = cell & 127;
        float d = gu[m*160 + 32 + s0];
#pragma unroll
        for (int mp = 0; mp < Mm; mp++) d -= sG[m*32 + mp] * sV[mp*128 + s0];
        vnew[cell] = sV[cell] + ALPHA * d;
    }
}

// ---------------------------------------------------------------------------
// Memcell pass 3: t_read = W @ cell_v_new -> NCHW [B,S,H2,W2].
// ---------------------------------------------------------------------------
__global__ void __launch_bounds__(256) memcell_read(
    const float* __restrict__ wmat, const float* __restrict__ vnew,
    float* __restrict__ d0m)
{
    __shared__ float sV[Mm*Ss];
    __shared__ float sW[64*33];
    const int tid = threadIdx.x;
    for (int i = tid; i < Mm*Ss; i += 256) sV[i] = vnew[i];
    const int tbase = blockIdx.x * 64;
    for (int i = tid; i < 64*32; i += 256) {
        int tk = i >> 5, m = i & 31;
        sW[tk*33 + m] = wmat[(size_t)(tbase + tk)*32 + m];
    }
    __syncthreads();

    const int lane = tid & 31, wid = tid >> 5;
    const int cb = wid * 16;
    float a0[16], a1[16];
#pragma unroll
    for (int c = 0; c < 16; c++) { a0[c] = 0.f; a1[c] = 0.f; }

    const float* w0 = sW + lane*33;
    const float* w1 = sW + (lane + 32)*33;
#pragma unroll 4
    for (int m = 0; m < Mm; m++) {
        float x0 = w0[m], x1 = w1[m];
        const float4* vv = (const float4*)(sV + m*128 + cb);
#pragma unroll
        for (int q = 0; q < 4; q++) {
            float4 v = vv[q];
            a0[q*4+0] += x0*v.x; a0[q*4+1] += x0*v.y;
            a0[q*4+2] += x0*v.z; a0[q*4+3] += x0*v.w;
            a1[q*4+0] += x1*v.x; a1[q*4+1] += x1*v.y;
            a1[q*4+2] += x1*v.z; a1[q*4+3] += x1*v.w;
        }
    }
    const int b = tbase >> 14;
    const int rem = tbase & 16383;
    const int h = rem >> 7;
    const int wcp = rem & 127;
    size_t obase = ((size_t)b*Ss)*((size_t)H2*W2) + (size_t)h*W2 + wcp;
#pragma unroll
    for (int c = 0; c < 16; c++) {
        size_t o = obase + (size_t)(cb + c)*(H2*W2);
        d0m[o + lane]      = a0[c];
        d0m[o + 32 + lane] = a1[c];
    }
}

// ---------------------------------------------------------------------------
// ConvTranspose2d(128->3, k4, s2, p1) + bias + SiLU.
// ---------------------------------------------------------------------------
__global__ void __launch_bounds__(256) deconv_kernel(
    const float* __restrict__ in, const float* __restrict__ dw,
    const float* __restrict__ db, float* __restrict__ out)
{
    __shared__ float sWd[4*128*12];              // [parity][cin][o][k] 24.6 KB
    __shared__ float sIn[16*100];                // 16 cins x 10x10
    const int tid = threadIdx.x;
    for (int i = tid; i < 4*128*12; i += 256) {
        int p = i / 1536, rem = i - p*1536;
        int cin = rem / 12, rr = rem - cin*12;
        int o = rr >> 2, k = rr & 3;
        int py = p >> 1, px = p & 1;
        int ky = py + 2*(k >> 1), kx = px + 2*(k & 1);
        sWd[i] = dw[cin*48 + o*16 + ky*4 + kx];
    }

    const int b  = blockIdx.z;
    const int Y0 = blockIdx.y*16, X0 = blockIdx.x*16;
    const int ty = tid >> 4, tx = tid & 15;
    const int y = Y0 + ty, x = X0 + tx;
    const int hb = (Y0 >> 1) - 1, wb = (X0 >> 1) - 1;

    const int py = (y + 1) & 1, px = (x + 1) & 1;
    const int hs0 = ((y + 1 - py) >> 1) - hb;
    const int ws0 = ((x + 1 - px) >> 1) - wb;

    const float* wp = sWd + (py*2 + px)*1536;
    float acc[3] = {0.f, 0.f, 0.f};
    const float* inb = in + (size_t)b * Ss * H2 * W2;

    for (int c0 = 0; c0 < Ss; c0 += 16) {
        __syncthreads();
        for (int i = tid; i < 1600; i += 256) {
            int c = i / 100, rr = i - c*100;
            int r = rr / 10, cc = rr - r*10;
            int h = hb + r, w = wb + cc;
            float v = 0.f;
            if ((unsigned)h < (unsigned)H2 && (unsigned)w < (unsigned)W2)
                v = inb[((size_t)(c0 + c)*H2 + h)*W2 + w];
            sIn[i] = v;
        }
        __syncthreads();
#pragma unroll
        for (int c = 0; c < 16; c++) {
            const float* sc = sIn + c*100;
            float i00 = sc[hs0*10 + ws0];
            float i01 = sc[hs0*10 + ws0 - 1];
            float i10 = sc[(hs0-1)*10 + ws0];
            float i11 = sc[(hs0-1)*10 + ws0 - 1];
            const float4* w4 = (const float4*)(wp + (c0 + c)*12);
#pragma unroll
            for (int o = 0; o < 3; o++) {
                float4 w = w4[o];
                acc[o] += i00*w.x + i01*w.y + i10*w.z + i11*w.w;
            }
        }
    }
#pragma unroll
    for (int o = 0; o < 3; o++) {
        float v = acc[o] + db[o];
        v = v / (1.f + __expf(-v));
        out[(((size_t)b*3 + o)*HIN + y)*WIN + x] = v;
    }
}

// ---------------------------------------------------------------------------
// Launch sequence
// ---------------------------------------------------------------------------
extern "C" void kernel_launch(void* const* d_in, const int* in_sizes, int n_in,
                              void* d_out, int out_size)
{
    const float* x      = (const float*)d_in[0];
    const float* e0n_w1 = (const float*)d_in[1];
    const float* e0n_b1 = (const float*)d_in[2];
    const float* e0n_w2 = (const float*)d_in[3];
    const float* e0n_b2 = (const float*)d_in[4];
    const float* e0s_w1 = (const float*)d_in[5];
    const float* e0s_b1 = (const float*)d_in[6];
    const float* e0s_w2 = (const float*)d_in[7];
    const float* e0s_b2 = (const float*)d_in[8];
    const float* d0_dw  = (const float*)d_in[9];
    const float* d0_db  = (const float*)d_in[10];
    const float* d0_cw  = (const float*)d_in[11];
    const float* d0_cb  = (const float*)d_in[12];
    const float* cell_k = (const float*)d_in[13];
    const float* cell_v = (const float*)d_in[14];
    float* outp = (float*)d_out;

    void *p_a1n, *p_a1s, *p_z, *p_ts, *p_w, *p_part, *p_gu, *p_vnew, *p_d0m, *p_dec;
    cudaGetSymbolAddress(&p_a1n, g_a1n);
    cudaGetSymbolAddress(&p_a1s, g_a1s);
    cudaGetSymbolAddress(&p_z,   g_z);
    cudaGetSymbolAddress(&p_ts,  g_ts);
    cudaGetSymbolAddress(&p_w,   g_w);
    cudaGetSymbolAddress(&p_part,g_part);
    cudaGetSymbolAddress(&p_gu,  g_gu);
    cudaGetSymbolAddress(&p_vnew,g_vnew);
    cudaGetSymbolAddress(&p_d0m, g_d0m);
    cudaGetSymbolAddress(&p_dec, g_dec);

    // Encoders
    convfast<3,16,1,false><<<dim3(8,8,Bb*2),256>>>(
        x, e0n_w1, e0n_b1, (float*)p_a1n, HIN, WIN, HIN, WIN);
    convfast<3,128,1,false><<<dim3(8,8,Bb*16),256>>>(
        x, e0s_w1, e0s_b1, (float*)p_a1s, HIN, WIN, HIN, WIN);
    convfast<16,16,2,true><<<dim3(4,4,Bb*2),256>>>(
        (const float*)p_a1n, e0n_w2, e0n_b2, (float*)p_z, HIN, WIN, H2, W2);
    convfast<128,128,2,true><<<dim3(4,4,Bb*16),256>>>(
        (const float*)p_a1s, e0s_w2, e0s_b2, (float*)p_ts, HIN, WIN, H2, W2);

    // Memcell
    memcell_softmax<<<Tt/256,256>>>((const float*)p_z, cell_k, (float*)p_w);
    memcell_outer<<<1024,256>>>((const float*)p_w, (const float*)p_ts, (float*)p_part);
    reduce_partials<<<20,256>>>((const float*)p_part, (float*)p_gu);
    cell_update<<<1,256>>>((const float*)p_gu, cell_v, (float*)p_vnew);
    memcell_read<<<Tt/64,256>>>((const float*)p_w, (const float*)p_vnew, (float*)p_d0m);

    // Decoder
    deconv_kernel<<<dim3(16,16,Bb),256>>>(
        (const float*)p_d0m, d0_dw, d0_db, (float*)p_dec);
    conv3x3<3,3,3,1,false><<<dim3(16,16,Bb),256>>>(
        (const float*)p_dec, d0_cw, d0_cb, outp, HIN, WIN, HIN, WIN);
}

// round 7
// speedup vs baseline: 1.3362x; 1.3362x over previous
#include <cuda_runtime.h>
#include <cuda_bf16.h>
#include <cstdint>

// ---------------------------------------------------------------------------
// Problem constants
// ---------------------------------------------------------------------------
#define Bb   8
#define HIN  256
#define WIN  256
#define H2   128
#define W2   128
#define Nn   16
#define Mm   32
#define Ss   128
#define Tt   (Bb*H2*W2)          // 131072 tokens
#define ALPHA 1e-6f

// ---------------------------------------------------------------------------
// Scratch buffers (static device globals; no cudaMalloc allowed)
// ---------------------------------------------------------------------------
__device__ float g_a1n [Bb*Nn*HIN*WIN];
__device__ float g_a1s [(size_t)Bb*Ss*HIN*WIN];
__device__ float g_z   [(size_t)Tt*Nn];
__device__ float g_ts  [(size_t)Tt*Ss];
__device__ float g_w   [(size_t)Tt*Mm];
__device__ float g_part[(size_t)1024*32*160];
__device__ float g_gu  [32*160];
__device__ float g_vnew[Mm*Ss];
__device__ float g_d0m [(size_t)Bb*Ss*H2*W2];
__device__ float g_dec [(size_t)Bb*3*HIN*WIN];

// ---------------------------------------------------------------------------
// cp.async helpers
// ---------------------------------------------------------------------------
__device__ __forceinline__ void cp_async4(unsigned dst, const float* src, int sz) {
    asm volatile("cp.async.ca.shared.global [%0], [%1], 4, %2;\n"
                 :: "r"(dst), "l"(src), "r"(sz));
}
__device__ __forceinline__ void cp_async4u(unsigned dst, const float* src) {
    asm volatile("cp.async.ca.shared.global [%0], [%1], 4;\n"
                 :: "r"(dst), "l"(src));
}
__device__ __forceinline__ void cp_commit() {
    asm volatile("cp.async.commit_group;\n" ::: "memory");
}
__device__ __forceinline__ void cp_wait0() {
    asm volatile("cp.async.wait_group 0;\n" ::: "memory");
}

// ---------------------------------------------------------------------------
// Fast fused conv3x3 + bias + SiLU.  pad=1, stride in {1,2}.
// 256 threads -> 32x32 output tile; thread = 4 x-pixels x 8 channels.
// STRIDE=2: parity-split smem input tile (lane-contiguous LDS.128).
// Staging addresses are cin-invariant: computed ONCE into smem tables;
// per-cin staging is 2 LDS + cp.async per element -> near-zero ALU.
// Double buffered input (dynamic smem; >48KB combined -> opt-in attr set
// host-side), one barrier per input channel, 3 blocks/SM.
// ---------------------------------------------------------------------------
template<int CIN, int OUTC, int STRIDE, bool TOKEN_OUT>
__global__ void __launch_bounds__(256, 3) convfast(
    const float* __restrict__ in, const float* __restrict__ wgt,
    const float* __restrict__ bias, float* __restrict__ out,
    int Hin, int Win, int Ho, int Wo)
{
    constexpr int COG  = 8;
    constexpr int ITX  = 31*STRIDE + 3;          // 65 (s2) / 34 (s1)
    constexpr int ODD  = 36;                     // odd-plane float offset (s2)
    constexpr int SRS  = (STRIDE==2) ? 72 : 36;  // smem row stride (floats)
    constexpr int ELEMS = ITX * ITX;             // 4225 / 1156
    constexpr int NIT  = (ELEMS + 255) / 256;    // 17 / 5
    constexpr int PLANE = ITX * SRS;             // floats per buffer

    extern __shared__ float sIn[];               // [2][PLANE]
    __shared__ float sW[2][COG*9 + 8];
    __shared__ unsigned short tSof[NIT*256];     // staging smem offsets (float idx)
    __shared__ int            tGof[NIT*256];     // staging gmem offsets (-1 = zfill)

    const int tid = threadIdx.x;
    const int tx = tid & 7, ty = tid >> 3;
    const int groups = OUTC / COG;
    const int b = blockIdx.z / groups;
    const int cbase = (blockIdx.z % groups) * COG;
    const int X0 = blockIdx.x * 32, Y0 = blockIdx.y * 32;
    const int iy0 = Y0*STRIDE - 1, ix0 = X0*STRIDE - 1;
    const size_t HW = (size_t)Hin * Win;
    const float* inb = in + (size_t)b * CIN * HW;

    const int wc = tid / 9, wtap = tid - wc*9;   // weight stage slot (tid<72)

    // ---- build staging tables ONCE (each thread writes & reads its own slots)
#pragma unroll
    for (int k = 0; k < NIT; k++) {
        int f = k*256 + tid;
        unsigned short sof = 0xFFFF;
        int gof = -1;
        if (f < ELEMS) {
            int r = f / ITX, c = f - r*ITX;
            int ih = iy0 + r, iw = ix0 + c;
            if (STRIDE == 2) sof = (unsigned short)(r*SRS + ((c & 1) ? ODD : 0) + (c >> 1));
            else             sof = (unsigned short)(r*SRS + c);
            gof = ((unsigned)ih < (unsigned)Hin && (unsigned)iw < (unsigned)Win)
                  ? (ih*Win + iw) : -1;
        }
        tSof[k*256 + tid] = sof;
        tGof[k*256 + tid] = gof;
    }

    // ---- staging: table-driven, near-zero ALU
    const unsigned sb0 = (unsigned)__cvta_generic_to_shared(sIn);
    auto stage = [&](int buf, int cin) {
        const float* ic = inb + (size_t)cin * HW;
        const unsigned sb = sb0 + (unsigned)buf * (PLANE*4);
#pragma unroll
        for (int k = 0; k < NIT; k++) {
            unsigned sof = tSof[k*256 + tid];
            int gof = tGof[k*256 + tid];
            if (sof != 0xFFFFu)
                cp_async4(sb + sof*4, ic + (gof < 0 ? 0 : gof), gof < 0 ? 0 : 4);
        }
        if (tid < COG*9) {
            unsigned dst = (unsigned)__cvta_generic_to_shared(
                               &sW[buf][wtap*COG + wc]);
            cp_async4u(dst, wgt + ((size_t)(cbase+wc)*CIN + cin)*9 + wtap);
        }
    };

    stage(0, 0);
    cp_commit();
    cp_wait0();
    __syncthreads();

    float acc[4][COG];
#pragma unroll
    for (int j = 0; j < 4; j++)
#pragma unroll
        for (int c = 0; c < COG; c++) acc[j][c] = 0.f;

    for (int cin = 0; cin < CIN; cin++) {
        const int cur = cin & 1;
        if (cin + 1 < CIN) { stage(cur^1, cin+1); cp_commit(); }

        const float* sc  = sIn + cur*PLANE;
        const float* swp = sW[cur];
#pragma unroll
        for (int dy = 0; dy < 3; dy++) {
            float V[3][4];
            if (STRIDE == 2) {
                const float* rp = sc + (ty*2 + dy)*SRS;
                float4 E = *(const float4*)(rp + tx*4);
                float  e4 = rp[tx*4 + 4];
                float4 O = *(const float4*)(rp + ODD + tx*4);
                V[0][0]=E.x; V[0][1]=E.y; V[0][2]=E.z; V[0][3]=E.w;
                V[1][0]=O.x; V[1][1]=O.y; V[1][2]=O.z; V[1][3]=O.w;
                V[2][0]=E.y; V[2][1]=E.z; V[2][2]=E.w; V[2][3]=e4;
            } else {
                const float* rp = sc + (ty + dy)*SRS + tx*4;
                float4 A = *(const float4*)rp;
                float2 Bv = *(const float2*)(rp + 4);
                float iv6[6] = {A.x, A.y, A.z, A.w, Bv.x, Bv.y};
#pragma unroll
                for (int dx = 0; dx < 3; dx++)
#pragma unroll
                    for (int k = 0; k < 4; k++) V[dx][k] = iv6[k+dx];
            }
#pragma unroll
            for (int dx = 0; dx < 3; dx++) {
                float4 w0 = *(const float4*)(swp + (dy*3+dx)*COG);
                float4 w1 = *(const float4*)(swp + (dy*3+dx)*COG + 4);
#pragma unroll
                for (int j = 0; j < 4; j++) {
                    float v = V[dx][j];
                    acc[j][0] += v*w0.x; acc[j][1] += v*w0.y;
                    acc[j][2] += v*w0.z; acc[j][3] += v*w0.w;
                    acc[j][4] += v*w1.x; acc[j][5] += v*w1.y;
                    acc[j][6] += v*w1.z; acc[j][7] += v*w1.w;
                }
            }
        }
        if (cin + 1 < CIN) cp_wait0();
        __syncthreads();
    }

    // -------- epilogue: bias + SiLU + vectorized stores
    float bv[COG];
#pragma unroll
    for (int c = 0; c < COG; c++) bv[c] = __ldg(bias + cbase + c);

    const int oy = Y0 + ty;
    if (TOKEN_OUT) {
#pragma unroll
        for (int j = 0; j < 4; j++) {
            float vv[COG];
#pragma unroll
            for (int c = 0; c < COG; c++) {
                float v = acc[j][c] + bv[c];
                vv[c] = v / (1.f + __expf(-v));
            }
            size_t t = ((size_t)b*Ho + oy)*Wo + X0 + tx*4 + j;
            float4* op = (float4*)(out + t*OUTC + cbase);
            op[0] = make_float4(vv[0], vv[1], vv[2], vv[3]);
            op[1] = make_float4(vv[4], vv[5], vv[6], vv[7]);
        }
    } else {
#pragma unroll
        for (int c = 0; c < COG; c++) {
            float4 o;
            float* po = (float*)&o;
#pragma unroll
            for (int j = 0; j < 4; j++) {
                float v = acc[j][c] + bv[c];
                po[j] = v / (1.f + __expf(-v));
            }
            *(float4*)(out + (((size_t)b*OUTC + cbase + c)*Ho + oy)*Wo + X0 + tx*4) = o;
        }
    }
}

// ---------------------------------------------------------------------------
// Legacy conv (used only for the tiny 3->3 decoder conv)
// ---------------------------------------------------------------------------
template<int CIN, int OUTC, int COG, int STRIDE, bool TOKEN_OUT>
__global__ void __launch_bounds__(256) conv3x3(
    const float* __restrict__ in, const float* __restrict__ wgt,
    const float* __restrict__ bias, float* __restrict__ out,
    int Hin, int Win, int Ho, int Wo)
{
    constexpr int ITD = 15*STRIDE + 3;
    __shared__ float sW[COG*CIN*9];
    __shared__ float sIn[ITD*ITD];

    const int tid = threadIdx.x;
    const int groups = OUTC / COG;
    const int b  = blockIdx.z / groups;
    const int cg = blockIdx.z % groups;
    const int cbase = cg * COG;

    for (int i = tid; i < COG*CIN*9; i += 256)
        sW[i] = wgt[(size_t)cbase*CIN*9 + i];

    const int ty = tid >> 4, tx = tid & 15;
    const int oy = blockIdx.y*16 + ty;
    const int ox = blockIdx.x*16 + tx;

    float acc[COG];
#pragma unroll
    for (int c = 0; c < COG; c++) acc[c] = 0.f;

    const float* inb = in + (size_t)b * CIN * Hin * Win;
    const int iy0 = blockIdx.y*16*STRIDE - 1;
    const int ix0 = blockIdx.x*16*STRIDE - 1;
    const int base = (ty*STRIDE)*ITD + tx*STRIDE;

    for (int cin = 0; cin < CIN; cin++) {
        __syncthreads();
        const float* ic = inb + (size_t)cin * Hin * Win;
        for (int i = tid; i < ITD*ITD; i += 256) {
            int r = i / ITD, cc = i - r*ITD;
            int ih = iy0 + r, iw = ix0 + cc;
            float v = 0.f;
            if ((unsigned)ih < (unsigned)Hin && (unsigned)iw < (unsigned)Win)
                v = ic[ih*Win + iw];
            sIn[i] = v;
        }
        __syncthreads();
        const float* wp = sW + cin*9;
#pragma unroll
        for (int dy = 0; dy < 3; dy++)
#pragma unroll
            for (int dx = 0; dx < 3; dx++) {
                float iv = sIn[base + dy*ITD + dx];
#pragma unroll
                for (int c = 0; c < COG; c++)
                    acc[c] += iv * wp[c*CIN*9 + dy*3 + dx];
            }
    }

#pragma unroll
    for (int c = 0; c < COG; c++) {
        float v = acc[c] + bias[cbase + c];
        v = v / (1.f + __expf(-v));
        if (TOKEN_OUT) {
            size_t t = ((size_t)b*Ho + oy)*Wo + ox;
            out[t*OUTC + cbase + c] = v;
        } else {
            out[(((size_t)b*OUTC + cbase + c)*Ho + oy)*Wo + ox] = v;
        }
    }
}

// ---------------------------------------------------------------------------
// Memcell pass 1: w = softmax(z @ K^T / 4) per token.
// ---------------------------------------------------------------------------
__global__ void __launch_bounds__(256) memcell_softmax(
    const float* __restrict__ z, const float* __restrict__ ck,
    float* __restrict__ wout)
{
    __shared__ float sK[Mm*Nn];
    const int tid = threadIdx.x;
    for (int i = tid; i < Mm*Nn; i += 256) sK[i] = ck[i];
    __syncthreads();

    const int t = blockIdx.x*256 + tid;
    const float4* zp = (const float4*)(z + (size_t)t*Nn);
    float4 z0 = zp[0], z1 = zp[1], z2 = zp[2], z3 = zp[3];

    float s[Mm];
    float mx = -1e30f;
#pragma unroll
    for (int m = 0; m < Mm; m++) {
        const float* k = sK + m*Nn;
        float d = z0.x*k[0] + z0.y*k[1] + z0.z*k[2] + z0.w*k[3]
                + z1.x*k[4] + z1.y*k[5] + z1.z*k[6] + z1.w*k[7]
                + z2.x*k[8] + z2.y*k[9] + z2.z*k[10]+ z2.w*k[11]
                + z3.x*k[12]+ z3.y*k[13]+ z3.z*k[14]+ z3.w*k[15];
        d *= 0.25f;
        s[m] = d;
        mx = fmaxf(mx, d);
    }
    float sum = 0.f;
#pragma unroll
    for (int m = 0; m < Mm; m++) { s[m] = __expf(s[m]-mx); sum += s[m]; }
    float inv = 1.f / sum;
    float4* wo = (float4*)(wout + (size_t)t*Mm);
#pragma unroll
    for (int j = 0; j < Mm/4; j++) {
        float4 v; v.x = s[4*j]*inv; v.y = s[4*j+1]*inv;
        v.z = s[4*j+2]*inv; v.w = s[4*j+3]*inv;
        wo[j] = v;
    }
}

// ---------------------------------------------------------------------------
// Memcell pass 2: block partials of [G | U], G = W^T W, U = W^T t_star.
// ---------------------------------------------------------------------------
__global__ void __launch_bounds__(256) memcell_outer(
    const float* __restrict__ wmat, const float* __restrict__ ts,
    float* __restrict__ part)
{
    __shared__ float sv[8*160];
    const int tid = threadIdx.x;
    const int ti = tid >> 5;
    const int tj = tid & 31;
    float acc[4][5];
#pragma unroll
    for (int a = 0; a < 4; a++)
#pragma unroll
        for (int q = 0; q < 5; q++) acc[a][q] = 0.f;

    const int tokb = blockIdx.x * 128;
    for (int ch = 0; ch < 128; ch += 8) {
        __syncthreads();
#pragma unroll
        for (int l = 0; l < 5; l++) {
            int idx = l*256 + tid;
            int tk = idx / 160, f = idx - tk*160;
            int t = tokb + ch + tk;
            sv[tk*160 + f] = (f < 32) ? wmat[(size_t)t*32 + f]
                                      : ts[(size_t)t*128 + (f-32)];
        }
        __syncthreads();
#pragma unroll
        for (int tk = 0; tk < 8; tk++) {
            float wi[4], vj[5];
#pragma unroll
            for (int a = 0; a < 4; a++) wi[a] = sv[tk*160 + ti*4 + a];
#pragma unroll
            for (int q = 0; q < 5; q++) vj[q] = sv[tk*160 + tj*5 + q];
#pragma unroll
            for (int a = 0; a < 4; a++)
#pragma unroll
                for (int q = 0; q < 5; q++) acc[a][q] += wi[a]*vj[q];
        }
    }
    float* pp = part + (size_t)blockIdx.x * 5120;
#pragma unroll
    for (int a = 0; a < 4; a++)
#pragma unroll
        for (int q = 0; q < 5; q++)
            pp[(ti*4+a)*160 + tj*5 + q] = acc[a][q];
}

__global__ void __launch_bounds__(256) reduce_partials(
    const float* __restrict__ part, float* __restrict__ gu)
{
    int cell = blockIdx.x*256 + threadIdx.x;
    float s = 0.f;
#pragma unroll 8
    for (int p = 0; p < 1024; p++) s += part[(size_t)p*5120 + cell];
    gu[cell] = s;
}

__global__ void __launch_bounds__(256) cell_update(
    const float* __restrict__ gu, const float* __restrict__ cv,
    float* __restrict__ vnew)
{
    __shared__ float sG[Mm*Mm];
    __shared__ float sV[Mm*Ss];
    const int tid = threadIdx.x;
    for (int i = tid; i < Mm*Mm; i += 256) {
        int m = i >> 5, j = i & 31;
        sG[i] = gu[m*160 + j];
    }
    for (int i = tid; i < Mm*Ss; i += 256) sV[i] = cv[i];
    __syncthreads();
    for (int k = 0; k < 16; k++) {
        int cell = k*256 + tid;
        int m = cell >> 7, s0 = cell & 127;
        float d = gu[m*160 + 32 + s0];
#pragma unroll
        for (int mp = 0; mp < Mm; mp++) d -= sG[m*32 + mp] * sV[mp*128 + s0];
        vnew[cell] = sV[cell] + ALPHA * d;
    }
}

// ---------------------------------------------------------------------------
// Memcell pass 3: t_read = W @ cell_v_new -> NCHW [B,S,H2,W2].
// ---------------------------------------------------------------------------
__global__ void __launch_bounds__(256) memcell_read(
    const float* __restrict__ wmat, const float* __restrict__ vnew,
    float* __restrict__ d0m)
{
    __shared__ float sV[Mm*Ss];
    __shared__ float sW[64*33];
    const int tid = threadIdx.x;
    for (int i = tid; i < Mm*Ss; i += 256) sV[i] = vnew[i];
    const int tbase = blockIdx.x * 64;
    for (int i = tid; i < 64*32; i += 256) {
        int tk = i >> 5, m = i & 31;
        sW[tk*33 + m] = wmat[(size_t)(tbase + tk)*32 + m];
    }
    __syncthreads();

    const int lane = tid & 31, wid = tid >> 5;
    const int cb = wid * 16;
    float a0[16], a1[16];
#pragma unroll
    for (int c = 0; c < 16; c++) { a0[c] = 0.f; a1[c] = 0.f; }

    const float* w0 = sW + lane*33;
    const float* w1 = sW + (lane + 32)*33;
#pragma unroll 4
    for (int m = 0; m < Mm; m++) {
        float x0 = w0[m], x1 = w1[m];
        const float4* vv = (const float4*)(sV + m*128 + cb);
#pragma unroll
        for (int q = 0; q < 4; q++) {
            float4 v = vv[q];
            a0[q*4+0] += x0*v.x; a0[q*4+1] += x0*v.y;
            a0[q*4+2] += x0*v.z; a0[q*4+3] += x0*v.w;
            a1[q*4+0] += x1*v.x; a1[q*4+1] += x1*v.y;
            a1[q*4+2] += x1*v.z; a1[q*4+3] += x1*v.w;
        }
    }
    const int b = tbase >> 14;
    const int rem = tbase & 16383;
    const int h = rem >> 7;
    const int wcp = rem & 127;
    size_t obase = ((size_t)b*Ss)*((size_t)H2*W2) + (size_t)h*W2 + wcp;
#pragma unroll
    for (int c = 0; c < 16; c++) {
        size_t o = obase + (size_t)(cb + c)*(H2*W2);
        d0m[o + lane]      = a0[c];
        d0m[o + 32 + lane] = a1[c];
    }
}

// ---------------------------------------------------------------------------
// ConvTranspose2d(128->3, k4, s2, p1) + bias + SiLU.
// ---------------------------------------------------------------------------
__global__ void __launch_bounds__(256) deconv_kernel(
    const float* __restrict__ in, const float* __restrict__ dw,
    const float* __restrict__ db, float* __restrict__ out)
{
    __shared__ float sWd[4*128*12];              // [parity][cin][o][k] 24.6 KB
    __shared__ float sIn[16*100];                // 16 cins x 10x10
    const int tid = threadIdx.x;
    for (int i = tid; i < 4*128*12; i += 256) {
        int p = i / 1536, rem = i - p*1536;
        int cin = rem / 12, rr = rem - cin*12;
        int o = rr >> 2, k = rr & 3;
        int py = p >> 1, px = p & 1;
        int ky = py + 2*(k >> 1), kx = px + 2*(k & 1);
        sWd[i] = dw[cin*48 + o*16 + ky*4 + kx];
    }

    const int b  = blockIdx.z;
    const int Y0 = blockIdx.y*16, X0 = blockIdx.x*16;
    const int ty = tid >> 4, tx = tid & 15;
    const int y = Y0 + ty, x = X0 + tx;
    const int hb = (Y0 >> 1) - 1, wb = (X0 >> 1) - 1;

    const int py = (y + 1) & 1, px = (x + 1) & 1;
    const int hs0 = ((y + 1 - py) >> 1) - hb;
    const int ws0 = ((x + 1 - px) >> 1) - wb;

    const float* wp = sWd + (py*2 + px)*1536;
    float acc[3] = {0.f, 0.f, 0.f};
    const float* inb = in + (size_t)b * Ss * H2 * W2;

    for (int c0 = 0; c0 < Ss; c0 += 16) {
        __syncthreads();
        for (int i = tid; i < 1600; i += 256) {
            int c = i / 100, rr = i - c*100;
            int r = rr / 10, cc = rr - r*10;
            int h = hb + r, w = wb + cc;
            float v = 0.f;
            if ((unsigned)h < (unsigned)H2 && (unsigned)w < (unsigned)W2)
                v = inb[((size_t)(c0 + c)*H2 + h)*W2 + w];
            sIn[i] = v;
        }
        __syncthreads();
#pragma unroll
        for (int c = 0; c < 16; c++) {
            const float* sc = sIn + c*100;
            float i00 = sc[hs0*10 + ws0];
            float i01 = sc[hs0*10 + ws0 - 1];
            float i10 = sc[(hs0-1)*10 + ws0];
            float i11 = sc[(hs0-1)*10 + ws0 - 1];
            const float4* w4 = (const float4*)(wp + (c0 + c)*12);
#pragma unroll
            for (int o = 0; o < 3; o++) {
                float4 w = w4[o];
                acc[o] += i00*w.x + i01*w.y + i10*w.z + i11*w.w;
            }
        }
    }
#pragma unroll
    for (int o = 0; o < 3; o++) {
        float v = acc[o] + db[o];
        v = v / (1.f + __expf(-v));
        out[(((size_t)b*3 + o)*HIN + y)*WIN + x] = v;
    }
}

// ---------------------------------------------------------------------------
// Launch sequence
// ---------------------------------------------------------------------------
extern "C" void kernel_launch(void* const* d_in, const int* in_sizes, int n_in,
                              void* d_out, int out_size)
{
    const float* x      = (const float*)d_in[0];
    const float* e0n_w1 = (const float*)d_in[1];
    const float* e0n_b1 = (const float*)d_in[2];
    const float* e0n_w2 = (const float*)d_in[3];
    const float* e0n_b2 = (const float*)d_in[4];
    const float* e0s_w1 = (const float*)d_in[5];
    const float* e0s_b1 = (const float*)d_in[6];
    const float* e0s_w2 = (const float*)d_in[7];
    const float* e0s_b2 = (const float*)d_in[8];
    const float* d0_dw  = (const float*)d_in[9];
    const float* d0_db  = (const float*)d_in[10];
    const float* d0_cw  = (const float*)d_in[11];
    const float* d0_cb  = (const float*)d_in[12];
    const float* cell_k = (const float*)d_in[13];
    const float* cell_v = (const float*)d_in[14];
    float* outp = (float*)d_out;

    void *p_a1n, *p_a1s, *p_z, *p_ts, *p_w, *p_part, *p_gu, *p_vnew, *p_d0m, *p_dec;
    cudaGetSymbolAddress(&p_a1n, g_a1n);
    cudaGetSymbolAddress(&p_a1s, g_a1s);
    cudaGetSymbolAddress(&p_z,   g_z);
    cudaGetSymbolAddress(&p_ts,  g_ts);
    cudaGetSymbolAddress(&p_w,   g_w);
    cudaGetSymbolAddress(&p_part,g_part);
    cudaGetSymbolAddress(&p_gu,  g_gu);
    cudaGetSymbolAddress(&p_vnew,g_vnew);
    cudaGetSymbolAddress(&p_d0m, g_d0m);
    cudaGetSymbolAddress(&p_dec, g_dec);

    // dynamic smem: 2 * ITX * SRS * 4 bytes
    const int dsm_s1 = 2 * 34 * 36 * 4;   //  9792 B
    const int dsm_s2 = 2 * 65 * 72 * 4;   // 37440 B

    // Opt-in: static (~27KB tables) + dynamic (37.4KB) exceeds the 48KB
    // default combined limit for the stride-2 instantiations. Host-side
    // attribute set; not a stream op, graph-capture safe, deterministic.
    cudaFuncSetAttribute((const void*)convfast<16,16,2,true>,
                         cudaFuncAttributeMaxDynamicSharedMemorySize, dsm_s2);
    cudaFuncSetAttribute((const void*)convfast<128,128,2,true>,
                         cudaFuncAttributeMaxDynamicSharedMemorySize, dsm_s2);
    cudaFuncSetAttribute((const void*)convfast<3,16,1,false>,
                         cudaFuncAttributeMaxDynamicSharedMemorySize, dsm_s1);
    cudaFuncSetAttribute((const void*)convfast<3,128,1,false>,
                         cudaFuncAttributeMaxDynamicSharedMemorySize, dsm_s1);

    // Encoders
    convfast<3,16,1,false><<<dim3(8,8,Bb*2),256,dsm_s1>>>(
        x, e0n_w1, e0n_b1, (float*)p_a1n, HIN, WIN, HIN, WIN);
    convfast<3,128,1,false><<<dim3(8,8,Bb*16),256,dsm_s1>>>(
        x, e0s_w1, e0s_b1, (float*)p_a1s, HIN, WIN, HIN, WIN);
    convfast<16,16,2,true><<<dim3(4,4,Bb*2),256,dsm_s2>>>(
        (const float*)p_a1n, e0n_w2, e0n_b2, (float*)p_z, HIN, WIN, H2, W2);
    convfast<128,128,2,true><<<dim3(4,4,Bb*16),256,dsm_s2>>>(
        (const float*)p_a1s, e0s_w2, e0s_b2, (float*)p_ts, HIN, WIN, H2, W2);

    // Memcell
    memcell_softmax<<<Tt/256,256>>>((const float*)p_z, cell_k, (float*)p_w);
    memcell_outer<<<1024,256>>>((const float*)p_w, (const float*)p_ts, (float*)p_part);
    reduce_partials<<<20,256>>>((const float*)p_part, (float*)p_gu);
    cell_update<<<1,256>>>((const float*)p_gu, cell_v, (float*)p_vnew);
    memcell_read<<<Tt/64,256>>>((const float*)p_w, (const float*)p_vnew, (float*)p_d0m);

    // Decoder
    deconv_kernel<<<dim3(16,16,Bb),256>>>(
        (const float*)p_d0m, d0_dw, d0_db, (float*)p_dec);
    conv3x3<3,3,3,1,false><<<dim3(16,16,Bb),256>>>(
        (const float*)p_dec, d0_cw, d0_cb, outp, HIN, WIN, HIN, WIN);
}

// round 8
// speedup vs baseline: 1.7230x; 1.2894x over previous
#include <cuda_runtime.h>
#include <cuda_bf16.h>
#include <cstdint>

// ---------------------------------------------------------------------------
// Problem constants
// ---------------------------------------------------------------------------
#define Bb   8
#define HIN  256
#define WIN  256
#define H2   128
#define W2   128
#define Nn   16
#define Mm   32
#define Ss   128
#define Tt   (Bb*H2*W2)          // 131072 tokens
#define ALPHA 1e-6f

// ---------------------------------------------------------------------------
// Scratch buffers (static device globals; no cudaMalloc allowed)
// ---------------------------------------------------------------------------
__device__ float g_a1n [Bb*Nn*HIN*WIN];
__device__ float g_a1s [(size_t)Bb*Ss*HIN*WIN];
__device__ float g_z   [(size_t)Tt*Nn];
__device__ float g_ts  [(size_t)Tt*Ss];
__device__ float g_w   [(size_t)Tt*Mm];
__device__ float g_part[(size_t)1024*32*160];
__device__ float g_gu  [32*160];
__device__ float g_vnew[Mm*Ss];
__device__ float g_d0m [(size_t)Bb*Ss*H2*W2];
__device__ float g_dec [(size_t)Bb*3*HIN*WIN];

// ---------------------------------------------------------------------------
// cp.async helpers
// ---------------------------------------------------------------------------
__device__ __forceinline__ void cp_async4(unsigned dst, const float* src, int sz) {
    asm volatile("cp.async.ca.shared.global [%0], [%1], 4, %2;\n"
                 :: "r"(dst), "l"(src), "r"(sz));
}
__device__ __forceinline__ void cp_async4u(unsigned dst, const float* src) {
    asm volatile("cp.async.ca.shared.global [%0], [%1], 4;\n"
                 :: "r"(dst), "l"(src));
}
__device__ __forceinline__ void cp_commit() {
    asm volatile("cp.async.commit_group;\n" ::: "memory");
}
__device__ __forceinline__ void cp_wait0() {
    asm volatile("cp.async.wait_group 0;\n" ::: "memory");
}

// ---------------------------------------------------------------------------
// Fast fused conv3x3 + bias + SiLU.  pad=1, stride in {1,2}.
// 256 threads -> 32x32 output tile; thread = 4 x-pixels x 16 channels.
// COG=16 halves tile-restaging per FLOP vs COG=8 (key L1 relief) and makes
// the inner loop 576 FFMA per cin per thread -> FFMA-pipe bound.
// STRIDE=2: parity-split smem input tile (lane-contiguous LDS.128).
// Staging addresses cin-invariant: single int2 table (gmem ofs, smem ofs),
// 17 LDS.64 + 17 cp.async per cin per thread. Double buffered, 2 blocks/SM.
// ---------------------------------------------------------------------------
template<int CIN, int OUTC, int STRIDE, bool TOKEN_OUT>
__global__ void __launch_bounds__(256, 2) convfast(
    const float* __restrict__ in, const float* __restrict__ wgt,
    const float* __restrict__ bias, float* __restrict__ out,
    int Hin, int Win, int Ho, int Wo)
{
    constexpr int COG  = 16;
    constexpr int ITX  = 31*STRIDE + 3;          // 65 (s2) / 34 (s1)
    constexpr int ODD  = 36;                     // odd-plane float offset (s2)
    constexpr int SRS  = (STRIDE==2) ? 72 : 36;  // smem row stride (floats)
    constexpr int ELEMS = ITX * ITX;             // 4225 / 1156
    constexpr int NIT  = (ELEMS + 255) / 256;    // 17 / 5
    constexpr int PLANE = ITX * SRS;             // floats per buffer

    extern __shared__ float sIn[];               // [2][PLANE]
    __shared__ float sW[2][COG*9 + 8];
    __shared__ int2 tTab[NIT*256];               // .x = gmem ofs (-1 zfill), .y = smem ofs (-1 skip)

    const int tid = threadIdx.x;
    const int tx = tid & 7, ty = tid >> 3;
    const int groups = OUTC / COG;
    const int b = blockIdx.z / groups;
    const int cbase = (blockIdx.z % groups) * COG;
    const int X0 = blockIdx.x * 32, Y0 = blockIdx.y * 32;
    const int iy0 = Y0*STRIDE - 1, ix0 = X0*STRIDE - 1;
    const size_t HW = (size_t)Hin * Win;
    const float* inb = in + (size_t)b * CIN * HW;

    const int wc = tid / 9, wtap = tid - wc*9;   // weight stage slot (tid<COG*9)

    // ---- build staging table ONCE (each thread writes & reads its own slots)
#pragma unroll
    for (int k = 0; k < NIT; k++) {
        int f = k*256 + tid;
        int sof = -1, gof = -1;
        if (f < ELEMS) {
            int r = f / ITX, c = f - r*ITX;
            int ih = iy0 + r, iw = ix0 + c;
            if (STRIDE == 2) sof = r*SRS + ((c & 1) ? ODD : 0) + (c >> 1);
            else             sof = r*SRS + c;
            gof = ((unsigned)ih < (unsigned)Hin && (unsigned)iw < (unsigned)Win)
                  ? (ih*Win + iw) : -1;
        }
        tTab[k*256 + tid] = make_int2(gof, sof);
    }

    // ---- staging: table-driven (1 LDS.64 + 1 cp.async per element)
    const unsigned sb0 = (unsigned)__cvta_generic_to_shared(sIn);
    auto stage = [&](int buf, int cin) {
        const float* ic = inb + (size_t)cin * HW;
        const unsigned sb = sb0 + (unsigned)buf * (PLANE*4);
#pragma unroll
        for (int k = 0; k < NIT; k++) {
            int2 t = tTab[k*256 + tid];
            if (t.y >= 0)
                cp_async4(sb + (unsigned)t.y*4, ic + (t.x < 0 ? 0 : t.x),
                          t.x < 0 ? 0 : 4);
        }
        if (tid < COG*9) {
            unsigned dst = (unsigned)__cvta_generic_to_shared(
                               &sW[buf][wtap*COG + wc]);
            cp_async4u(dst, wgt + ((size_t)(cbase+wc)*CIN + cin)*9 + wtap);
        }
    };

    stage(0, 0);
    cp_commit();
    cp_wait0();
    __syncthreads();

    float acc[4][COG];
#pragma unroll
    for (int j = 0; j < 4; j++)
#pragma unroll
        for (int c = 0; c < COG; c++) acc[j][c] = 0.f;

    for (int cin = 0; cin < CIN; cin++) {
        const int cur = cin & 1;
        if (cin + 1 < CIN) { stage(cur^1, cin+1); cp_commit(); }

        const float* sc  = sIn + cur*PLANE;
        const float* swp = sW[cur];
#pragma unroll
        for (int dy = 0; dy < 3; dy++) {
            float V[3][4];
            if (STRIDE == 2) {
                const float* rp = sc + (ty*2 + dy)*SRS;
                float4 E = *(const float4*)(rp + tx*4);
                float  e4 = rp[tx*4 + 4];
                float4 O = *(const float4*)(rp + ODD + tx*4);
                V[0][0]=E.x; V[0][1]=E.y; V[0][2]=E.z; V[0][3]=E.w;
                V[1][0]=O.x; V[1][1]=O.y; V[1][2]=O.z; V[1][3]=O.w;
                V[2][0]=E.y; V[2][1]=E.z; V[2][2]=E.w; V[2][3]=e4;
            } else {
                const float* rp = sc + (ty + dy)*SRS + tx*4;
                float4 A = *(const float4*)rp;
                float2 Bv = *(const float2*)(rp + 4);
                float iv6[6] = {A.x, A.y, A.z, A.w, Bv.x, Bv.y};
#pragma unroll
                for (int dx = 0; dx < 3; dx++)
#pragma unroll
                    for (int k = 0; k < 4; k++) V[dx][k] = iv6[k+dx];
            }
#pragma unroll
            for (int dx = 0; dx < 3; dx++) {
                const float* wp = swp + (dy*3+dx)*COG;
                float4 w0 = *(const float4*)(wp);
                float4 w1 = *(const float4*)(wp + 4);
                float4 w2 = *(const float4*)(wp + 8);
                float4 w3 = *(const float4*)(wp + 12);
#pragma unroll
                for (int j = 0; j < 4; j++) {
                    float v = V[dx][j];
                    acc[j][0]  += v*w0.x; acc[j][1]  += v*w0.y;
                    acc[j][2]  += v*w0.z; acc[j][3]  += v*w0.w;
                    acc[j][4]  += v*w1.x; acc[j][5]  += v*w1.y;
                    acc[j][6]  += v*w1.z; acc[j][7]  += v*w1.w;
                    acc[j][8]  += v*w2.x; acc[j][9]  += v*w2.y;
                    acc[j][10] += v*w2.z; acc[j][11] += v*w2.w;
                    acc[j][12] += v*w3.x; acc[j][13] += v*w3.y;
                    acc[j][14] += v*w3.z; acc[j][15] += v*w3.w;
                }
            }
        }
        if (cin + 1 < CIN) cp_wait0();
        __syncthreads();
    }

    // -------- epilogue: bias + SiLU + vectorized stores
    float bv[COG];
#pragma unroll
    for (int c = 0; c < COG; c++) bv[c] = __ldg(bias + cbase + c);

    const int oy = Y0 + ty;
    if (TOKEN_OUT) {
#pragma unroll
        for (int j = 0; j < 4; j++) {
            float vv[COG];
#pragma unroll
            for (int c = 0; c < COG; c++) {
                float v = acc[j][c] + bv[c];
                vv[c] = v / (1.f + __expf(-v));
            }
            size_t t = ((size_t)b*Ho + oy)*Wo + X0 + tx*4 + j;
            float4* op = (float4*)(out + t*OUTC + cbase);
            op[0] = make_float4(vv[0],  vv[1],  vv[2],  vv[3]);
            op[1] = make_float4(vv[4],  vv[5],  vv[6],  vv[7]);
            op[2] = make_float4(vv[8],  vv[9],  vv[10], vv[11]);
            op[3] = make_float4(vv[12], vv[13], vv[14], vv[15]);
        }
    } else {
#pragma unroll
        for (int c = 0; c < COG; c++) {
            float4 o;
            float* po = (float*)&o;
#pragma unroll
            for (int j = 0; j < 4; j++) {
                float v = acc[j][c] + bv[c];
                po[j] = v / (1.f + __expf(-v));
            }
            *(float4*)(out + (((size_t)b*OUTC + cbase + c)*Ho + oy)*Wo + X0 + tx*4) = o;
        }
    }
}

// ---------------------------------------------------------------------------
// Legacy conv (used only for the tiny 3->3 decoder conv)
// ---------------------------------------------------------------------------
template<int CIN, int OUTC, int COG, int STRIDE, bool TOKEN_OUT>
__global__ void __launch_bounds__(256) conv3x3(
    const float* __restrict__ in, const float* __restrict__ wgt,
    const float* __restrict__ bias, float* __restrict__ out,
    int Hin, int Win, int Ho, int Wo)
{
    constexpr int ITD = 15*STRIDE + 3;
    __shared__ float sW[COG*CIN*9];
    __shared__ float sIn[ITD*ITD];

    const int tid = threadIdx.x;
    const int groups = OUTC / COG;
    const int b  = blockIdx.z / groups;
    const int cg = blockIdx.z % groups;
    const int cbase = cg * COG;

    for (int i = tid; i < COG*CIN*9; i += 256)
        sW[i] = wgt[(size_t)cbase*CIN*9 + i];

    const int ty = tid >> 4, tx = tid & 15;
    const int oy = blockIdx.y*16 + ty;
    const int ox = blockIdx.x*16 + tx;

    float acc[COG];
#pragma unroll
    for (int c = 0; c < COG; c++) acc[c] = 0.f;

    const float* inb = in + (size_t)b * CIN * Hin * Win;
    const int iy0 = blockIdx.y*16*STRIDE - 1;
    const int ix0 = blockIdx.x*16*STRIDE - 1;
    const int base = (ty*STRIDE)*ITD + tx*STRIDE;

    for (int cin = 0; cin < CIN; cin++) {
        __syncthreads();
        const float* ic = inb + (size_t)cin * Hin * Win;
        for (int i = tid; i < ITD*ITD; i += 256) {
            int r = i / ITD, cc = i - r*ITD;
            int ih = iy0 + r, iw = ix0 + cc;
            float v = 0.f;
            if ((unsigned)ih < (unsigned)Hin && (unsigned)iw < (unsigned)Win)
                v = ic[ih*Win + iw];
            sIn[i] = v;
        }
        __syncthreads();
        const float* wp = sW + cin*9;
#pragma unroll
        for (int dy = 0; dy < 3; dy++)
#pragma unroll
            for (int dx = 0; dx < 3; dx++) {
                float iv = sIn[base + dy*ITD + dx];
#pragma unroll
                for (int c = 0; c < COG; c++)
                    acc[c] += iv * wp[c*CIN*9 + dy*3 + dx];
            }
    }

#pragma unroll
    for (int c = 0; c < COG; c++) {
        float v = acc[c] + bias[cbase + c];
        v = v / (1.f + __expf(-v));
        if (TOKEN_OUT) {
            size_t t = ((size_t)b*Ho + oy)*Wo + ox;
            out[t*OUTC + cbase + c] = v;
        } else {
            out[(((size_t)b*OUTC + cbase + c)*Ho + oy)*Wo + ox] = v;
        }
    }
}

// ---------------------------------------------------------------------------
// Memcell pass 1: w = softmax(z @ K^T / 4) per token.
// ---------------------------------------------------------------------------
__global__ void __launch_bounds__(256) memcell_softmax(
    const float* __restrict__ z, const float* __restrict__ ck,
    float* __restrict__ wout)
{
    __shared__ float sK[Mm*Nn];
    const int tid = threadIdx.x;
    for (int i = tid; i < Mm*Nn; i += 256) sK[i] = ck[i];
    __syncthreads();

    const int t = blockIdx.x*256 + tid;
    const float4* zp = (const float4*)(z + (size_t)t*Nn);
    float4 z0 = zp[0], z1 = zp[1], z2 = zp[2], z3 = zp[3];

    float s[Mm];
    float mx = -1e30f;
#pragma unroll
    for (int m = 0; m < Mm; m++) {
        const float* k = sK + m*Nn;
        float d = z0.x*k[0] + z0.y*k[1] + z0.z*k[2] + z0.w*k[3]
                + z1.x*k[4] + z1.y*k[5] + z1.z*k[6] + z1.w*k[7]
                + z2.x*k[8] + z2.y*k[9] + z2.z*k[10]+ z2.w*k[11]
                + z3.x*k[12]+ z3.y*k[13]+ z3.z*k[14]+ z3.w*k[15];
        d *= 0.25f;
        s[m] = d;
        mx = fmaxf(mx, d);
    }
    float sum = 0.f;
#pragma unroll
    for (int m = 0; m < Mm; m++) { s[m] = __expf(s[m]-mx); sum += s[m]; }
    float inv = 1.f / sum;
    float4* wo = (float4*)(wout + (size_t)t*Mm);
#pragma unroll
    for (int j = 0; j < Mm/4; j++) {
        float4 v; v.x = s[4*j]*inv; v.y = s[4*j+1]*inv;
        v.z = s[4*j+2]*inv; v.w = s[4*j+3]*inv;
        wo[j] = v;
    }
}

// ---------------------------------------------------------------------------
// Memcell pass 2: block partials of [G | U], G = W^T W, U = W^T t_star.
// ---------------------------------------------------------------------------
__global__ void __launch_bounds__(256) memcell_outer(
    const float* __restrict__ wmat, const float* __restrict__ ts,
    float* __restrict__ part)
{
    __shared__ float sv[8*160];
    const int tid = threadIdx.x;
    const int ti = tid >> 5;
    const int tj = tid & 31;
    float acc[4][5];
#pragma unroll
    for (int a = 0; a < 4; a++)
#pragma unroll
        for (int q = 0; q < 5; q++) acc[a][q] = 0.f;

    const int tokb = blockIdx.x * 128;
    for (int ch = 0; ch < 128; ch += 8) {
        __syncthreads();
#pragma unroll
        for (int l = 0; l < 5; l++) {
            int idx = l*256 + tid;
            int tk = idx / 160, f = idx - tk*160;
            int t = tokb + ch + tk;
            sv[tk*160 + f] = (f < 32) ? wmat[(size_t)t*32 + f]
                                      : ts[(size_t)t*128 + (f-32)];
        }
        __syncthreads();
#pragma unroll
        for (int tk = 0; tk < 8; tk++) {
            float wi[4], vj[5];
#pragma unroll
            for (int a = 0; a < 4; a++) wi[a] = sv[tk*160 + ti*4 + a];
#pragma unroll
            for (int q = 0; q < 5; q++) vj[q] = sv[tk*160 + tj*5 + q];
#pragma unroll
            for (int a = 0; a < 4; a++)
#pragma unroll
                for (int q = 0; q < 5; q++) acc[a][q] += wi[a]*vj[q];
        }
    }
    float* pp = part + (size_t)blockIdx.x * 5120;
#pragma unroll
    for (int a = 0; a < 4; a++)
#pragma unroll
        for (int q = 0; q < 5; q++)
            pp[(ti*4+a)*160 + tj*5 + q] = acc[a][q];
}

__global__ void __launch_bounds__(256) reduce_partials(
    const float* __restrict__ part, float* __restrict__ gu)
{
    int cell = blockIdx.x*256 + threadIdx.x;
    float s = 0.f;
#pragma unroll 8
    for (int p = 0; p < 1024; p++) s += part[(size_t)p*5120 + cell];
    gu[cell] = s;
}

__global__ void __launch_bounds__(256) cell_update(
    const float* __restrict__ gu, const float* __restrict__ cv,
    float* __restrict__ vnew)
{
    __shared__ float sG[Mm*Mm];
    __shared__ float sV[Mm*Ss];
    const int tid = threadIdx.x;
    for (int i = tid; i < Mm*Mm; i += 256) {
        int m = i >> 5, j = i & 31;
        sG[i] = gu[m*160 + j];
    }
    for (int i = tid; i < Mm*Ss; i += 256) sV[i] = cv[i];
    __syncthreads();
    for (int k = 0; k < 16; k++) {
        int cell = k*256 + tid;
        int m = cell >> 7, s0 = cell & 127;
        float d = gu[m*160 + 32 + s0];
#pragma unroll
        for (int mp = 0; mp < Mm; mp++) d -= sG[m*32 + mp] * sV[mp*128 + s0];
        vnew[cell] = sV[cell] + ALPHA * d;
    }
}

// ---------------------------------------------------------------------------
// Memcell pass 3: t_read = W @ cell_v_new -> NCHW [B,S,H2,W2].
// ---------------------------------------------------------------------------
__global__ void __launch_bounds__(256) memcell_read(
    const float* __restrict__ wmat, const float* __restrict__ vnew,
    float* __restrict__ d0m)
{
    __shared__ float sV[Mm*Ss];
    __shared__ float sW[64*33];
    const int tid = threadIdx.x;
    for (int i = tid; i < Mm*Ss; i += 256) sV[i] = vnew[i];
    const int tbase = blockIdx.x * 64;
    for (int i = tid; i < 64*32; i += 256) {
        int tk = i >> 5, m = i & 31;
        sW[tk*33 + m] = wmat[(size_t)(tbase + tk)*32 + m];
    }
    __syncthreads();

    const int lane = tid & 31, wid = tid >> 5;
    const int cb = wid * 16;
    float a0[16], a1[16];
#pragma unroll
    for (int c = 0; c < 16; c++) { a0[c] = 0.f; a1[c] = 0.f; }

    const float* w0 = sW + lane*33;
    const float* w1 = sW + (lane + 32)*33;
#pragma unroll 4
    for (int m = 0; m < Mm; m++) {
        float x0 = w0[m], x1 = w1[m];
        const float4* vv = (const float4*)(sV + m*128 + cb);
#pragma unroll
        for (int q = 0; q < 4; q++) {
            float4 v = vv[q];
            a0[q*4+0] += x0*v.x; a0[q*4+1] += x0*v.y;
            a0[q*4+2] += x0*v.z; a0[q*4+3] += x0*v.w;
            a1[q*4+0] += x1*v.x; a1[q*4+1] += x1*v.y;
            a1[q*4+2] += x1*v.z; a1[q*4+3] += x1*v.w;
        }
    }
    const int b = tbase >> 14;
    const int rem = tbase & 16383;
    const int h = rem >> 7;
    const int wcp = rem & 127;
    size_t obase = ((size_t)b*Ss)*((size_t)H2*W2) + (size_t)h*W2 + wcp;
#pragma unroll
    for (int c = 0; c < 16; c++) {
        size_t o = obase + (size_t)(cb + c)*(H2*W2);
        d0m[o + lane]      = a0[c];
        d0m[o + 32 + lane] = a1[c];
    }
}

// ---------------------------------------------------------------------------
// ConvTranspose2d(128->3, k4, s2, p1) + bias + SiLU.
// ---------------------------------------------------------------------------
__global__ void __launch_bounds__(256) deconv_kernel(
    const float* __restrict__ in, const float* __restrict__ dw,
    const float* __restrict__ db, float* __restrict__ out)
{
    __shared__ float sWd[4*128*12];              // [parity][cin][o][k] 24.6 KB
    __shared__ float sIn[16*100];                // 16 cins x 10x10
    const int tid = threadIdx.x;
    for (int i = tid; i < 4*128*12; i += 256) {
        int p = i / 1536, rem = i - p*1536;
        int cin = rem / 12, rr = rem - cin*12;
        int o = rr >> 2, k = rr & 3;
        int py = p >> 1, px = p & 1;
        int ky = py + 2*(k >> 1), kx = px + 2*(k & 1);
        sWd[i] = dw[cin*48 + o*16 + ky*4 + kx];
    }

    const int b  = blockIdx.z;
    const int Y0 = blockIdx.y*16, X0 = blockIdx.x*16;
    const int ty = tid >> 4, tx = tid & 15;
    const int y = Y0 + ty, x = X0 + tx;
    const int hb = (Y0 >> 1) - 1, wb = (X0 >> 1) - 1;

    const int py = (y + 1) & 1, px = (x + 1) & 1;
    const int hs0 = ((y + 1 - py) >> 1) - hb;
    const int ws0 = ((x + 1 - px) >> 1) - wb;

    const float* wp = sWd + (py*2 + px)*1536;
    float acc[3] = {0.f, 0.f, 0.f};
    const float* inb = in + (size_t)b * Ss * H2 * W2;

    for (int c0 = 0; c0 < Ss; c0 += 16) {
        __syncthreads();
        for (int i = tid; i < 1600; i += 256) {
            int c = i / 100, rr = i - c*100;
            int r = rr / 10, cc = rr - r*10;
            int h = hb + r, w = wb + cc;
            float v = 0.f;
            if ((unsigned)h < (unsigned)H2 && (unsigned)w < (unsigned)W2)
                v = inb[((size_t)(c0 + c)*H2 + h)*W2 + w];
            sIn[i] = v;
        }
        __syncthreads();
#pragma unroll
        for (int c = 0; c < 16; c++) {
            const float* sc = sIn + c*100;
            float i00 = sc[hs0*10 + ws0];
            float i01 = sc[hs0*10 + ws0 - 1];
            float i10 = sc[(hs0-1)*10 + ws0];
            float i11 = sc[(hs0-1)*10 + ws0 - 1];
            const float4* w4 = (const float4*)(wp + (c0 + c)*12);
#pragma unroll
            for (int o = 0; o < 3; o++) {
                float4 w = w4[o];
                acc[o] += i00*w.x + i01*w.y + i10*w.z + i11*w.w;
            }
        }
    }
#pragma unroll
    for (int o = 0; o < 3; o++) {
        float v = acc[o] + db[o];
        v = v / (1.f + __expf(-v));
        out[(((size_t)b*3 + o)*HIN + y)*WIN + x] = v;
    }
}

// ---------------------------------------------------------------------------
// Launch sequence
// ---------------------------------------------------------------------------
extern "C" void kernel_launch(void* const* d_in, const int* in_sizes, int n_in,
                              void* d_out, int out_size)
{
    const float* x      = (const float*)d_in[0];
    const float* e0n_w1 = (const float*)d_in[1];
    const float* e0n_b1 = (const float*)d_in[2];
    const float* e0n_w2 = (const float*)d_in[3];
    const float* e0n_b2 = (const float*)d_in[4];
    const float* e0s_w1 = (const float*)d_in[5];
    const float* e0s_b1 = (const float*)d_in[6];
    const float* e0s_w2 = (const float*)d_in[7];
    const float* e0s_b2 = (const float*)d_in[8];
    const float* d0_dw  = (const float*)d_in[9];
    const float* d0_db  = (const float*)d_in[10];
    const float* d0_cw  = (const float*)d_in[11];
    const float* d0_cb  = (const float*)d_in[12];
    const float* cell_k = (const float*)d_in[13];
    const float* cell_v = (const float*)d_in[14];
    float* outp = (float*)d_out;

    void *p_a1n, *p_a1s, *p_z, *p_ts, *p_w, *p_part, *p_gu, *p_vnew, *p_d0m, *p_dec;
    cudaGetSymbolAddress(&p_a1n, g_a1n);
    cudaGetSymbolAddress(&p_a1s, g_a1s);
    cudaGetSymbolAddress(&p_z,   g_z);
    cudaGetSymbolAddress(&p_ts,  g_ts);
    cudaGetSymbolAddress(&p_w,   g_w);
    cudaGetSymbolAddress(&p_part,g_part);
    cudaGetSymbolAddress(&p_gu,  g_gu);
    cudaGetSymbolAddress(&p_vnew,g_vnew);
    cudaGetSymbolAddress(&p_d0m, g_d0m);
    cudaGetSymbolAddress(&p_dec, g_dec);

    // dynamic smem: 2 * ITX * SRS * 4 bytes
    const int dsm_s1 = 2 * 34 * 36 * 4;   //  9792 B
    const int dsm_s2 = 2 * 65 * 72 * 4;   // 37440 B

    // Opt-in above the 48KB default combined limit (static tables + dynamic).
    cudaFuncSetAttribute((const void*)convfast<16,16,2,true>,
                         cudaFuncAttributeMaxDynamicSharedMemorySize, dsm_s2);
    cudaFuncSetAttribute((const void*)convfast<128,128,2,true>,
                         cudaFuncAttributeMaxDynamicSharedMemorySize, dsm_s2);
    cudaFuncSetAttribute((const void*)convfast<3,16,1,false>,
                         cudaFuncAttributeMaxDynamicSharedMemorySize, dsm_s1);
    cudaFuncSetAttribute((const void*)convfast<3,128,1,false>,
                         cudaFuncAttributeMaxDynamicSharedMemorySize, dsm_s1);

    // Encoders (COG=16: groups = OUTC/16)
    convfast<3,16,1,false><<<dim3(8,8,Bb),256,dsm_s1>>>(
        x, e0n_w1, e0n_b1, (float*)p_a1n, HIN, WIN, HIN, WIN);
    convfast<3,128,1,false><<<dim3(8,8,Bb*8),256,dsm_s1>>>(
        x, e0s_w1, e0s_b1, (float*)p_a1s, HIN, WIN, HIN, WIN);
    convfast<16,16,2,true><<<dim3(4,4,Bb),256,dsm_s2>>>(
        (const float*)p_a1n, e0n_w2, e0n_b2, (float*)p_z, HIN, WIN, H2, W2);
    convfast<128,128,2,true><<<dim3(4,4,Bb*8),256,dsm_s2>>>(
        (const float*)p_a1s, e0s_w2, e0s_b2, (float*)p_ts, HIN, WIN, H2, W2);

    // Memcell
    memcell_softmax<<<Tt/256,256>>>((const float*)p_z, cell_k, (float*)p_w);
    memcell_outer<<<1024,256>>>((const float*)p_w, (const float*)p_ts, (float*)p_part);
    reduce_partials<<<20,256>>>((const float*)p_part, (float*)p_gu);
    cell_update<<<1,256>>>((const float*)p_gu, cell_v, (float*)p_vnew);
    memcell_read<<<Tt/64,256>>>((const float*)p_w, (const float*)p_vnew, (float*)p_d0m);

    // Decoder
    deconv_kernel<<<dim3(16,16,Bb),256>>>(
        (const float*)p_d0m, d0_dw, d0_db, (float*)p_dec);
    conv3x3<3,3,3,1,false><<<dim3(16,16,Bb),256>>>(
        (const float*)p_dec, d0_cw, d0_cb, outp, HIN, WIN, HIN, WIN);
}

// round 11
// speedup vs baseline: 2.2542x; 1.3083x over previous
#include <cuda_runtime.h>
#include <cuda_bf16.h>
#include <cstdint>

// ---------------------------------------------------------------------------
// Problem constants
// ---------------------------------------------------------------------------
#define Bb   8
#define HIN  256
#define WIN  256
#define H2   128
#define W2   128
#define Nn   16
#define Mm   32
#define Ss   128
#define Tt   (Bb*H2*W2)          // 131072 tokens
#define ALPHA 1e-6f

// Padded parity-split activation layout (per channel):
//   258 rows (row = image_y + 1; row 0 = top border of zeros)
//   row = [op 132 | ep 132]  (264 floats, 1056B)
//   op[k] = col 2k-1  (k=0..128; op[0] = col -1, zeroed border)
//   ep[k] = col 2k    (k=0..127 valid)
#define PROW 264
#define PCH  (258*PROW)

// ---------------------------------------------------------------------------
// Scratch buffers (static device globals; no cudaMalloc allowed)
// ---------------------------------------------------------------------------
__device__ float g_a1n [(size_t)Bb*Nn*PCH];      // padded silu(conv1_n)
__device__ float g_a1s [(size_t)Bb*Ss*PCH];      // padded silu(conv1_s) ~279MB
__device__ float g_z   [(size_t)Tt*Nn];
__device__ float g_ts  [(size_t)Tt*Ss];
__device__ float g_w   [(size_t)Tt*Mm];
__device__ float g_part[(size_t)1024*32*160];
__device__ float g_gu  [32*160];
__device__ float g_vnew[Mm*Ss];
__device__ float g_d0m [(size_t)Bb*Ss*H2*W2];
__device__ float g_dec [(size_t)Bb*3*HIN*WIN];

// ---------------------------------------------------------------------------
// cp.async helpers
// ---------------------------------------------------------------------------
__device__ __forceinline__ void cp_async4(unsigned dst, const float* src, int sz) {
    asm volatile("cp.async.ca.shared.global [%0], [%1], 4, %2;\n"
                 :: "r"(dst), "l"(src), "r"(sz));
}
__device__ __forceinline__ void cp_async4u(unsigned dst, const float* src) {
    asm volatile("cp.async.ca.shared.global [%0], [%1], 4;\n"
                 :: "r"(dst), "l"(src));
}
__device__ __forceinline__ void cp_async16(unsigned dst, const float* src) {
    asm volatile("cp.async.cg.shared.global [%0], [%1], 16;\n"
                 :: "r"(dst), "l"(src));
}
__device__ __forceinline__ void cp_commit() {
    asm volatile("cp.async.commit_group;\n" ::: "memory");
}
__device__ __forceinline__ void cp_wait0() {
    asm volatile("cp.async.wait_group 0;\n" ::: "memory");
}

// ---------------------------------------------------------------------------
// Zero the padded-layout borders (row 0 and op[0] of every row).
// One block per (b, channel).
// ---------------------------------------------------------------------------
__global__ void zero_borders(float* buf) {
    float* p = buf + (size_t)blockIdx.x * PCH;
    int tid = threadIdx.x;
    for (int i = tid; i < PROW; i += 256) p[i] = 0.f;       // row 0
    p[(tid + 1) * PROW] = 0.f;                               // op[0], rows 1..256
}

// ---------------------------------------------------------------------------
// Stride-1 fused conv3x3 + bias + SiLU (encoders stage 1: CIN=3).
// 32x32 tile, COG=16. Table-driven cp.async staging (input is raw NCHW).
// OUTMODE: 0 = plain NCHW, 2 = padded parity-split.
// ---------------------------------------------------------------------------
template<int CIN, int OUTC, int OUTMODE>
__global__ void __launch_bounds__(256, 2) convfast(
    const float* __restrict__ in, const float* __restrict__ wgt,
    const float* __restrict__ bias, float* __restrict__ out,
    int Hin, int Win)
{
    constexpr int COG  = 16;
    constexpr int ITX  = 34;
    constexpr int SRS  = 36;
    constexpr int ELEMS = ITX * ITX;             // 1156
    constexpr int NIT  = (ELEMS + 255) / 256;    // 5
    constexpr int PLANE = ITX * SRS;

    extern __shared__ float sIn[];               // [2][PLANE]
    __shared__ float sW[2][COG*9 + 8];
    __shared__ int2 tTab[NIT*256];

    const int tid = threadIdx.x;
    const int tx = tid & 7, ty = tid >> 3;
    const int groups = OUTC / COG;
    const int b = blockIdx.z / groups;
    const int cbase = (blockIdx.z % groups) * COG;
    const int X0 = blockIdx.x * 32, Y0 = blockIdx.y * 32;
    const int iy0 = Y0 - 1, ix0 = X0 - 1;
    const size_t HW = (size_t)Hin * Win;
    const float* inb = in + (size_t)b * CIN * HW;

    const int wc = tid / 9, wtap = tid - wc*9;

#pragma unroll
    for (int k = 0; k < NIT; k++) {
        int f = k*256 + tid;
        int sof = -1, gof = -1;
        if (f < ELEMS) {
            int r = f / ITX, c = f - r*ITX;
            int ih = iy0 + r, iw = ix0 + c;
            sof = r*SRS + c;
            gof = ((unsigned)ih < (unsigned)Hin && (unsigned)iw < (unsigned)Win)
                  ? (ih*Win + iw) : -1;
        }
        tTab[k*256 + tid] = make_int2(gof, sof);
    }

    const unsigned sb0 = (unsigned)__cvta_generic_to_shared(sIn);
    auto stage = [&](int buf, int cin) {
        const float* ic = inb + (size_t)cin * HW;
        const unsigned sb = sb0 + (unsigned)buf * (PLANE*4);
#pragma unroll
        for (int k = 0; k < NIT; k++) {
            int2 t = tTab[k*256 + tid];
            if (t.y >= 0)
                cp_async4(sb + (unsigned)t.y*4, ic + (t.x < 0 ? 0 : t.x),
                          t.x < 0 ? 0 : 4);
        }
        if (tid < COG*9) {
            unsigned dst = (unsigned)__cvta_generic_to_shared(
                               &sW[buf][wtap*COG + wc]);
            cp_async4u(dst, wgt + ((size_t)(cbase+wc)*CIN + cin)*9 + wtap);
        }
    };

    stage(0, 0);
    cp_commit();
    cp_wait0();
    __syncthreads();

    float acc[4][COG];
#pragma unroll
    for (int j = 0; j < 4; j++)
#pragma unroll
        for (int c = 0; c < COG; c++) acc[j][c] = 0.f;

    for (int cin = 0; cin < CIN; cin++) {
        const int cur = cin & 1;
        if (cin + 1 < CIN) { stage(cur^1, cin+1); cp_commit(); }

        const float* sc  = sIn + cur*PLANE;
        const float* swp = sW[cur];
#pragma unroll
        for (int dy = 0; dy < 3; dy++) {
            const float* rp = sc + (ty + dy)*SRS + tx*4;
            float4 A = *(const float4*)rp;
            float2 Bv = *(const float2*)(rp + 4);
            float iv6[6] = {A.x, A.y, A.z, A.w, Bv.x, Bv.y};
#pragma unroll
            for (int dx = 0; dx < 3; dx++) {
                const float* wp = swp + (dy*3+dx)*COG;
                float4 w0 = *(const float4*)(wp);
                float4 w1 = *(const float4*)(wp + 4);
                float4 w2 = *(const float4*)(wp + 8);
                float4 w3 = *(const float4*)(wp + 12);
#pragma unroll
                for (int j = 0; j < 4; j++) {
                    float v = iv6[j+dx];
                    acc[j][0]  += v*w0.x; acc[j][1]  += v*w0.y;
                    acc[j][2]  += v*w0.z; acc[j][3]  += v*w0.w;
                    acc[j][4]  += v*w1.x; acc[j][5]  += v*w1.y;
                    acc[j][6]  += v*w1.z; acc[j][7]  += v*w1.w;
                    acc[j][8]  += v*w2.x; acc[j][9]  += v*w2.y;
                    acc[j][10] += v*w2.z; acc[j][11] += v*w2.w;
                    acc[j][12] += v*w3.x; acc[j][13] += v*w3.y;
                    acc[j][14] += v*w3.z; acc[j][15] += v*w3.w;
                }
            }
        }
        if (cin + 1 < CIN) cp_wait0();
        __syncthreads();
    }

    float bv[COG];
#pragma unroll
    for (int c = 0; c < COG; c++) bv[c] = __ldg(bias + cbase + c);

    const int oy = Y0 + ty;
    const int x0 = X0 + tx*4;
#pragma unroll
    for (int c = 0; c < COG; c++) {
        float vv[4];
#pragma unroll
        for (int j = 0; j < 4; j++) {
            float v = acc[j][c] + bv[c];
            vv[j] = v / (1.f + __expf(-v));
        }
        if (OUTMODE == 2) {
            size_t rowbase = ((size_t)(b*OUTC + cbase + c)*258 + (oy+1))*PROW;
            // evens (cols x0, x0+2) -> ep[x0/2], ep[x0/2+1]
            *(float2*)(out + rowbase + 132 + (x0>>1)) = make_float2(vv[0], vv[2]);
            // odds (cols x0+1, x0+3) -> op[x0/2+1], op[x0/2+2]
            out[rowbase + (x0>>1) + 1] = vv[1];
            out[rowbase + (x0>>1) + 2] = vv[3];
        } else {
            *(float4*)(out + (((size_t)b*OUTC + cbase + c)*Hin + oy)*Win + x0) =
                make_float4(vv[0], vv[1], vv[2], vv[3]);
        }
    }
}

// ---------------------------------------------------------------------------
// Stride-2 fused conv3x3 + bias + SiLU (encoders stage 2), padded input.
// 32x32 output tile, COG=16, thread = 4 x-pixels x 16 channels.
// smem seg0 (offset 0)  = op[X0+0..35] = global cols 2(X0+i)-1
// smem seg1 (offset 36) = ep[X0+0..35] = global cols 2(X0+i)
// Output x' (local): dx=0 -> op[x'] (E), dx=1 -> ep[x'] (O), dx=2 -> op[x'+1].
// Staging: 5 register-addressed cp.async.16 per cin per thread.
// ---------------------------------------------------------------------------
template<int CIN, int OUTC>
__global__ void __launch_bounds__(256, 2) convfast2(
    const float* __restrict__ in, const float* __restrict__ wgt,
    const float* __restrict__ bias, float* __restrict__ out)
{
    constexpr int COG  = 16;
    constexpr int SRS  = 72;
    constexpr int ODD  = 36;
    constexpr int PLANE = 65*SRS;
    constexpr int NOPS = 65*18;                  // 1170 float4 staging ops

    extern __shared__ float sIn[];               // [2][PLANE]
    __shared__ float sW[2][COG*9 + 8];

    const int tid = threadIdx.x;
    const int tx = tid & 7, ty = tid >> 3;
    const int groups = OUTC / COG;
    const int b = blockIdx.z / groups;
    const int cbase = (blockIdx.z % groups) * COG;
    const int X0 = blockIdx.x * 32, Y0 = blockIdx.y * 32;
    const float* inb = in + (size_t)b * CIN * PCH;

    const int wc = tid / 9, wtap = tid - wc*9;

    // cin-invariant staging offsets (5 per thread, in registers)
    int gofs[5]; int sofs[5];
#pragma unroll
    for (int k = 0; k < 5; k++) {
        int id = k*256 + tid;
        if (id < NOPS) {
            int row = id / 18;
            int rem = id - row*18;
            int seg = rem / 9;                   // 0 = op, 1 = ep
            int q   = rem - seg*9;
            gofs[k] = (2*Y0 + row)*PROW + seg*132 + X0 + q*4;
            sofs[k] = (row*SRS + seg*ODD + q*4) * 4;
        } else { gofs[k] = 0; sofs[k] = -1; }
    }

    const unsigned sb0 = (unsigned)__cvta_generic_to_shared(sIn);
    auto stage = [&](int buf, int cin) {
        const float* ic = inb + (size_t)cin * PCH;
        const unsigned sb = sb0 + (unsigned)buf * (PLANE*4);
#pragma unroll
        for (int k = 0; k < 5; k++)
            if (sofs[k] >= 0) cp_async16(sb + (unsigned)sofs[k], ic + gofs[k]);
        if (tid < COG*9) {
            unsigned dst = (unsigned)__cvta_generic_to_shared(
                               &sW[buf][wtap*COG + wc]);
            cp_async4u(dst, wgt + ((size_t)(cbase+wc)*CIN + cin)*9 + wtap);
        }
    };

    stage(0, 0);
    cp_commit();
    cp_wait0();
    __syncthreads();

    float acc[4][COG];
#pragma unroll
    for (int j = 0; j < 4; j++)
#pragma unroll
        for (int c = 0; c < COG; c++) acc[j][c] = 0.f;

    for (int cin = 0; cin < CIN; cin++) {
        const int cur = cin & 1;
        if (cin + 1 < CIN) { stage(cur^1, cin+1); cp_commit(); }

        const float* sc  = sIn + cur*PLANE;
        const float* swp = sW[cur];
#pragma unroll
        for (int dy = 0; dy < 3; dy++) {
            const float* rp = sc + (ty*2 + dy)*SRS;
            float4 E = *(const float4*)(rp + tx*4);          // op[4tx..4tx+3]
            float  e4 = rp[tx*4 + 4];                        // op[4tx+4]
            float4 O = *(const float4*)(rp + ODD + tx*4);    // ep[4tx..4tx+3]
            float V[3][4];
            V[0][0]=E.x; V[0][1]=E.y; V[0][2]=E.z; V[0][3]=E.w;  // dx=0: col 2x-1
            V[1][0]=O.x; V[1][1]=O.y; V[1][2]=O.z; V[1][3]=O.w;  // dx=1: col 2x
            V[2][0]=E.y; V[2][1]=E.z; V[2][2]=E.w; V[2][3]=e4;   // dx=2: col 2x+1
#pragma unroll
            for (int dx = 0; dx < 3; dx++) {
                const float* wp = swp + (dy*3+dx)*COG;
                float4 w0 = *(const float4*)(wp);
                float4 w1 = *(const float4*)(wp + 4);
                float4 w2 = *(const float4*)(wp + 8);
                float4 w3 = *(const float4*)(wp + 12);
#pragma unroll
                for (int j = 0; j < 4; j++) {
                    float v = V[dx][j];
                    acc[j][0]  += v*w0.x; acc[j][1]  += v*w0.y;
                    acc[j][2]  += v*w0.z; acc[j][3]  += v*w0.w;
                    acc[j][4]  += v*w1.x; acc[j][5]  += v*w1.y;
                    acc[j][6]  += v*w1.z; acc[j][7]  += v*w1.w;
                    acc[j][8]  += v*w2.x; acc[j][9]  += v*w2.y;
                    acc[j][10] += v*w2.z; acc[j][11] += v*w2.w;
                    acc[j][12] += v*w3.x; acc[j][13] += v*w3.y;
                    acc[j][14] += v*w3.z; acc[j][15] += v*w3.w;
                }
            }
        }
        if (cin + 1 < CIN) cp_wait0();
        __syncthreads();
    }

    float bv[COG];
#pragma unroll
    for (int c = 0; c < COG; c++) bv[c] = __ldg(bias + cbase + c);

    const int oy = Y0 + ty;
#pragma unroll
    for (int j = 0; j < 4; j++) {
        float vv[COG];
#pragma unroll
        for (int c = 0; c < COG; c++) {
            float v = acc[j][c] + bv[c];
            vv[c] = v / (1.f + __expf(-v));
        }
        size_t t = ((size_t)b*H2 + oy)*W2 + X0 + tx*4 + j;
        float4* op = (float4*)(out + t*OUTC + cbase);
        op[0] = make_float4(vv[0],  vv[1],  vv[2],  vv[3]);
        op[1] = make_float4(vv[4],  vv[5],  vv[6],  vv[7]);
        op[2] = make_float4(vv[8],  vv[9],  vv[10], vv[11]);
        op[3] = make_float4(vv[12], vv[13], vv[14], vv[15]);
    }
}

// ---------------------------------------------------------------------------
// Legacy conv (final tiny 3->3 decoder conv)
// ---------------------------------------------------------------------------
template<int CIN, int OUTC, int COG>
__global__ void __launch_bounds__(256) conv3x3(
    const float* __restrict__ in, const float* __restrict__ wgt,
    const float* __restrict__ bias, float* __restrict__ out,
    int Hin, int Win)
{
    constexpr int ITD = 18;
    __shared__ float sW[COG*CIN*9];
    __shared__ float sIn[ITD*ITD];

    const int tid = threadIdx.x;
    const int groups = OUTC / COG;
    const int b  = blockIdx.z / groups;
    const int cbase = (blockIdx.z % groups) * COG;

    for (int i = tid; i < COG*CIN*9; i += 256)
        sW[i] = wgt[(size_t)cbase*CIN*9 + i];

    const int ty = tid >> 4, tx = tid & 15;
    const int oy = blockIdx.y*16 + ty;
    const int ox = blockIdx.x*16 + tx;

    float acc[COG];
#pragma unroll
    for (int c = 0; c < COG; c++) acc[c] = 0.f;

    const float* inb = in + (size_t)b * CIN * Hin * Win;
    const int iy0 = blockIdx.y*16 - 1;
    const int ix0 = blockIdx.x*16 - 1;
    const int base = ty*ITD + tx;

    for (int cin = 0; cin < CIN; cin++) {
        __syncthreads();
        const float* ic = inb + (size_t)cin * Hin * Win;
        for (int i = tid; i < ITD*ITD; i += 256) {
            int r = i / ITD, cc = i - r*ITD;
            int ih = iy0 + r, iw = ix0 + cc;
            float v = 0.f;
            if ((unsigned)ih < (unsigned)Hin && (unsigned)iw < (unsigned)Win)
                v = ic[ih*Win + iw];
            sIn[i] = v;
        }
        __syncthreads();
        const float* wp = sW + cin*9;
#pragma unroll
        for (int dy = 0; dy < 3; dy++)
#pragma unroll
            for (int dx = 0; dx < 3; dx++) {
                float iv = sIn[base + dy*ITD + dx];
#pragma unroll
                for (int c = 0; c < COG; c++)
                    acc[c] += iv * wp[c*CIN*9 + dy*3 + dx];
            }
    }

#pragma unroll
    for (int c = 0; c < COG; c++) {
        float v = acc[c] + bias[cbase + c];
        v = v / (1.f + __expf(-v));
        out[(((size_t)b*OUTC + cbase + c)*Hin + oy)*Win + ox] = v;
    }
}

// ---------------------------------------------------------------------------
// Memcell pass 1: w = softmax(z @ K^T / 4) per token.
// ---------------------------------------------------------------------------
__global__ void __launch_bounds__(256) memcell_softmax(
    const float* __restrict__ z, const float* __restrict__ ck,
    float* __restrict__ wout)
{
    __shared__ float sK[Mm*Nn];
    const int tid = threadIdx.x;
    for (int i = tid; i < Mm*Nn; i += 256) sK[i] = ck[i];
    __syncthreads();

    const int t = blockIdx.x*256 + tid;
    const float4* zp = (const float4*)(z + (size_t)t*Nn);
    float4 z0 = zp[0], z1 = zp[1], z2 = zp[2], z3 = zp[3];

    float s[Mm];
    float mx = -1e30f;
#pragma unroll
    for (int m = 0; m < Mm; m++) {
        const float* k = sK + m*Nn;
        float d = z0.x*k[0] + z0.y*k[1] + z0.z*k[2] + z0.w*k[3]
                + z1.x*k[4] + z1.y*k[5] + z1.z*k[6] + z1.w*k[7]
                + z2.x*k[8] + z2.y*k[9] + z2.z*k[10]+ z2.w*k[11]
                + z3.x*k[12]+ z3.y*k[13]+ z3.z*k[14]+ z3.w*k[15];
        d *= 0.25f;
        s[m] = d;
        mx = fmaxf(mx, d);
    }
    float sum = 0.f;
#pragma unroll
    for (int m = 0; m < Mm; m++) { s[m] = __expf(s[m]-mx); sum += s[m]; }
    float inv = 1.f / sum;
    float4* wo = (float4*)(wout + (size_t)t*Mm);
#pragma unroll
    for (int j = 0; j < Mm/4; j++) {
        float4 v; v.x = s[4*j]*inv; v.y = s[4*j+1]*inv;
        v.z = s[4*j+2]*inv; v.w = s[4*j+3]*inv;
        wo[j] = v;
    }
}

// ---------------------------------------------------------------------------
// Memcell pass 2: block partials of [G | U], G = W^T W, U = W^T t_star.
// ---------------------------------------------------------------------------
__global__ void __launch_bounds__(256) memcell_outer(
    const float* __restrict__ wmat, const float* __restrict__ ts,
    float* __restrict__ part)
{
    __shared__ float sv[8*160];
    const int tid = threadIdx.x;
    const int ti = tid >> 5;
    const int tj = tid & 31;
    float acc[4][5];
#pragma unroll
    for (int a = 0; a < 4; a++)
#pragma unroll
        for (int q = 0; q < 5; q++) acc[a][q] = 0.f;

    const int tokb = blockIdx.x * 128;
    for (int ch = 0; ch < 128; ch += 8) {
        __syncthreads();
#pragma unroll
        for (int l = 0; l < 5; l++) {
            int idx = l*256 + tid;
            int tk = idx / 160, f = idx - tk*160;
            int t = tokb + ch + tk;
            sv[tk*160 + f] = (f < 32) ? wmat[(size_t)t*32 + f]
                                      : ts[(size_t)t*128 + (f-32)];
        }
        __syncthreads();
#pragma unroll
        for (int tk = 0; tk < 8; tk++) {
            float wi[4], vj[5];
#pragma unroll
            for (int a = 0; a < 4; a++) wi[a] = sv[tk*160 + ti*4 + a];
#pragma unroll
            for (int q = 0; q < 5; q++) vj[q] = sv[tk*160 + tj*5 + q];
#pragma unroll
            for (int a = 0; a < 4; a++)
#pragma unroll
                for (int q = 0; q < 5; q++) acc[a][q] += wi[a]*vj[q];
        }
    }
    float* pp = part + (size_t)blockIdx.x * 5120;
#pragma unroll
    for (int a = 0; a < 4; a++)
#pragma unroll
        for (int q = 0; q < 5; q++)
            pp[(ti*4+a)*160 + tj*5 + q] = acc[a][q];
}

__global__ void __launch_bounds__(256) reduce_partials(
    const float* __restrict__ part, float* __restrict__ gu)
{
    int cell = blockIdx.x*256 + threadIdx.x;
    float s = 0.f;
#pragma unroll 8
    for (int p = 0; p < 1024; p++) s += part[(size_t)p*5120 + cell];
    gu[cell] = s;
}

__global__ void __launch_bounds__(256) cell_update(
    const float* __restrict__ gu, const float* __restrict__ cv,
    float* __restrict__ vnew)
{
    __shared__ float sG[Mm*Mm];
    __shared__ float sV[Mm*Ss];
    const int tid = threadIdx.x;
    for (int i = tid; i < Mm*Mm; i += 256) {
        int m = i >> 5, j = i & 31;
        sG[i] = gu[m*160 + j];
    }
    for (int i = tid; i < Mm*Ss; i += 256) sV[i] = cv[i];
    __syncthreads();
    for (int k = 0; k < 16; k++) {
        int cell = k*256 + tid;
        int m = cell >> 7, s0 = cell & 127;
        float d = gu[m*160 + 32 + s0];
#pragma unroll
        for (int mp = 0; mp < Mm; mp++) d -= sG[m*32 + mp] * sV[mp*128 + s0];
        vnew[cell] = sV[cell] + ALPHA * d;
    }
}

// ---------------------------------------------------------------------------
// Memcell pass 3: t_read = W @ cell_v_new -> NCHW [B,S,H2,W2].
// ---------------------------------------------------------------------------
__global__ void __launch_bounds__(256) memcell_read(
    const float* __restrict__ wmat, const float* __restrict__ vnew,
    float* __restrict__ d0m)
{
    __shared__ float sV[Mm*Ss];
    __shared__ float sW[64*33];
    const int tid = threadIdx.x;
    for (int i = tid; i < Mm*Ss; i += 256) sV[i] = vnew[i];
    const int tbase = blockIdx.x * 64;
    for (int i = tid; i < 64*32; i += 256) {
        int tk = i >> 5, m = i & 31;
        sW[tk*33 + m] = wmat[(size_t)(tbase + tk)*32 + m];
    }
    __syncthreads();

    const int lane = tid & 31, wid = tid >> 5;
    const int cb = wid * 16;
    float a0[16], a1[16];
#pragma unroll
    for (int c = 0; c < 16; c++) { a0[c] = 0.f; a1[c] = 0.f; }

    const float* w0 = sW + lane*33;
    const float* w1 = sW + (lane + 32)*33;
#pragma unroll 4
    for (int m = 0; m < Mm; m++) {
        float x0 = w0[m], x1 = w1[m];
        const float4* vv = (const float4*)(sV + m*128 + cb);
#pragma unroll
        for (int q = 0; q < 4; q++) {
            float4 v = vv[q];
            a0[q*4+0] += x0*v.x; a0[q*4+1] += x0*v.y;
            a0[q*4+2] += x0*v.z; a0[q*4+3] += x0*v.w;
            a1[q*4+0] += x1*v.x; a1[q*4+1] += x1*v.y;
            a1[q*4+2] += x1*v.z; a1[q*4+3] += x1*v.w;
        }
    }
    const int b = tbase >> 14;
    const int rem = tbase & 16383;
    const int h = rem >> 7;
    const int wcp = rem & 127;
    size_t obase = ((size_t)b*Ss)*((size_t)H2*W2) + (size_t)h*W2 + wcp;
#pragma unroll
    for (int c = 0; c < 16; c++) {
        size_t o = obase + (size_t)(cb + c)*(H2*W2);
        d0m[o + lane]      = a0[c];
        d0m[o + 32 + lane] = a1[c];
    }
}

// ---------------------------------------------------------------------------
// ConvTranspose2d(128->3, k4, s2, p1) + bias + SiLU.  32x32 output tiles
// (4 px/thread, same parity -> one weight set); input re-reads cut 4x.
// ---------------------------------------------------------------------------
__global__ void __launch_bounds__(256) deconv_kernel(
    const float* __restrict__ in, const float* __restrict__ dw,
    const float* __restrict__ db, float* __restrict__ out)
{
    __shared__ float sWd[4*128*12];              // [parity][cin][o][k] 24.6 KB
    __shared__ float sIn[16*324];                // 16 cins x 18x18 (20.7 KB)
    const int tid = threadIdx.x;
    for (int i = tid; i < 4*128*12; i += 256) {
        int p = i / 1536, rem = i - p*1536;
        int cin = rem / 12, rr = rem - cin*12;
        int o = rr >> 2, k = rr & 3;
        int py = p >> 1, px = p & 1;
        int ky = py + 2*(k >> 1), kx = px + 2*(k & 1);
        sWd[i] = dw[cin*48 + o*16 + ky*4 + kx];
    }

    const int b  = blockIdx.z;
    const int Y0 = blockIdx.y*32, X0 = blockIdx.x*32;
    const int ty = tid >> 4, tx = tid & 15;
    const int y0 = Y0 + ty, x0 = X0 + tx;
    const int hb = (Y0 >> 1) - 1, wb = (X0 >> 1) - 1;

    const int py = (y0 + 1) & 1, px = (x0 + 1) & 1;
    const int hs0 = ((y0 + 1 - py) >> 1) - hb;   // 1..9
    const int ws0 = ((x0 + 1 - px) >> 1) - wb;

    const float* wp = sWd + (py*2 + px)*1536;
    float acc[2][2][3];
#pragma unroll
    for (int a = 0; a < 2; a++)
#pragma unroll
        for (int e = 0; e < 2; e++)
#pragma unroll
            for (int o = 0; o < 3; o++) acc[a][e][o] = 0.f;

    const float* inb = in + (size_t)b * Ss * H2 * W2;

    for (int c0 = 0; c0 < Ss; c0 += 16) {
        __syncthreads();
        for (int i = tid; i < 16*324; i += 256) {
            int c = i / 324, rr = i - c*324;
            int r = rr / 18, cc = rr - r*18;
            int h = hb + r, w = wb + cc;
            float v = 0.f;
            if ((unsigned)h < (unsigned)H2 && (unsigned)w < (unsigned)W2)
                v = inb[((size_t)(c0 + c)*H2 + h)*W2 + w];
            sIn[i] = v;
        }
        __syncthreads();
#pragma unroll
        for (int c = 0; c < 16; c++) {
            const float* sc = sIn + c*324;
            const float4* w4 = (const float4*)(wp + (c0 + c)*12);
            float4 Wa = w4[0], Wb = w4[1], Wc = w4[2];
#pragma unroll
            for (int a = 0; a < 2; a++)
#pragma unroll
                for (int e = 0; e < 2; e++) {
                    int hh = hs0 + 8*a, ww = ws0 + 8*e;
                    float i00 = sc[hh*18 + ww];
                    float i01 = sc[hh*18 + ww - 1];
                    float i10 = sc[(hh-1)*18 + ww];
                    float i11 = sc[(hh-1)*18 + ww - 1];
                    acc[a][e][0] += i00*Wa.x + i01*Wa.y + i10*Wa.z + i11*Wa.w;
                    acc[a][e][1] += i00*Wb.x + i01*Wb.y + i10*Wb.z + i11*Wb.w;
                    acc[a][e][2] += i00*Wc.x + i01*Wc.y + i10*Wc.z + i11*Wc.w;
                }
        }
    }
#pragma unroll
    for (int a = 0; a < 2; a++)
#pragma unroll
        for (int e = 0; e < 2; e++)
#pragma unroll
            for (int o = 0; o < 3; o++) {
                float v = acc[a][e][o] + db[o];
                v = v / (1.f + __expf(-v));
                out[(((size_t)b*3 + o)*HIN + y0 + 16*a)*WIN + x0 + 16*e] = v;
            }
}

// ---------------------------------------------------------------------------
// Launch sequence
// ---------------------------------------------------------------------------
extern "C" void kernel_launch(void* const* d_in, const int* in_sizes, int n_in,
                              void* d_out, int out_size)
{
    const float* x      = (const float*)d_in[0];
    const float* e0n_w1 = (const float*)d_in[1];
    const float* e0n_b1 = (const float*)d_in[2];
    const float* e0n_w2 = (const float*)d_in[3];
    const float* e0n_b2 = (const float*)d_in[4];
    const float* e0s_w1 = (const float*)d_in[5];
    const float* e0s_b1 = (const float*)d_in[6];
    const float* e0s_w2 = (const float*)d_in[7];
    const float* e0s_b2 = (const float*)d_in[8];
    const float* d0_dw  = (const float*)d_in[9];
    const float* d0_db  = (const float*)d_in[10];
    const float* d0_cw  = (const float*)d_in[11];
    const float* d0_cb  = (const float*)d_in[12];
    const float* cell_k = (const float*)d_in[13];
    const float* cell_v = (const float*)d_in[14];
    float* outp = (float*)d_out;

    void *p_a1n, *p_a1s, *p_z, *p_ts, *p_w, *p_part, *p_gu, *p_vnew, *p_d0m, *p_dec;
    cudaGetSymbolAddress(&p_a1n, g_a1n);
    cudaGetSymbolAddress(&p_a1s, g_a1s);
    cudaGetSymbolAddress(&p_z,   g_z);
    cudaGetSymbolAddress(&p_ts,  g_ts);
    cudaGetSymbolAddress(&p_w,   g_w);
    cudaGetSymbolAddress(&p_part,g_part);
    cudaGetSymbolAddress(&p_gu,  g_gu);
    cudaGetSymbolAddress(&p_vnew,g_vnew);
    cudaGetSymbolAddress(&p_d0m, g_d0m);
    cudaGetSymbolAddress(&p_dec, g_dec);

    const int dsm_s1 = 2 * 34 * 36 * 4;   //  9792 B
    const int dsm_s2 = 2 * 65 * 72 * 4;   // 37440 B

    cudaFuncSetAttribute((const void*)convfast<3,16,2>,
                         cudaFuncAttributeMaxDynamicSharedMemorySize, dsm_s1);
    cudaFuncSetAttribute((const void*)convfast<3,128,2>,
                         cudaFuncAttributeMaxDynamicSharedMemorySize, dsm_s1);
    cudaFuncSetAttribute((const void*)convfast2<16,16>,
                         cudaFuncAttributeMaxDynamicSharedMemorySize, dsm_s2);
    cudaFuncSetAttribute((const void*)convfast2<128,128>,
                         cudaFuncAttributeMaxDynamicSharedMemorySize, dsm_s2);

    // Borders of the padded intermediates (disjoint from conv1 writes)
    zero_borders<<<Bb*Nn, 256>>>((float*)p_a1n);
    zero_borders<<<Bb*Ss, 256>>>((float*)p_a1s);

    // Encoders
    convfast<3,16,2><<<dim3(8,8,Bb),256,dsm_s1>>>(
        x, e0n_w1, e0n_b1, (float*)p_a1n, HIN, WIN);
    convfast<3,128,2><<<dim3(8,8,Bb*8),256,dsm_s1>>>(
        x, e0s_w1, e0s_b1, (float*)p_a1s, HIN, WIN);
    convfast2<16,16><<<dim3(4,4,Bb),256,dsm_s2>>>(
        (const float*)p_a1n, e0n_w2, e0n_b2, (float*)p_z);
    convfast2<128,128><<<dim3(4,4,Bb*8),256,dsm_s2>>>(
        (const float*)p_a1s, e0s_w2, e0s_b2, (float*)p_ts);

    // Memcell
    memcell_softmax<<<Tt/256,256>>>((const float*)p_z, cell_k, (float*)p_w);
    memcell_outer<<<1024,256>>>((const float*)p_w, (const float*)p_ts, (float*)p_part);
    reduce_partials<<<20,256>>>((const float*)p_part, (float*)p_gu);
    cell_update<<<1,256>>>((const float*)p_gu, cell_v, (float*)p_vnew);
    memcell_read<<<Tt/64,256>>>((const float*)p_w, (const float*)p_vnew, (float*)p_d0m);

    // Decoder
    deconv_kernel<<<dim3(8,8,Bb),256>>>(
        (const float*)p_d0m, d0_dw, d0_db, (float*)p_dec);
    conv3x3<3,3,3><<<dim3(16,16,Bb),256>>>(
        (const float*)p_dec, d0_cw, d0_cb, outp, HIN, WIN);
}

// round 12
// speedup vs baseline: 2.3458x; 1.0406x over previous
#include <cuda_runtime.h>
#include <cuda_bf16.h>
#include <cstdint>

// ---------------------------------------------------------------------------
// Problem constants
// ---------------------------------------------------------------------------
#define Bb   8
#define HIN  256
#define WIN  256
#define H2   128
#define W2   128
#define Nn   16
#define Mm   32
#define Ss   128
#define Tt   (Bb*H2*W2)          // 131072 tokens
#define ALPHA 1e-6f

// Padded parity-split activation layout (per channel):
//   258 rows (row = image_y + 1; row 0 = top border of zeros)
//   row = [op 132 | ep 132]  (264 floats, 1056B)
//   op[k] = col 2k-1  (k=0..128; op[0] = col -1, zeroed border)
//   ep[k] = col 2k    (k=0..127 valid)
#define PROW 264
#define PCH  (258*PROW)

typedef unsigned long long u64;

// ---------------------------------------------------------------------------
// Scratch buffers (static device globals; no cudaMalloc allowed)
// ---------------------------------------------------------------------------
__device__ float g_a1n [(size_t)Bb*Nn*PCH];      // padded silu(conv1_n)
__device__ float g_a1s [(size_t)Bb*Ss*PCH];      // padded silu(conv1_s) ~279MB
__device__ float g_z   [(size_t)Tt*Nn];
__device__ float g_ts  [(size_t)Tt*Ss];
__device__ float g_w   [(size_t)Tt*Mm];
__device__ float g_part[(size_t)1024*32*160];
__device__ float g_gu  [32*160];
__device__ float g_vnew[Mm*Ss];
__device__ float g_d0m [(size_t)Bb*Ss*H2*W2];
__device__ float g_dec [(size_t)Bb*3*HIN*WIN];

// ---------------------------------------------------------------------------
// cp.async + f32x2 helpers
// ---------------------------------------------------------------------------
__device__ __forceinline__ void cp_async4(unsigned dst, const float* src, int sz) {
    asm volatile("cp.async.ca.shared.global [%0], [%1], 4, %2;\n"
                 :: "r"(dst), "l"(src), "r"(sz));
}
__device__ __forceinline__ void cp_async4u(unsigned dst, const float* src) {
    asm volatile("cp.async.ca.shared.global [%0], [%1], 4;\n"
                 :: "r"(dst), "l"(src));
}
__device__ __forceinline__ void cp_async16(unsigned dst, const float* src) {
    asm volatile("cp.async.cg.shared.global [%0], [%1], 16;\n"
                 :: "r"(dst), "l"(src));
}
__device__ __forceinline__ void cp_commit() {
    asm volatile("cp.async.commit_group;\n" ::: "memory");
}
__device__ __forceinline__ void cp_wait0() {
    asm volatile("cp.async.wait_group 0;\n" ::: "memory");
}

// packed fp32x2 FMA: d = a*b + d  (two independent rn-rounded fp32 FMAs)
#define FMA2(d, a, b) \
    asm("fma.rn.f32x2 %0, %1, %2, %0;" : "+l"(d) : "l"(a), "l"(b))
#define PACK2(dst, v) \
    asm("mov.b64 %0, {%1, %1};" : "=l"(dst) : "f"(v))
#define UNPACK2(lo, hi, src) \
    asm("mov.b64 {%0, %1}, %2;" : "=f"(lo), "=f"(hi) : "l"(src))

// 8-pair FFMA2 block: acc[0..7] += {v,v} * w[0..7]
__device__ __forceinline__ void fma2_row(u64* acc, float v,
                                         const ulonglong2& q0, const ulonglong2& q1,
                                         const ulonglong2& q2, const ulonglong2& q3) {
    u64 vv; PACK2(vv, v);
    FMA2(acc[0], vv, q0.x); FMA2(acc[1], vv, q0.y);
    FMA2(acc[2], vv, q1.x); FMA2(acc[3], vv, q1.y);
    FMA2(acc[4], vv, q2.x); FMA2(acc[5], vv, q2.y);
    FMA2(acc[6], vv, q3.x); FMA2(acc[7], vv, q3.y);
}

// ---------------------------------------------------------------------------
// Zero the padded-layout borders (row 0 and op[0] of every row).
// ---------------------------------------------------------------------------
__global__ void zero_borders(float* buf) {
    float* p = buf + (size_t)blockIdx.x * PCH;
    int tid = threadIdx.x;
    for (int i = tid; i < PROW; i += 256) p[i] = 0.f;       // row 0
    p[(tid + 1) * PROW] = 0.f;                               // op[0], rows 1..256
}

// ---------------------------------------------------------------------------
// Stride-1 fused conv3x3 + bias + SiLU (encoders stage 1: CIN=3).
// 32x32 tile, COG=16, f32x2 inner loop. OUTMODE: 0=NCHW, 2=padded parity.
// ---------------------------------------------------------------------------
template<int CIN, int OUTC, int OUTMODE>
__global__ void __launch_bounds__(256, 2) convfast(
    const float* __restrict__ in, const float* __restrict__ wgt,
    const float* __restrict__ bias, float* __restrict__ out,
    int Hin, int Win)
{
    constexpr int COG  = 16;
    constexpr int ITX  = 34;
    constexpr int SRS  = 36;
    constexpr int ELEMS = ITX * ITX;             // 1156
    constexpr int NIT  = (ELEMS + 255) / 256;    // 5
    constexpr int PLANE = ITX * SRS;

    extern __shared__ float sIn[];               // [2][PLANE]
    __shared__ float sW[2][COG*9 + 8];
    __shared__ int2 tTab[NIT*256];

    const int tid = threadIdx.x;
    const int tx = tid & 7, ty = tid >> 3;
    const int groups = OUTC / COG;
    const int b = blockIdx.z / groups;
    const int cbase = (blockIdx.z % groups) * COG;
    const int X0 = blockIdx.x * 32, Y0 = blockIdx.y * 32;
    const int iy0 = Y0 - 1, ix0 = X0 - 1;
    const size_t HW = (size_t)Hin * Win;
    const float* inb = in + (size_t)b * CIN * HW;

    const int wc = tid / 9, wtap = tid - wc*9;

#pragma unroll
    for (int k = 0; k < NIT; k++) {
        int f = k*256 + tid;
        int sof = -1, gof = -1;
        if (f < ELEMS) {
            int r = f / ITX, c = f - r*ITX;
            int ih = iy0 + r, iw = ix0 + c;
            sof = r*SRS + c;
            gof = ((unsigned)ih < (unsigned)Hin && (unsigned)iw < (unsigned)Win)
                  ? (ih*Win + iw) : -1;
        }
        tTab[k*256 + tid] = make_int2(gof, sof);
    }

    const unsigned sb0 = (unsigned)__cvta_generic_to_shared(sIn);
    auto stage = [&](int buf, int cin) {
        const float* ic = inb + (size_t)cin * HW;
        const unsigned sb = sb0 + (unsigned)buf * (PLANE*4);
#pragma unroll
        for (int k = 0; k < NIT; k++) {
            int2 t = tTab[k*256 + tid];
            if (t.y >= 0)
                cp_async4(sb + (unsigned)t.y*4, ic + (t.x < 0 ? 0 : t.x),
                          t.x < 0 ? 0 : 4);
        }
        if (tid < COG*9) {
            unsigned dst = (unsigned)__cvta_generic_to_shared(
                               &sW[buf][wtap*COG + wc]);
            cp_async4u(dst, wgt + ((size_t)(cbase+wc)*CIN + cin)*9 + wtap);
        }
    };

    stage(0, 0);
    cp_commit();
    cp_wait0();
    __syncthreads();

    u64 acc2[4][8];
#pragma unroll
    for (int j = 0; j < 4; j++)
#pragma unroll
        for (int p = 0; p < 8; p++) acc2[j][p] = 0ull;

    for (int cin = 0; cin < CIN; cin++) {
        const int cur = cin & 1;
        if (cin + 1 < CIN) { stage(cur^1, cin+1); cp_commit(); }

        const float* sc  = sIn + cur*PLANE;
        const float* swp = sW[cur];
#pragma unroll
        for (int dy = 0; dy < 3; dy++) {
            const float* rp = sc + (ty + dy)*SRS + tx*4;
            float4 A = *(const float4*)rp;
            float2 Bv = *(const float2*)(rp + 4);
            float iv6[6] = {A.x, A.y, A.z, A.w, Bv.x, Bv.y};
#pragma unroll
            for (int dx = 0; dx < 3; dx++) {
                const ulonglong2* wq = (const ulonglong2*)(swp + (dy*3+dx)*COG);
                ulonglong2 q0 = wq[0], q1 = wq[1], q2 = wq[2], q3 = wq[3];
#pragma unroll
                for (int j = 0; j < 4; j++)
                    fma2_row(acc2[j], iv6[j+dx], q0, q1, q2, q3);
            }
        }
        if (cin + 1 < CIN) cp_wait0();
        __syncthreads();
    }

    float bv[COG];
#pragma unroll
    for (int c = 0; c < COG; c++) bv[c] = __ldg(bias + cbase + c);

    const int oy = Y0 + ty;
    const int x0 = X0 + tx*4;
#pragma unroll
    for (int c = 0; c < COG; c++) {
        float vv[4];
#pragma unroll
        for (int j = 0; j < 4; j++) {
            float lo, hi;
            UNPACK2(lo, hi, acc2[j][c >> 1]);
            float v = ((c & 1) ? hi : lo) + bv[c];
            vv[j] = v / (1.f + __expf(-v));
        }
        if (OUTMODE == 2) {
            size_t rowbase = ((size_t)(b*OUTC + cbase + c)*258 + (oy+1))*PROW;
            // evens (cols x0, x0+2) -> ep[x0/2], ep[x0/2+1]
            *(float2*)(out + rowbase + 132 + (x0>>1)) = make_float2(vv[0], vv[2]);
            // odds (cols x0+1, x0+3) -> op[x0/2+1], op[x0/2+2]
            out[rowbase + (x0>>1) + 1] = vv[1];
            out[rowbase + (x0>>1) + 2] = vv[3];
        } else {
            *(float4*)(out + (((size_t)b*OUTC + cbase + c)*Hin + oy)*Win + x0) =
                make_float4(vv[0], vv[1], vv[2], vv[3]);
        }
    }
}

// ---------------------------------------------------------------------------
// Stride-2 fused conv3x3 + bias + SiLU (encoders stage 2), padded input.
// 32x32 output tile, COG=16, f32x2 inner loop.
// smem seg0 (offset 0)  = op[...] = global cols 2x-1 (dx=0, dx=2 shifted)
// smem seg1 (offset 36) = ep[...] = global cols 2x   (dx=1)
// ---------------------------------------------------------------------------
template<int CIN, int OUTC>
__global__ void __launch_bounds__(256, 2) convfast2(
    const float* __restrict__ in, const float* __restrict__ wgt,
    const float* __restrict__ bias, float* __restrict__ out)
{
    constexpr int COG  = 16;
    constexpr int SRS  = 72;
    constexpr int ODD  = 36;
    constexpr int PLANE = 65*SRS;
    constexpr int NOPS = 65*18;                  // 1170 float4 staging ops

    extern __shared__ float sIn[];               // [2][PLANE]
    __shared__ float sW[2][COG*9 + 8];

    const int tid = threadIdx.x;
    const int tx = tid & 7, ty = tid >> 3;
    const int groups = OUTC / COG;
    const int b = blockIdx.z / groups;
    const int cbase = (blockIdx.z % groups) * COG;
    const int X0 = blockIdx.x * 32, Y0 = blockIdx.y * 32;
    const float* inb = in + (size_t)b * CIN * PCH;

    const int wc = tid / 9, wtap = tid - wc*9;

    // cin-invariant staging offsets (5 per thread, in registers)
    int gofs[5]; int sofs[5];
#pragma unroll
    for (int k = 0; k < 5; k++) {
        int id = k*256 + tid;
        if (id < NOPS) {
            int row = id / 18;
            int rem = id - row*18;
            int seg = rem / 9;                   // 0 = op, 1 = ep
            int q   = rem - seg*9;
            gofs[k] = (2*Y0 + row)*PROW + seg*132 + X0 + q*4;
            sofs[k] = (row*SRS + seg*ODD + q*4) * 4;
        } else { gofs[k] = 0; sofs[k] = -1; }
    }

    const unsigned sb0 = (unsigned)__cvta_generic_to_shared(sIn);
    auto stage = [&](int buf, int cin) {
        const float* ic = inb + (size_t)cin * PCH;
        const unsigned sb = sb0 + (unsigned)buf * (PLANE*4);
#pragma unroll
        for (int k = 0; k < 5; k++)
            if (sofs[k] >= 0) cp_async16(sb + (unsigned)sofs[k], ic + gofs[k]);
        if (tid < COG*9) {
            unsigned dst = (unsigned)__cvta_generic_to_shared(
                               &sW[buf][wtap*COG + wc]);
            cp_async4u(dst, wgt + ((size_t)(cbase+wc)*CIN + cin)*9 + wtap);
        }
    };

    stage(0, 0);
    cp_commit();
    cp_wait0();
    __syncthreads();

    u64 acc2[4][8];
#pragma unroll
    for (int j = 0; j < 4; j++)
#pragma unroll
        for (int p = 0; p < 8; p++) acc2[j][p] = 0ull;

    for (int cin = 0; cin < CIN; cin++) {
        const int cur = cin & 1;
        if (cin + 1 < CIN) { stage(cur^1, cin+1); cp_commit(); }

        const float* sc  = sIn + cur*PLANE;
        const float* swp = sW[cur];
#pragma unroll
        for (int dy = 0; dy < 3; dy++) {
            const float* rp = sc + (ty*2 + dy)*SRS;
            float4 E = *(const float4*)(rp + tx*4);          // op[4tx..4tx+3]
            float  e4 = rp[tx*4 + 4];                        // op[4tx+4]
            float4 O = *(const float4*)(rp + ODD + tx*4);    // ep[4tx..4tx+3]
            float V[3][4];
            V[0][0]=E.x; V[0][1]=E.y; V[0][2]=E.z; V[0][3]=E.w;  // dx=0: col 2x-1
            V[1][0]=O.x; V[1][1]=O.y; V[1][2]=O.z; V[1][3]=O.w;  // dx=1: col 2x
            V[2][0]=E.y; V[2][1]=E.z; V[2][2]=E.w; V[2][3]=e4;   // dx=2: col 2x+1
#pragma unroll
            for (int dx = 0; dx < 3; dx++) {
                const ulonglong2* wq = (const ulonglong2*)(swp + (dy*3+dx)*COG);
                ulonglong2 q0 = wq[0], q1 = wq[1], q2 = wq[2], q3 = wq[3];
#pragma unroll
                for (int j = 0; j < 4; j++)
                    fma2_row(acc2[j], V[dx][j], q0, q1, q2, q3);
            }
        }
        if (cin + 1 < CIN) cp_wait0();
        __syncthreads();
    }

    float bv[COG];
#pragma unroll
    for (int c = 0; c < COG; c++) bv[c] = __ldg(bias + cbase + c);

    const int oy = Y0 + ty;
#pragma unroll
    for (int j = 0; j < 4; j++) {
        float vv[COG];
#pragma unroll
        for (int p = 0; p < 8; p++) {
            float lo, hi;
            UNPACK2(lo, hi, acc2[j][p]);
            float v0 = lo + bv[2*p],     v1 = hi + bv[2*p+1];
            vv[2*p]   = v0 / (1.f + __expf(-v0));
            vv[2*p+1] = v1 / (1.f + __expf(-v1));
        }
        size_t t = ((size_t)b*H2 + oy)*W2 + X0 + tx*4 + j;
        float4* op = (float4*)(out + t*OUTC + cbase);
        op[0] = make_float4(vv[0],  vv[1],  vv[2],  vv[3]);
        op[1] = make_float4(vv[4],  vv[5],  vv[6],  vv[7]);
        op[2] = make_float4(vv[8],  vv[9],  vv[10], vv[11]);
        op[3] = make_float4(vv[12], vv[13], vv[14], vv[15]);
    }
}

// ---------------------------------------------------------------------------
// Legacy conv (final tiny 3->3 decoder conv)
// ---------------------------------------------------------------------------
template<int CIN, int OUTC, int COG>
__global__ void __launch_bounds__(256) conv3x3(
    const float* __restrict__ in, const float* __restrict__ wgt,
    const float* __restrict__ bias, float* __restrict__ out,
    int Hin, int Win)
{
    constexpr int ITD = 18;
    __shared__ float sW[COG*CIN*9];
    __shared__ float sIn[ITD*ITD];

    const int tid = threadIdx.x;
    const int groups = OUTC / COG;
    const int b  = blockIdx.z / groups;
    const int cbase = (blockIdx.z % groups) * COG;

    for (int i = tid; i < COG*CIN*9; i += 256)
        sW[i] = wgt[(size_t)cbase*CIN*9 + i];

    const int ty = tid >> 4, tx = tid & 15;
    const int oy = blockIdx.y*16 + ty;
    const int ox = blockIdx.x*16 + tx;

    float acc[COG];
#pragma unroll
    for (int c = 0; c < COG; c++) acc[c] = 0.f;

    const float* inb = in + (size_t)b * CIN * Hin * Win;
    const int iy0 = blockIdx.y*16 - 1;
    const int ix0 = blockIdx.x*16 - 1;
    const int base = ty*ITD + tx;

    for (int cin = 0; cin < CIN; cin++) {
        __syncthreads();
        const float* ic = inb + (size_t)cin * Hin * Win;
        for (int i = tid; i < ITD*ITD; i += 256) {
            int r = i / ITD, cc = i - r*ITD;
            int ih = iy0 + r, iw = ix0 + cc;
            float v = 0.f;
            if ((unsigned)ih < (unsigned)Hin && (unsigned)iw < (unsigned)Win)
                v = ic[ih*Win + iw];
            sIn[i] = v;
        }
        __syncthreads();
        const float* wp = sW + cin*9;
#pragma unroll
        for (int dy = 0; dy < 3; dy++)
#pragma unroll
            for (int dx = 0; dx < 3; dx++) {
                float iv = sIn[base + dy*ITD + dx];
#pragma unroll
                for (int c = 0; c < COG; c++)
                    acc[c] += iv * wp[c*CIN*9 + dy*3 + dx];
            }
    }

#pragma unroll
    for (int c = 0; c < COG; c++) {
        float v = acc[c] + bias[cbase + c];
        v = v / (1.f + __expf(-v));
        out[(((size_t)b*OUTC + cbase + c)*Hin + oy)*Win + ox] = v;
    }
}

// ---------------------------------------------------------------------------
// Memcell pass 1: w = softmax(z @ K^T / 4) per token.
// ---------------------------------------------------------------------------
__global__ void __launch_bounds__(256) memcell_softmax(
    const float* __restrict__ z, const float* __restrict__ ck,
    float* __restrict__ wout)
{
    __shared__ float sK[Mm*Nn];
    const int tid = threadIdx.x;
    for (int i = tid; i < Mm*Nn; i += 256) sK[i] = ck[i];
    __syncthreads();

    const int t = blockIdx.x*256 + tid;
    const float4* zp = (const float4*)(z + (size_t)t*Nn);
    float4 z0 = zp[0], z1 = zp[1], z2 = zp[2], z3 = zp[3];

    float s[Mm];
    float mx = -1e30f;
#pragma unroll
    for (int m = 0; m < Mm; m++) {
        const float* k = sK + m*Nn;
        float d = z0.x*k[0] + z0.y*k[1] + z0.z*k[2] + z0.w*k[3]
                + z1.x*k[4] + z1.y*k[5] + z1.z*k[6] + z1.w*k[7]
                + z2.x*k[8] + z2.y*k[9] + z2.z*k[10]+ z2.w*k[11]
                + z3.x*k[12]+ z3.y*k[13]+ z3.z*k[14]+ z3.w*k[15];
        d *= 0.25f;
        s[m] = d;
        mx = fmaxf(mx, d);
    }
    float sum = 0.f;
#pragma unroll
    for (int m = 0; m < Mm; m++) { s[m] = __expf(s[m]-mx); sum += s[m]; }
    float inv = 1.f / sum;
    float4* wo = (float4*)(wout + (size_t)t*Mm);
#pragma unroll
    for (int j = 0; j < Mm/4; j++) {
        float4 v; v.x = s[4*j]*inv; v.y = s[4*j+1]*inv;
        v.z = s[4*j+2]*inv; v.w = s[4*j+3]*inv;
        wo[j] = v;
    }
}

// ---------------------------------------------------------------------------
// Memcell pass 2: block partials of [G | U], G = W^T W, U = W^T t_star.
// ---------------------------------------------------------------------------
__global__ void __launch_bounds__(256) memcell_outer(
    const float* __restrict__ wmat, const float* __restrict__ ts,
    float* __restrict__ part)
{
    __shared__ float sv[8*160];
    const int tid = threadIdx.x;
    const int ti = tid >> 5;
    const int tj = tid & 31;
    float acc[4][5];
#pragma unroll
    for (int a = 0; a < 4; a++)
#pragma unroll
        for (int q = 0; q < 5; q++) acc[a][q] = 0.f;

    const int tokb = blockIdx.x * 128;
    for (int ch = 0; ch < 128; ch += 8) {
        __syncthreads();
#pragma unroll
        for (int l = 0; l < 5; l++) {
            int idx = l*256 + tid;
            int tk = idx / 160, f = idx - tk*160;
            int t = tokb + ch + tk;
            sv[tk*160 + f] = (f < 32) ? wmat[(size_t)t*32 + f]
                                      : ts[(size_t)t*128 + (f-32)];
        }
        __syncthreads();
#pragma unroll
        for (int tk = 0; tk < 8; tk++) {
            float wi[4], vj[5];
#pragma unroll
            for (int a = 0; a < 4; a++) wi[a] = sv[tk*160 + ti*4 + a];
#pragma unroll
            for (int q = 0; q < 5; q++) vj[q] = sv[tk*160 + tj*5 + q];
#pragma unroll
            for (int a = 0; a < 4; a++)
#pragma unroll
                for (int q = 0; q < 5; q++) acc[a][q] += wi[a]*vj[q];
        }
    }
    float* pp = part + (size_t)blockIdx.x * 5120;
#pragma unroll
    for (int a = 0; a < 4; a++)
#pragma unroll
        for (int q = 0; q < 5; q++)
            pp[(ti*4+a)*160 + tj*5 + q] = acc[a][q];
}

__global__ void __launch_bounds__(256) reduce_partials(
    const float* __restrict__ part, float* __restrict__ gu)
{
    int cell = blockIdx.x*256 + threadIdx.x;
    float s = 0.f;
#pragma unroll 8
    for (int p = 0; p < 1024; p++) s += part[(size_t)p*5120 + cell];
    gu[cell] = s;
}

__global__ void __launch_bounds__(256) cell_update(
    const float* __restrict__ gu, const float* __restrict__ cv,
    float* __restrict__ vnew)
{
    __shared__ float sG[Mm*Mm];
    __shared__ float sV[Mm*Ss];
    const int tid = threadIdx.x;
    for (int i = tid; i < Mm*Mm; i += 256) {
        int m = i >> 5, j = i & 31;
        sG[i] = gu[m*160 + j];
    }
    for (int i = tid; i < Mm*Ss; i += 256) sV[i] = cv[i];
    __syncthreads();
    for (int k = 0; k < 16; k++) {
        int cell = k*256 + tid;
        int m = cell >> 7, s0 = cell & 127;
        float d = gu[m*160 + 32 + s0];
#pragma unroll
        for (int mp = 0; mp < Mm; mp++) d -= sG[m*32 + mp] * sV[mp*128 + s0];
        vnew[cell] = sV[cell] + ALPHA * d;
    }
}

// ---------------------------------------------------------------------------
// Memcell pass 3: t_read = W @ cell_v_new -> NCHW [B,S,H2,W2].
// ---------------------------------------------------------------------------
__global__ void __launch_bounds__(256) memcell_read(
    const float* __restrict__ wmat, const float* __restrict__ vnew,
    float* __restrict__ d0m)
{
    __shared__ float sV[Mm*Ss];
    __shared__ float sW[64*33];
    const int tid = threadIdx.x;
    for (int i = tid; i < Mm*Ss; i += 256) sV[i] = vnew[i];
    const int tbase = blockIdx.x * 64;
    for (int i = tid; i < 64*32; i += 256) {
        int tk = i >> 5, m = i & 31;
        sW[tk*33 + m] = wmat[(size_t)(tbase + tk)*32 + m];
    }
    __syncthreads();

    const int lane = tid & 31, wid = tid >> 5;
    const int cb = wid * 16;
    float a0[16], a1[16];
#pragma unroll
    for (int c = 0; c < 16; c++) { a0[c] = 0.f; a1[c] = 0.f; }

    const float* w0 = sW + lane*33;
    const float* w1 = sW + (lane + 32)*33;
#pragma unroll 4
    for (int m = 0; m < Mm; m++) {
        float x0 = w0[m], x1 = w1[m];
        const float4* vv = (const float4*)(sV + m*128 + cb);
#pragma unroll
        for (int q = 0; q < 4; q++) {
            float4 v = vv[q];
            a0[q*4+0] += x0*v.x; a0[q*4+1] += x0*v.y;
            a0[q*4+2] += x0*v.z; a0[q*4+3] += x0*v.w;
            a1[q*4+0] += x1*v.x; a1[q*4+1] += x1*v.y;
            a1[q*4+2] += x1*v.z; a1[q*4+3] += x1*v.w;
        }
    }
    const int b = tbase >> 14;
    const int rem = tbase & 16383;
    const int h = rem >> 7;
    const int wcp = rem & 127;
    size_t obase = ((size_t)b*Ss)*((size_t)H2*W2) + (size_t)h*W2 + wcp;
#pragma unroll
    for (int c = 0; c < 16; c++) {
        size_t o = obase + (size_t)(cb + c)*(H2*W2);
        d0m[o + lane]      = a0[c];
        d0m[o + 32 + lane] = a1[c];
    }
}

// ---------------------------------------------------------------------------
// ConvTranspose2d(128->3, k4, s2, p1) + bias + SiLU.  32x32 output tiles.
// ---------------------------------------------------------------------------
__global__ void __launch_bounds__(256) deconv_kernel(
    const float* __restrict__ in, const float* __restrict__ dw,
    const float* __restrict__ db, float* __restrict__ out)
{
    __shared__ float sWd[4*128*12];              // [parity][cin][o][k] 24.6 KB
    __shared__ float sIn[16*324];                // 16 cins x 18x18 (20.7 KB)
    const int tid = threadIdx.x;
    for (int i = tid; i < 4*128*12; i += 256) {
        int p = i / 1536, rem = i - p*1536;
        int cin = rem / 12, rr = rem - cin*12;
        int o = rr >> 2, k = rr & 3;
        int py = p >> 1, px = p & 1;
        int ky = py + 2*(k >> 1), kx = px + 2*(k & 1);
        sWd[i] = dw[cin*48 + o*16 + ky*4 + kx];
    }

    const int b  = blockIdx.z;
    const int Y0 = blockIdx.y*32, X0 = blockIdx.x*32;
    const int ty = tid >> 4, tx = tid & 15;
    const int y0 = Y0 + ty, x0 = X0 + tx;
    const int hb = (Y0 >> 1) - 1, wb = (X0 >> 1) - 1;

    const int py = (y0 + 1) & 1, px = (x0 + 1) & 1;
    const int hs0 = ((y0 + 1 - py) >> 1) - hb;   // 1..9
    const int ws0 = ((x0 + 1 - px) >> 1) - wb;

    const float* wp = sWd + (py*2 + px)*1536;
    float acc[2][2][3];
#pragma unroll
    for (int a = 0; a < 2; a++)
#pragma unroll
        for (int e = 0; e < 2; e++)
#pragma unroll
            for (int o = 0; o < 3; o++) acc[a][e][o] = 0.f;

    const float* inb = in + (size_t)b * Ss * H2 * W2;

    for (int c0 = 0; c0 < Ss; c0 += 16) {
        __syncthreads();
        for (int i = tid; i < 16*324; i += 256) {
            int c = i / 324, rr = i - c*324;
            int r = rr / 18, cc = rr - r*18;
            int h = hb + r, w = wb + cc;
            float v = 0.f;
            if ((unsigned)h < (unsigned)H2 && (unsigned)w < (unsigned)W2)
                v = inb[((size_t)(c0 + c)*H2 + h)*W2 + w];
            sIn[i] = v;
        }
        __syncthreads();
#pragma unroll
        for (int c = 0; c < 16; c++) {
            const float* sc = sIn + c*324;
            const float4* w4 = (const float4*)(wp + (c0 + c)*12);
            float4 Wa = w4[0], Wb = w4[1], Wc = w4[2];
#pragma unroll
            for (int a = 0; a < 2; a++)
#pragma unroll
                for (int e = 0; e < 2; e++) {
                    int hh = hs0 + 8*a, ww = ws0 + 8*e;
                    float i00 = sc[hh*18 + ww];
                    float i01 = sc[hh*18 + ww - 1];
                    float i10 = sc[(hh-1)*18 + ww];
                    float i11 = sc[(hh-1)*18 + ww - 1];
                    acc[a][e][0] += i00*Wa.x + i01*Wa.y + i10*Wa.z + i11*Wa.w;
                    acc[a][e][1] += i00*Wb.x + i01*Wb.y + i10*Wb.z + i11*Wb.w;
                    acc[a][e][2] += i00*Wc.x + i01*Wc.y + i10*Wc.z + i11*Wc.w;
                }
        }
    }
#pragma unroll
    for (int a = 0; a < 2; a++)
#pragma unroll
        for (int e = 0; e < 2; e++)
#pragma unroll
            for (int o = 0; o < 3; o++) {
                float v = acc[a][e][o] + db[o];
                v = v / (1.f + __expf(-v));
                out[(((size_t)b*3 + o)*HIN + y0 + 16*a)*WIN + x0 + 16*e] = v;
            }
}

// ---------------------------------------------------------------------------
// Launch sequence
// ---------------------------------------------------------------------------
extern "C" void kernel_launch(void* const* d_in, const int* in_sizes, int n_in,
                              void* d_out, int out_size)
{
    const float* x      = (const float*)d_in[0];
    const float* e0n_w1 = (const float*)d_in[1];
    const float* e0n_b1 = (const float*)d_in[2];
    const float* e0n_w2 = (const float*)d_in[3];
    const float* e0n_b2 = (const float*)d_in[4];
    const float* e0s_w1 = (const float*)d_in[5];
    const float* e0s_b1 = (const float*)d_in[6];
    const float* e0s_w2 = (const float*)d_in[7];
    const float* e0s_b2 = (const float*)d_in[8];
    const float* d0_dw  = (const float*)d_in[9];
    const float* d0_db  = (const float*)d_in[10];
    const float* d0_cw  = (const float*)d_in[11];
    const float* d0_cb  = (const float*)d_in[12];
    const float* cell_k = (const float*)d_in[13];
    const float* cell_v = (const float*)d_in[14];
    float* outp = (float*)d_out;

    void *p_a1n, *p_a1s, *p_z, *p_ts, *p_w, *p_part, *p_gu, *p_vnew, *p_d0m, *p_dec;
    cudaGetSymbolAddress(&p_a1n, g_a1n);
    cudaGetSymbolAddress(&p_a1s, g_a1s);
    cudaGetSymbolAddress(&p_z,   g_z);
    cudaGetSymbolAddress(&p_ts,  g_ts);
    cudaGetSymbolAddress(&p_w,   g_w);
    cudaGetSymbolAddress(&p_part,g_part);
    cudaGetSymbolAddress(&p_gu,  g_gu);
    cudaGetSymbolAddress(&p_vnew,g_vnew);
    cudaGetSymbolAddress(&p_d0m, g_d0m);
    cudaGetSymbolAddress(&p_dec, g_dec);

    const int dsm_s1 = 2 * 34 * 36 * 4;   //  9792 B
    const int dsm_s2 = 2 * 65 * 72 * 4;   // 37440 B

    cudaFuncSetAttribute((const void*)convfast<3,16,2>,
                         cudaFuncAttributeMaxDynamicSharedMemorySize, dsm_s1);
    cudaFuncSetAttribute((const void*)convfast<3,128,2>,
                         cudaFuncAttributeMaxDynamicSharedMemorySize, dsm_s1);
    cudaFuncSetAttribute((const void*)convfast2<16,16>,
                         cudaFuncAttributeMaxDynamicSharedMemorySize, dsm_s2);
    cudaFuncSetAttribute((const void*)convfast2<128,128>,
                         cudaFuncAttributeMaxDynamicSharedMemorySize, dsm_s2);

    // Borders of the padded intermediates (disjoint from conv1 writes)
    zero_borders<<<Bb*Nn, 256>>>((float*)p_a1n);
    zero_borders<<<Bb*Ss, 256>>>((float*)p_a1s);

    // Encoders
    convfast<3,16,2><<<dim3(8,8,Bb),256,dsm_s1>>>(
        x, e0n_w1, e0n_b1, (float*)p_a1n, HIN, WIN);
    convfast<3,128,2><<<dim3(8,8,Bb*8),256,dsm_s1>>>(
        x, e0s_w1, e0s_b1, (float*)p_a1s, HIN, WIN);
    convfast2<16,16><<<dim3(4,4,Bb),256,dsm_s2>>>(
        (const float*)p_a1n, e0n_w2, e0n_b2, (float*)p_z);
    convfast2<128,128><<<dim3(4,4,Bb*8),256,dsm_s2>>>(
        (const float*)p_a1s, e0s_w2, e0s_b2, (float*)p_ts);

    // Memcell
    memcell_softmax<<<Tt/256,256>>>((const float*)p_z, cell_k, (float*)p_w);
    memcell_outer<<<1024,256>>>((const float*)p_w, (const float*)p_ts, (float*)p_part);
    reduce_partials<<<20,256>>>((const float*)p_part, (float*)p_gu);
    cell_update<<<1,256>>>((const float*)p_gu, cell_v, (float*)p_vnew);
    memcell_read<<<Tt/64,256>>>((const float*)p_w, (const float*)p_vnew, (float*)p_d0m);

    // Decoder
    deconv_kernel<<<dim3(8,8,Bb),256>>>(
        (const float*)p_d0m, d0_dw, d0_db, (float*)p_dec);
    conv3x3<3,3,3><<<dim3(16,16,Bb),256>>>(
        (const float*)p_dec, d0_cw, d0_cb, outp, HIN, WIN);
}

// round 13
// speedup vs baseline: 2.8516x; 1.2156x over previous
#include <cuda_runtime.h>
#include <cuda_bf16.h>
#include <cstdint>

// ---------------------------------------------------------------------------
// Problem constants
// ---------------------------------------------------------------------------
#define Bb   8
#define HIN  256
#define WIN  256
#define H2   128
#define W2   128
#define Nn   16
#define Mm   32
#define Ss   128
#define Tt   (Bb*H2*W2)          // 131072 tokens
#define ALPHA 1e-6f

// Padded parity-split activation layout (fp32 path, conv1_n -> conv2_n):
#define PROW 264
#define PCH  (258*PROW)

// NHWC-padded bf16 layout for conv1_s output (rows/cols padded by 1):
//   [b][row 0..257][col 0..257][cin 0..127]
#define NR   258
#define NCH  ((size_t)NR*NR*128)

typedef unsigned long long u64;
typedef unsigned int u32t;

// ---------------------------------------------------------------------------
// Scratch buffers (static device globals; no cudaMalloc allowed)
// ---------------------------------------------------------------------------
__device__ float g_a1n [(size_t)Bb*Nn*PCH];        // padded silu(conv1_n) fp32
__device__ __nv_bfloat16 g_hi [(size_t)Bb*NCH];    // silu(conv1_s) bf16 hi (~136MB)
__device__ __nv_bfloat16 g_lo [(size_t)Bb*NCH];    // bf16 lo
__device__ u32t  g_wph[8*9*128*8];                 // packed conv2_s weights hi
__device__ u32t  g_wpl[8*9*128*8];                 // packed conv2_s weights lo
__device__ float g_z   [(size_t)Tt*Nn];
__device__ float g_ts  [(size_t)Tt*Ss];
__device__ float g_w   [(size_t)Tt*Mm];
__device__ float g_part[(size_t)1024*32*160];
__device__ float g_gu  [32*160];
__device__ float g_vnew[Mm*Ss];
__device__ float g_d0m [(size_t)Bb*Ss*H2*W2];
__device__ float g_dec [(size_t)Bb*3*HIN*WIN];

// ---------------------------------------------------------------------------
// cp.async + f32x2 helpers
// ---------------------------------------------------------------------------
__device__ __forceinline__ void cp_async4(unsigned dst, const float* src, int sz) {
    asm volatile("cp.async.ca.shared.global [%0], [%1], 4, %2;\n"
                 :: "r"(dst), "l"(src), "r"(sz));
}
__device__ __forceinline__ void cp_async4u(unsigned dst, const float* src) {
    asm volatile("cp.async.ca.shared.global [%0], [%1], 4;\n"
                 :: "r"(dst), "l"(src));
}
__device__ __forceinline__ void cp_async16(unsigned dst, const void* src) {
    asm volatile("cp.async.cg.shared.global [%0], [%1], 16;\n"
                 :: "r"(dst), "l"(src));
}
__device__ __forceinline__ void cp_commit() {
    asm volatile("cp.async.commit_group;\n" ::: "memory");
}
__device__ __forceinline__ void cp_wait0() {
    asm volatile("cp.async.wait_group 0;\n" ::: "memory");
}

#define FMA2(d, a, b) \
    asm("fma.rn.f32x2 %0, %1, %2, %0;" : "+l"(d) : "l"(a), "l"(b))
#define PACK2(dst, v) \
    asm("mov.b64 %0, {%1, %1};" : "=l"(dst) : "f"(v))
#define UNPACK2(lo, hi, src) \
    asm("mov.b64 {%0, %1}, %2;" : "=f"(lo), "=f"(hi) : "l"(src))

__device__ __forceinline__ void fma2_row(u64* acc, float v,
                                         const ulonglong2& q0, const ulonglong2& q1,
                                         const ulonglong2& q2, const ulonglong2& q3) {
    u64 vv; PACK2(vv, v);
    FMA2(acc[0], vv, q0.x); FMA2(acc[1], vv, q0.y);
    FMA2(acc[2], vv, q1.x); FMA2(acc[3], vv, q1.y);
    FMA2(acc[4], vv, q2.x); FMA2(acc[5], vv, q2.y);
    FMA2(acc[6], vv, q3.x); FMA2(acc[7], vv, q3.y);
}

// mma.sync m16n8k16 bf16 (fp32 accumulate)
#define MMA_BF16(c, a0,a1,a2,a3, b0,b1) \
    asm volatile("mma.sync.aligned.m16n8k16.row.col.f32.bf16.bf16.f32 " \
        "{%0,%1,%2,%3}, {%4,%5,%6,%7}, {%8,%9}, {%0,%1,%2,%3};" \
        : "+f"(c[0]), "+f"(c[1]), "+f"(c[2]), "+f"(c[3]) \
        : "r"(a0), "r"(a1), "r"(a2), "r"(a3), "r"(b0), "r"(b1))

__device__ __forceinline__ u32t pk_bf16x2(float a, float b) {
    __nv_bfloat162 t = __floats2bfloat162_rn(a, b);   // low = a, high = b
    return *(u32t*)&t;
}

// ---------------------------------------------------------------------------
// Border zero kernels
// ---------------------------------------------------------------------------
__global__ void zero_borders(float* buf) {
    float* p = buf + (size_t)blockIdx.x * PCH;
    int tid = threadIdx.x;
    for (int i = tid; i < PROW; i += 256) p[i] = 0.f;
    p[(tid + 1) * PROW] = 0.f;
}

// zero rows 0,257 and cols 0,257 of one NHWC-padded batch image (both bufs)
__global__ void zb_nhwc(__nv_bfloat16* gh, __nv_bfloat16* gl) {
    const int b = blockIdx.x;
    u32t* h = (u32t*)(gh + (size_t)b*NCH);
    u32t* l = (u32t*)(gl + (size_t)b*NCH);
    const int tid = threadIdx.x;
    // rows 0 and 257: 258*128 bf16 = 16512 u32 each
    for (int i = tid; i < NR*64; i += 256) {
        h[i] = 0u; l[i] = 0u;
        h[(size_t)257*NR*64 + i] = 0u; l[(size_t)257*NR*64 + i] = 0u;
    }
    // cols 0 and 257, rows 1..256: 64 u32 per position
    for (int i = tid; i < 256*64; i += 256) {
        int r = 1 + i/64, c2 = i%64;
        size_t o0 = ((size_t)r*NR + 0)*64 + c2;
        size_t o1 = ((size_t)r*NR + 257)*64 + c2;
        h[o0] = 0u; l[o0] = 0u; h[o1] = 0u; l[o1] = 0u;
    }
}

// ---------------------------------------------------------------------------
// conv2_s weight pre-pack: g_wp[((cc*9+tap)*128+co)*8 + q] =
//   {bf16 W[cin][co], bf16 W[cin+1][co]},  cin = cc*16 + 2q.
// Source layout: wgt[co][cin][3][3] (co*1152 + cin*9 + tap).
// ---------------------------------------------------------------------------
__global__ void wprep(const float* __restrict__ wgt,
                      u32t* __restrict__ wph, u32t* __restrict__ wpl) {
    int i = blockIdx.x*256 + threadIdx.x;
    if (i >= 8*9*128*8) return;
    int q = i & 7;
    int r = i >> 3;
    int co = r & 127; r >>= 7;
    int tap = r % 9;
    int cc  = r / 9;
    int cin = cc*16 + 2*q;
    float w0 = wgt[co*1152 + cin*9 + tap];
    float w1 = wgt[co*1152 + (cin+1)*9 + tap];
    __nv_bfloat16 h0 = __float2bfloat16_rn(w0);
    __nv_bfloat16 h1 = __float2bfloat16_rn(w1);
    float l0 = w0 - __bfloat162float(h0);
    float l1 = w1 - __bfloat162float(h1);
    wph[i] = pk_bf16x2(__bfloat162float(h0), __bfloat162float(h1));
    wpl[i] = pk_bf16x2(l0, l1);
}

// ---------------------------------------------------------------------------
// Stride-1 fused conv3x3 + bias + SiLU (CIN=3).
// OUTMODE: 2 = padded parity fp32; 3 = NHWC-padded bf16 hi/lo split.
// ---------------------------------------------------------------------------
template<int CIN, int OUTC, int OUTMODE>
__global__ void __launch_bounds__(256, 2) convfast(
    const float* __restrict__ in, const float* __restrict__ wgt,
    const float* __restrict__ bias, float* __restrict__ out,
    __nv_bfloat16* __restrict__ outH, __nv_bfloat16* __restrict__ outL,
    int Hin, int Win)
{
    constexpr int COG  = 16;
    constexpr int ITX  = 34;
    constexpr int SRS  = 36;
    constexpr int ELEMS = ITX * ITX;
    constexpr int NIT  = (ELEMS + 255) / 256;
    constexpr int PLANE = ITX * SRS;

    extern __shared__ float sIn[];
    __shared__ float sW[2][COG*9 + 8];
    __shared__ int2 tTab[NIT*256];

    const int tid = threadIdx.x;
    const int tx = tid & 7, ty = tid >> 3;
    const int groups = OUTC / COG;
    const int b = blockIdx.z / groups;
    const int cbase = (blockIdx.z % groups) * COG;
    const int X0 = blockIdx.x * 32, Y0 = blockIdx.y * 32;
    const int iy0 = Y0 - 1, ix0 = X0 - 1;
    const size_t HW = (size_t)Hin * Win;
    const float* inb = in + (size_t)b * CIN * HW;

    const int wc = tid / 9, wtap = tid - wc*9;

#pragma unroll
    for (int k = 0; k < NIT; k++) {
        int f = k*256 + tid;
        int sof = -1, gof = -1;
        if (f < ELEMS) {
            int r = f / ITX, c = f - r*ITX;
            int ih = iy0 + r, iw = ix0 + c;
            sof = r*SRS + c;
            gof = ((unsigned)ih < (unsigned)Hin && (unsigned)iw < (unsigned)Win)
                  ? (ih*Win + iw) : -1;
        }
        tTab[k*256 + tid] = make_int2(gof, sof);
    }

    const unsigned sb0 = (unsigned)__cvta_generic_to_shared(sIn);
    auto stage = [&](int buf, int cin) {
        const float* ic = inb + (size_t)cin * HW;
        const unsigned sb = sb0 + (unsigned)buf * (PLANE*4);
#pragma unroll
        for (int k = 0; k < NIT; k++) {
            int2 t = tTab[k*256 + tid];
            if (t.y >= 0)
                cp_async4(sb + (unsigned)t.y*4, ic + (t.x < 0 ? 0 : t.x),
                          t.x < 0 ? 0 : 4);
        }
        if (tid < COG*9) {
            unsigned dst = (unsigned)__cvta_generic_to_shared(
                               &sW[buf][wtap*COG + wc]);
            cp_async4u(dst, wgt + ((size_t)(cbase+wc)*CIN + cin)*9 + wtap);
        }
    };

    stage(0, 0);
    cp_commit();
    cp_wait0();
    __syncthreads();

    u64 acc2[4][8];
#pragma unroll
    for (int j = 0; j < 4; j++)
#pragma unroll
        for (int p = 0; p < 8; p++) acc2[j][p] = 0ull;

    for (int cin = 0; cin < CIN; cin++) {
        const int cur = cin & 1;
        if (cin + 1 < CIN) { stage(cur^1, cin+1); cp_commit(); }

        const float* sc  = sIn + cur*PLANE;
        const float* swp = sW[cur];
#pragma unroll
        for (int dy = 0; dy < 3; dy++) {
            const float* rp = sc + (ty + dy)*SRS + tx*4;
            float4 A = *(const float4*)rp;
            float2 Bv = *(const float2*)(rp + 4);
            float iv6[6] = {A.x, A.y, A.z, A.w, Bv.x, Bv.y};
#pragma unroll
            for (int dx = 0; dx < 3; dx++) {
                const ulonglong2* wq = (const ulonglong2*)(swp + (dy*3+dx)*COG);
                ulonglong2 q0 = wq[0], q1 = wq[1], q2 = wq[2], q3 = wq[3];
#pragma unroll
                for (int j = 0; j < 4; j++)
                    fma2_row(acc2[j], iv6[j+dx], q0, q1, q2, q3);
            }
        }
        if (cin + 1 < CIN) cp_wait0();
        __syncthreads();
    }

    float bv[COG];
#pragma unroll
    for (int c = 0; c < COG; c++) bv[c] = __ldg(bias + cbase + c);

    const int oy = Y0 + ty;
    const int x0 = X0 + tx*4;
    if (OUTMODE == 3) {
#pragma unroll
        for (int j = 0; j < 4; j++) {
            u32t hp[8], lp[8];
#pragma unroll
            for (int p = 0; p < 8; p++) {
                float flo, fhi;
                UNPACK2(flo, fhi, acc2[j][p]);
                float v0 = flo + bv[2*p];     v0 = v0 / (1.f + __expf(-v0));
                float v1 = fhi + bv[2*p+1];   v1 = v1 / (1.f + __expf(-v1));
                __nv_bfloat16 h0 = __float2bfloat16_rn(v0);
                __nv_bfloat16 h1 = __float2bfloat16_rn(v1);
                hp[p] = pk_bf16x2(v0, v1);    // rn-rounded pair
                lp[p] = pk_bf16x2(v0 - __bfloat162float(h0),
                                  v1 - __bfloat162float(h1));
            }
            size_t base = (((size_t)b*NR + (oy+1))*NR + (x0+j+1))*128 + cbase;
            uint4* dh = (uint4*)(outH + base);
            uint4* dl = (uint4*)(outL + base);
            dh[0] = make_uint4(hp[0],hp[1],hp[2],hp[3]);
            dh[1] = make_uint4(hp[4],hp[5],hp[6],hp[7]);
            dl[0] = make_uint4(lp[0],lp[1],lp[2],lp[3]);
            dl[1] = make_uint4(lp[4],lp[5],lp[6],lp[7]);
        }
    } else {
#pragma unroll
        for (int c = 0; c < COG; c++) {
            float vv[4];
#pragma unroll
            for (int j = 0; j < 4; j++) {
                float flo, fhi;
                UNPACK2(flo, fhi, acc2[j][c >> 1]);
                float v = ((c & 1) ? fhi : flo) + bv[c];
                vv[j] = v / (1.f + __expf(-v));
            }
            size_t rowbase = ((size_t)(b*OUTC + cbase + c)*258 + (oy+1))*PROW;
            *(float2*)(out + rowbase + 132 + (x0>>1)) = make_float2(vv[0], vv[2]);
            out[rowbase + (x0>>1) + 1] = vv[1];
            out[rowbase + (x0>>1) + 2] = vv[3];
        }
    }
}

// ---------------------------------------------------------------------------
// Stride-2 conv (fp32 FFMA2 path) — used only for conv2_n (16->16).
// ---------------------------------------------------------------------------
template<int CIN, int OUTC>
__global__ void __launch_bounds__(256, 2) convfast2(
    const float* __restrict__ in, const float* __restrict__ wgt,
    const float* __restrict__ bias, float* __restrict__ out)
{
    constexpr int COG  = 16;
    constexpr int SRS  = 72;
    constexpr int ODD  = 36;
    constexpr int PLANE = 65*SRS;
    constexpr int NOPS = 65*18;

    extern __shared__ float sIn[];
    __shared__ float sW[2][COG*9 + 8];

    const int tid = threadIdx.x;
    const int tx = tid & 7, ty = tid >> 3;
    const int groups = OUTC / COG;
    const int b = blockIdx.z / groups;
    const int cbase = (blockIdx.z % groups) * COG;
    const int X0 = blockIdx.x * 32, Y0 = blockIdx.y * 32;
    const float* inb = in + (size_t)b * CIN * PCH;

    const int wc = tid / 9, wtap = tid - wc*9;

    int gofs[5]; int sofs[5];
#pragma unroll
    for (int k = 0; k < 5; k++) {
        int id = k*256 + tid;
        if (id < NOPS) {
            int row = id / 18;
            int rem = id - row*18;
            int seg = rem / 9;
            int q   = rem - seg*9;
            gofs[k] = (2*Y0 + row)*PROW + seg*132 + X0 + q*4;
            sofs[k] = (row*SRS + seg*ODD + q*4) * 4;
        } else { gofs[k] = 0; sofs[k] = -1; }
    }

    const unsigned sb0 = (unsigned)__cvta_generic_to_shared(sIn);
    auto stage = [&](int buf, int cin) {
        const float* ic = inb + (size_t)cin * PCH;
        const unsigned sb = sb0 + (unsigned)buf * (PLANE*4);
#pragma unroll
        for (int k = 0; k < 5; k++)
            if (sofs[k] >= 0) cp_async16(sb + (unsigned)sofs[k], ic + gofs[k]);
        if (tid < COG*9) {
            unsigned dst = (unsigned)__cvta_generic_to_shared(
                               &sW[buf][wtap*COG + wc]);
            cp_async4u(dst, wgt + ((size_t)(cbase+wc)*CIN + cin)*9 + wtap);
        }
    };

    stage(0, 0);
    cp_commit();
    cp_wait0();
    __syncthreads();

    u64 acc2[4][8];
#pragma unroll
    for (int j = 0; j < 4; j++)
#pragma unroll
        for (int p = 0; p < 8; p++) acc2[j][p] = 0ull;

    for (int cin = 0; cin < CIN; cin++) {
        const int cur = cin & 1;
        if (cin + 1 < CIN) { stage(cur^1, cin+1); cp_commit(); }

        const float* sc  = sIn + cur*PLANE;
        const float* swp = sW[cur];
#pragma unroll
        for (int dy = 0; dy < 3; dy++) {
            const float* rp = sc + (ty*2 + dy)*SRS;
            float4 E = *(const float4*)(rp + tx*4);
            float  e4 = rp[tx*4 + 4];
            float4 O = *(const float4*)(rp + ODD + tx*4);
            float V[3][4];
            V[0][0]=E.x; V[0][1]=E.y; V[0][2]=E.z; V[0][3]=E.w;
            V[1][0]=O.x; V[1][1]=O.y; V[1][2]=O.z; V[1][3]=O.w;
            V[2][0]=E.y; V[2][1]=E.z; V[2][2]=E.w; V[2][3]=e4;
#pragma unroll
            for (int dx = 0; dx < 3; dx++) {
                const ulonglong2* wq = (const ulonglong2*)(swp + (dy*3+dx)*COG);
                ulonglong2 q0 = wq[0], q1 = wq[1], q2 = wq[2], q3 = wq[3];
#pragma unroll
                for (int j = 0; j < 4; j++)
                    fma2_row(acc2[j], V[dx][j], q0, q1, q2, q3);
            }
        }
        if (cin + 1 < CIN) cp_wait0();
        __syncthreads();
    }

    float bv[COG];
#pragma unroll
    for (int c = 0; c < COG; c++) bv[c] = __ldg(bias + cbase + c);

    const int oy = Y0 + ty;
#pragma unroll
    for (int j = 0; j < 4; j++) {
        float vv[COG];
#pragma unroll
        for (int p = 0; p < 8; p++) {
            float flo, fhi;
            UNPACK2(flo, fhi, acc2[j][p]);
            float v0 = flo + bv[2*p],     v1 = fhi + bv[2*p+1];
            vv[2*p]   = v0 / (1.f + __expf(-v0));
            vv[2*p+1] = v1 / (1.f + __expf(-v1));
        }
        size_t t = ((size_t)b*H2 + oy)*W2 + X0 + tx*4 + j;
        float4* op = (float4*)(out + t*OUTC + cbase);
        op[0] = make_float4(vv[0],  vv[1],  vv[2],  vv[3]);
        op[1] = make_float4(vv[4],  vv[5],  vv[6],  vv[7]);
        op[2] = make_float4(vv[8],  vv[9],  vv[10], vv[11]);
        op[3] = make_float4(vv[12], vv[13], vv[14], vv[15]);
    }
}

// ---------------------------------------------------------------------------
// conv2_s as token-GEMM on tensor cores (mma.sync m16n8k16 bf16, 3-pass).
// Block: 64 tokens (fixed b,y; x'=x0..x0+63) x 128 out-channels, 8 warps
// (warp grid 4M x 2N; warp = 16 tokens x 64 co). K = 9 taps x 128 cin,
// looped as 8 chunks of 16 cins x 9 taps.
// A: NHWC-padded bf16 hi/lo; token x', tap(dy,dx) -> row 2y+dy, col 2x'+dx.
// ---------------------------------------------------------------------------
#define APS 12                      // sA p-stride in u32 (48B, 16B aligned)
#define BPS 12                      // sB (tap,co)-stride in u32
#define SA_U32 (3*129*APS)          // 4644 u32
#define SB_U32 (9*128*BPS)          // 13824 u32
#define C2_SMEM ((2*SA_U32 + 2*SB_U32)*4)   // 147744 B

__global__ void __launch_bounds__(256, 1) conv2s_mma(
    const __nv_bfloat16* __restrict__ gh, const __nv_bfloat16* __restrict__ gl,
    const u32t* __restrict__ wph, const u32t* __restrict__ wpl,
    const float* __restrict__ bias, float* __restrict__ out)
{
    extern __shared__ u32t sm32[];
    u32t* sAh = sm32;
    u32t* sAl = sAh + SA_U32;
    u32t* sBh = sAl + SA_U32;
    u32t* sBl = sBh + SB_U32;

    const int tid = threadIdx.x, lane = tid & 31, w = tid >> 5;
    const int wm = w & 3, wn = w >> 2;
    const int x0 = blockIdx.x * 64;
    const int y  = blockIdx.y;
    const int b  = blockIdx.z;

    const unsigned aH = (unsigned)__cvta_generic_to_shared(sAh);
    const unsigned aL = (unsigned)__cvta_generic_to_shared(sAl);
    const unsigned bH = (unsigned)__cvta_generic_to_shared(sBh);
    const unsigned bL = (unsigned)__cvta_generic_to_shared(sBl);

    float acc[8][4];
#pragma unroll
    for (int nt = 0; nt < 8; nt++)
#pragma unroll
        for (int r = 0; r < 4; r++) acc[nt][r] = 0.f;

    const int q = lane & 3;
    const int g = lane >> 2;
    const int mlow = 16*wm + g;

    for (int cc = 0; cc < 8; cc++) {
        __syncthreads();   // previous compute done before smem overwrite
        // ---- stage A: 387 positions x {half, buf} = 1548 cp.async.16
        for (int i = tid; i < 1548; i += 256) {
            int pos = i >> 2; int half = (i >> 1) & 1; int buf = i & 1;
            int dy = pos / 129, pl = pos - dy*129;
            size_t gofs = (((size_t)b*NR + (2*y + dy))*NR + (2*x0 + pl))*128
                          + cc*16 + half*8;
            const __nv_bfloat16* src = (buf ? gl : gh) + gofs;
            unsigned dst = (buf ? aL : aH) + (unsigned)(pos*APS*4 + half*16);
            cp_async16(dst, src);
        }
        // ---- stage B: (tap,co) 1152 x {half, buf} = 4608 cp.async.16
        for (int i = tid; i < 4608; i += 256) {
            int tc = i >> 2; int half = (i >> 1) & 1; int buf = i & 1;
            const u32t* src = (buf ? wpl : wph) + (cc*1152 + tc)*8 + half*4;
            unsigned dst = (buf ? bL : bH) + (unsigned)(tc*BPS*4 + half*16);
            cp_async16(dst, src);
        }
        cp_commit();
        cp_wait0();
        __syncthreads();

        // ---- compute: 9 taps x 8 n-tiles x 3 passes
#pragma unroll
        for (int dy = 0; dy < 3; dy++)
#pragma unroll
        for (int dx = 0; dx < 3; dx++) {
            const int tap = dy*3 + dx;
            const int baseA = (dy*129 + 2*mlow + dx) * APS;
            const int baseA8 = baseA + 16*APS;            // token row +8
            u32t a0h = sAh[baseA + q],      a2h = sAh[baseA + q + 4];
            u32t a1h = sAh[baseA8 + q],     a3h = sAh[baseA8 + q + 4];
            u32t a0l = sAl[baseA + q],      a2l = sAl[baseA + q + 4];
            u32t a1l = sAl[baseA8 + q],     a3l = sAl[baseA8 + q + 4];
#pragma unroll
            for (int nt = 0; nt < 8; nt++) {
                int co = 64*wn + 8*nt + g;
                int bb = (tap*128 + co) * BPS;
                u32t bh0 = sBh[bb + q], bh1 = sBh[bb + q + 4];
                u32t bl0 = sBl[bb + q], bl1 = sBl[bb + q + 4];
                MMA_BF16(acc[nt], a0h, a1h, a2h, a3h, bh0, bh1);
                MMA_BF16(acc[nt], a0h, a1h, a2h, a3h, bl0, bl1);
                MMA_BF16(acc[nt], a0l, a1l, a2l, a3l, bh0, bh1);
            }
        }
    }

    // ---- epilogue: bias + SiLU -> token-major g_ts
    size_t t1 = ((size_t)(b*H2 + y)*W2 + (x0 + mlow)) * 128;
    size_t t2 = t1 + (size_t)8*128;
#pragma unroll
    for (int nt = 0; nt < 8; nt++) {
        int co = 64*wn + 8*nt + 2*q;
        float bv0 = __ldg(bias + co), bv1 = __ldg(bias + co + 1);
        float v0 = acc[nt][0] + bv0; v0 = v0 / (1.f + __expf(-v0));
        float v1 = acc[nt][1] + bv1; v1 = v1 / (1.f + __expf(-v1));
        float v2 = acc[nt][2] + bv0; v2 = v2 / (1.f + __expf(-v2));
        float v3 = acc[nt][3] + bv1; v3 = v3 / (1.f + __expf(-v3));
        *(float2*)(out + t1 + co) = make_float2(v0, v1);
        *(float2*)(out + t2 + co) = make_float2(v2, v3);
    }
}

// ---------------------------------------------------------------------------
// Legacy conv (final tiny 3->3 decoder conv)
// ---------------------------------------------------------------------------
template<int CIN, int OUTC, int COG>
__global__ void __launch_bounds__(256) conv3x3(
    const float* __restrict__ in, const float* __restrict__ wgt,
    const float* __restrict__ bias, float* __restrict__ out,
    int Hin, int Win)
{
    constexpr int ITD = 18;
    __shared__ float sW[COG*CIN*9];
    __shared__ float sIn[ITD*ITD];

    const int tid = threadIdx.x;
    const int groups = OUTC / COG;
    const int b  = blockIdx.z / groups;
    const int cbase = (blockIdx.z % groups) * COG;

    for (int i = tid; i < COG*CIN*9; i += 256)
        sW[i] = wgt[(size_t)cbase*CIN*9 + i];

    const int ty = tid >> 4, tx = tid & 15;
    const int oy = blockIdx.y*16 + ty;
    const int ox = blockIdx.x*16 + tx;

    float acc[COG];
#pragma unroll
    for (int c = 0; c < COG; c++) acc[c] = 0.f;

    const float* inb = in + (size_t)b * CIN * Hin * Win;
    const int iy0 = blockIdx.y*16 - 1;
    const int ix0 = blockIdx.x*16 - 1;
    const int base = ty*ITD + tx;

    for (int cin = 0; cin < CIN; cin++) {
        __syncthreads();
        const float* ic = inb + (size_t)cin * Hin * Win;
        for (int i = tid; i < ITD*ITD; i += 256) {
            int r = i / ITD, cc = i - r*ITD;
            int ih = iy0 + r, iw = ix0 + cc;
            float v = 0.f;
            if ((unsigned)ih < (unsigned)Hin && (unsigned)iw < (unsigned)Win)
                v = ic[ih*Win + iw];
            sIn[i] = v;
        }
        __syncthreads();
        const float* wp = sW + cin*9;
#pragma unroll
        for (int dy = 0; dy < 3; dy++)
#pragma unroll
            for (int dx = 0; dx < 3; dx++) {
                float iv = sIn[base + dy*ITD + dx];
#pragma unroll
                for (int c = 0; c < COG; c++)
                    acc[c] += iv * wp[c*CIN*9 + dy*3 + dx];
            }
    }

#pragma unroll
    for (int c = 0; c < COG; c++) {
        float v = acc[c] + bias[cbase + c];
        v = v / (1.f + __expf(-v));
        out[(((size_t)b*OUTC + cbase + c)*Hin + oy)*Win + ox] = v;
    }
}

// ---------------------------------------------------------------------------
// Memcell pass 1: w = softmax(z @ K^T / 4) per token.
// ---------------------------------------------------------------------------
__global__ void __launch_bounds__(256) memcell_softmax(
    const float* __restrict__ z, const float* __restrict__ ck,
    float* __restrict__ wout)
{
    __shared__ float sK[Mm*Nn];
    const int tid = threadIdx.x;
    for (int i = tid; i < Mm*Nn; i += 256) sK[i] = ck[i];
    __syncthreads();

    const int t = blockIdx.x*256 + tid;
    const float4* zp = (const float4*)(z + (size_t)t*Nn);
    float4 z0 = zp[0], z1 = zp[1], z2 = zp[2], z3 = zp[3];

    float s[Mm];
    float mx = -1e30f;
#pragma unroll
    for (int m = 0; m < Mm; m++) {
        const float* k = sK + m*Nn;
        float d = z0.x*k[0] + z0.y*k[1] + z0.z*k[2] + z0.w*k[3]
                + z1.x*k[4] + z1.y*k[5] + z1.z*k[6] + z1.w*k[7]
                + z2.x*k[8] + z2.y*k[9] + z2.z*k[10]+ z2.w*k[11]
                + z3.x*k[12]+ z3.y*k[13]+ z3.z*k[14]+ z3.w*k[15];
        d *= 0.25f;
        s[m] = d;
        mx = fmaxf(mx, d);
    }
    float sum = 0.f;
#pragma unroll
    for (int m = 0; m < Mm; m++) { s[m] = __expf(s[m]-mx); sum += s[m]; }
    float inv = 1.f / sum;
    float4* wo = (float4*)(wout + (size_t)t*Mm);
#pragma unroll
    for (int j = 0; j < Mm/4; j++) {
        float4 v; v.x = s[4*j]*inv; v.y = s[4*j+1]*inv;
        v.z = s[4*j+2]*inv; v.w = s[4*j+3]*inv;
        wo[j] = v;
    }
}

// ---------------------------------------------------------------------------
// Memcell pass 2: block partials of [G | U].
// ---------------------------------------------------------------------------
__global__ void __launch_bounds__(256) memcell_outer(
    const float* __restrict__ wmat, const float* __restrict__ ts,
    float* __restrict__ part)
{
    __shared__ float sv[8*160];
    const int tid = threadIdx.x;
    const int ti = tid >> 5;
    const int tj = tid & 31;
    float acc[4][5];
#pragma unroll
    for (int a = 0; a < 4; a++)
#pragma unroll
        for (int qq = 0; qq < 5; qq++) acc[a][qq] = 0.f;

    const int tokb = blockIdx.x * 128;
    for (int ch = 0; ch < 128; ch += 8) {
        __syncthreads();
#pragma unroll
        for (int l = 0; l < 5; l++) {
            int idx = l*256 + tid;
            int tk = idx / 160, f = idx - tk*160;
            int t = tokb + ch + tk;
            sv[tk*160 + f] = (f < 32) ? wmat[(size_t)t*32 + f]
                                      : ts[(size_t)t*128 + (f-32)];
        }
        __syncthreads();
#pragma unroll
        for (int tk = 0; tk < 8; tk++) {
            float wi[4], vj[5];
#pragma unroll
            for (int a = 0; a < 4; a++) wi[a] = sv[tk*160 + ti*4 + a];
#pragma unroll
            for (int qq = 0; qq < 5; qq++) vj[qq] = sv[tk*160 + tj*5 + qq];
#pragma unroll
            for (int a = 0; a < 4; a++)
#pragma unroll
                for (int qq = 0; qq < 5; qq++) acc[a][qq] += wi[a]*vj[qq];
        }
    }
    float* pp = part + (size_t)blockIdx.x * 5120;
#pragma unroll
    for (int a = 0; a < 4; a++)
#pragma unroll
        for (int qq = 0; qq < 5; qq++)
            pp[(ti*4+a)*160 + tj*5 + qq] = acc[a][qq];
}

__global__ void __launch_bounds__(256) reduce_partials(
    const float* __restrict__ part, float* __restrict__ gu)
{
    int cell = blockIdx.x*256 + threadIdx.x;
    float s = 0.f;
#pragma unroll 8
    for (int p = 0; p < 1024; p++) s += part[(size_t)p*5120 + cell];
    gu[cell] = s;
}

__global__ void __launch_bounds__(256) cell_update(
    const float* __restrict__ gu, const float* __restrict__ cv,
    float* __restrict__ vnew)
{
    __shared__ float sG[Mm*Mm];
    __shared__ float sV[Mm*Ss];
    const int tid = threadIdx.x;
    for (int i = tid; i < Mm*Mm; i += 256) {
        int m = i >> 5, j = i & 31;
        sG[i] = gu[m*160 + j];
    }
    for (int i = tid; i < Mm*Ss; i += 256) sV[i] = cv[i];
    __syncthreads();
    for (int k = 0; k < 16; k++) {
        int cell = k*256 + tid;
        int m = cell >> 7, s0 = cell & 127;
        float d = gu[m*160 + 32 + s0];
#pragma unroll
        for (int mp = 0; mp < Mm; mp++) d -= sG[m*32 + mp] * sV[mp*128 + s0];
        vnew[cell] = sV[cell] + ALPHA * d;
    }
}

// ---------------------------------------------------------------------------
// Memcell pass 3: t_read = W @ cell_v_new -> NCHW [B,S,H2,W2].
// ---------------------------------------------------------------------------
__global__ void __launch_bounds__(256) memcell_read(
    const float* __restrict__ wmat, const float* __restrict__ vnew,
    float* __restrict__ d0m)
{
    __shared__ float sV[Mm*Ss];
    __shared__ float sW[64*33];
    const int tid = threadIdx.x;
    for (int i = tid; i < Mm*Ss; i += 256) sV[i] = vnew[i];
    const int tbase = blockIdx.x * 64;
    for (int i = tid; i < 64*32; i += 256) {
        int tk = i >> 5, m = i & 31;
        sW[tk*33 + m] = wmat[(size_t)(tbase + tk)*32 + m];
    }
    __syncthreads();

    const int lane = tid & 31, wid = tid >> 5;
    const int cb = wid * 16;
    float a0[16], a1[16];
#pragma unroll
    for (int c = 0; c < 16; c++) { a0[c] = 0.f; a1[c] = 0.f; }

    const float* w0 = sW + lane*33;
    const float* w1 = sW + (lane + 32)*33;
#pragma unroll 4
    for (int m = 0; m < Mm; m++) {
        float x0 = w0[m], x1 = w1[m];
        const float4* vv = (const float4*)(sV + m*128 + cb);
#pragma unroll
        for (int qq = 0; qq < 4; qq++) {
            float4 v = vv[qq];
            a0[qq*4+0] += x0*v.x; a0[qq*4+1] += x0*v.y;
            a0[qq*4+2] += x0*v.z; a0[qq*4+3] += x0*v.w;
            a1[qq*4+0] += x1*v.x; a1[qq*4+1] += x1*v.y;
            a1[qq*4+2] += x1*v.z; a1[qq*4+3] += x1*v.w;
        }
    }
    const int b = tbase >> 14;
    const int rem = tbase & 16383;
    const int h = rem >> 7;
    const int wcp = rem & 127;
    size_t obase = ((size_t)b*Ss)*((size_t)H2*W2) + (size_t)h*W2 + wcp;
#pragma unroll
    for (int c = 0; c < 16; c++) {
        size_t o = obase + (size_t)(cb + c)*(H2*W2);
        d0m[o + lane]      = a0[c];
        d0m[o + 32 + lane] = a1[c];
    }
}

// ---------------------------------------------------------------------------
// ConvTranspose2d(128->3, k4, s2, p1) + bias + SiLU.  32x32 output tiles.
// ---------------------------------------------------------------------------
__global__ void __launch_bounds__(256) deconv_kernel(
    const float* __restrict__ in, const float* __restrict__ dw,
    const float* __restrict__ db, float* __restrict__ out)
{
    __shared__ float sWd[4*128*12];
    __shared__ float sIn[16*324];
    const int tid = threadIdx.x;
    for (int i = tid; i < 4*128*12; i += 256) {
        int p = i / 1536, rem = i - p*1536;
        int cin = rem / 12, rr = rem - cin*12;
        int o = rr >> 2, k = rr & 3;
        int py = p >> 1, px = p & 1;
        int ky = py + 2*(k >> 1), kx = px + 2*(k & 1);
        sWd[i] = dw[cin*48 + o*16 + ky*4 + kx];
    }

    const int b  = blockIdx.z;
    const int Y0 = blockIdx.y*32, X0 = blockIdx.x*32;
    const int ty = tid >> 4, tx = tid & 15;
    const int y0 = Y0 + ty, x0 = X0 + tx;
    const int hb = (Y0 >> 1) - 1, wb = (X0 >> 1) - 1;

    const int py = (y0 + 1) & 1, px = (x0 + 1) & 1;
    const int hs0 = ((y0 + 1 - py) >> 1) - hb;
    const int ws0 = ((x0 + 1 - px) >> 1) - wb;

    const float* wp = sWd + (py*2 + px)*1536;
    float acc[2][2][3];
#pragma unroll
    for (int a = 0; a < 2; a++)
#pragma unroll
        for (int e = 0; e < 2; e++)
#pragma unroll
            for (int o = 0; o < 3; o++) acc[a][e][o] = 0.f;

    const float* inb = in + (size_t)b * Ss * H2 * W2;

    for (int c0 = 0; c0 < Ss; c0 += 16) {
        __syncthreads();
        for (int i = tid; i < 16*324; i += 256) {
            int c = i / 324, rr = i - c*324;
            int r = rr / 18, cc = rr - r*18;
            int h = hb + r, w = wb + cc;
            float v = 0.f;
            if ((unsigned)h < (unsigned)H2 && (unsigned)w < (unsigned)W2)
                v = inb[((size_t)(c0 + c)*H2 + h)*W2 + w];
            sIn[i] = v;
        }
        __syncthreads();
#pragma unroll
        for (int c = 0; c < 16; c++) {
            const float* sc = sIn + c*324;
            const float4* w4 = (const float4*)(wp + (c0 + c)*12);
            float4 Wa = w4[0], Wb = w4[1], Wc = w4[2];
#pragma unroll
            for (int a = 0; a < 2; a++)
#pragma unroll
                for (int e = 0; e < 2; e++) {
                    int hh = hs0 + 8*a, ww = ws0 + 8*e;
                    float i00 = sc[hh*18 + ww];
                    float i01 = sc[hh*18 + ww - 1];
                    float i10 = sc[(hh-1)*18 + ww];
                    float i11 = sc[(hh-1)*18 + ww - 1];
                    acc[a][e][0] += i00*Wa.x + i01*Wa.y + i10*Wa.z + i11*Wa.w;
                    acc[a][e][1] += i00*Wb.x + i01*Wb.y + i10*Wb.z + i11*Wb.w;
                    acc[a][e][2] += i00*Wc.x + i01*Wc.y + i10*Wc.z + i11*Wc.w;
                }
        }
    }
#pragma unroll
    for (int a = 0; a < 2; a++)
#pragma unroll
        for (int e = 0; e < 2; e++)
#pragma unroll
            for (int o = 0; o < 3; o++) {
                float v = acc[a][e][o] + db[o];
                v = v / (1.f + __expf(-v));
                out[(((size_t)b*3 + o)*HIN + y0 + 16*a)*WIN + x0 + 16*e] = v;
            }
}

// ---------------------------------------------------------------------------
// Launch sequence
// ---------------------------------------------------------------------------
extern "C" void kernel_launch(void* const* d_in, const int* in_sizes, int n_in,
                              void* d_out, int out_size)
{
    const float* x      = (const float*)d_in[0];
    const float* e0n_w1 = (const float*)d_in[1];
    const float* e0n_b1 = (const float*)d_in[2];
    const float* e0n_w2 = (const float*)d_in[3];
    const float* e0n_b2 = (const float*)d_in[4];
    const float* e0s_w1 = (const float*)d_in[5];
    const float* e0s_b1 = (const float*)d_in[6];
    const float* e0s_w2 = (const float*)d_in[7];
    const float* e0s_b2 = (const float*)d_in[8];
    const float* d0_dw  = (const float*)d_in[9];
    const float* d0_db  = (const float*)d_in[10];
    const float* d0_cw  = (const float*)d_in[11];
    const float* d0_cb  = (const float*)d_in[12];
    const float* cell_k = (const float*)d_in[13];
    const float* cell_v = (const float*)d_in[14];
    float* outp = (float*)d_out;

    void *p_a1n, *p_hi, *p_lo, *p_wph, *p_wpl, *p_z, *p_ts, *p_w,
         *p_part, *p_gu, *p_vnew, *p_d0m, *p_dec;
    cudaGetSymbolAddress(&p_a1n, g_a1n);
    cudaGetSymbolAddress(&p_hi,  g_hi);
    cudaGetSymbolAddress(&p_lo,  g_lo);
    cudaGetSymbolAddress(&p_wph, g_wph);
    cudaGetSymbolAddress(&p_wpl, g_wpl);
    cudaGetSymbolAddress(&p_z,   g_z);
    cudaGetSymbolAddress(&p_ts,  g_ts);
    cudaGetSymbolAddress(&p_w,   g_w);
    cudaGetSymbolAddress(&p_part,g_part);
    cudaGetSymbolAddress(&p_gu,  g_gu);
    cudaGetSymbolAddress(&p_vnew,g_vnew);
    cudaGetSymbolAddress(&p_d0m, g_d0m);
    cudaGetSymbolAddress(&p_dec, g_dec);

    const int dsm_s1 = 2 * 34 * 36 * 4;   //  9792 B
    const int dsm_s2 = 2 * 65 * 72 * 4;   // 37440 B

    cudaFuncSetAttribute((const void*)convfast<3,16,2>,
                         cudaFuncAttributeMaxDynamicSharedMemorySize, dsm_s1);
    cudaFuncSetAttribute((const void*)convfast<3,128,3>,
                         cudaFuncAttributeMaxDynamicSharedMemorySize, dsm_s1);
    cudaFuncSetAttribute((const void*)convfast2<16,16>,
                         cudaFuncAttributeMaxDynamicSharedMemorySize, dsm_s2);
    cudaFuncSetAttribute((const void*)conv2s_mma,
                         cudaFuncAttributeMaxDynamicSharedMemorySize, C2_SMEM);

    // Prep: borders + packed weights
    zero_borders<<<Bb*Nn, 256>>>((float*)p_a1n);
    zb_nhwc<<<Bb, 256>>>((__nv_bfloat16*)p_hi, (__nv_bfloat16*)p_lo);
    wprep<<<288, 256>>>(e0s_w2, (u32t*)p_wph, (u32t*)p_wpl);

    // Encoders
    convfast<3,16,2><<<dim3(8,8,Bb),256,dsm_s1>>>(
        x, e0n_w1, e0n_b1, (float*)p_a1n, nullptr, nullptr, HIN, WIN);
    convfast<3,128,3><<<dim3(8,8,Bb*8),256,dsm_s1>>>(
        x, e0s_w1, e0s_b1, nullptr,
        (__nv_bfloat16*)p_hi, (__nv_bfloat16*)p_lo, HIN, WIN);
    convfast2<16,16><<<dim3(4,4,Bb),256,dsm_s2>>>(
        (const float*)p_a1n, e0n_w2, e0n_b2, (float*)p_z);
    conv2s_mma<<<dim3(2,128,Bb),256,C2_SMEM>>>(
        (const __nv_bfloat16*)p_hi, (const __nv_bfloat16*)p_lo,
        (const u32t*)p_wph, (const u32t*)p_wpl, e0s_b2, (float*)p_ts);

    // Memcell
    memcell_softmax<<<Tt/256,256>>>((const float*)p_z, cell_k, (float*)p_w);
    memcell_outer<<<1024,256>>>((const float*)p_w, (const float*)p_ts, (float*)p_part);
    reduce_partials<<<20,256>>>((const float*)p_part, (float*)p_gu);
    cell_update<<<1,256>>>((const float*)p_gu, cell_v, (float*)p_vnew);
    memcell_read<<<Tt/64,256>>>((const float*)p_w, (const float*)p_vnew, (float*)p_d0m);

    // Decoder
    deconv_kernel<<<dim3(8,8,Bb),256>>>(
        (const float*)p_d0m, d0_dw, d0_db, (float*)p_dec);
    conv3x3<3,3,3><<<dim3(16,16,Bb),256>>>(
        (const float*)p_dec, d0_cw, d0_cb, outp, HIN, WIN);
}

// round 14
// speedup vs baseline: 3.1815x; 1.1157x over previous
#include <cuda_runtime.h>
#include <cuda_bf16.h>
#include <cstdint>

// ---------------------------------------------------------------------------
// Problem constants
// ---------------------------------------------------------------------------
#define Bb   8
#define HIN  256
#define WIN  256
#define H2   128
#define W2   128
#define Nn   16
#define Mm   32
#define Ss   128
#define Tt   (Bb*H2*W2)          // 131072 tokens
#define ALPHA 1e-6f

// Padded parity-split activation layout (fp32 path, conv1_n -> conv2_n):
#define PROW 264
#define PCH  (258*PROW)

// NHWC-padded bf16 layout for conv1_s output (rows/cols padded by 1):
#define NR   258
#define NCH  ((size_t)NR*NR*128)

typedef unsigned long long u64;
typedef unsigned int u32t;

// ---------------------------------------------------------------------------
// Scratch buffers (static device globals; no cudaMalloc allowed)
// ---------------------------------------------------------------------------
__device__ float g_a1n [(size_t)Bb*Nn*PCH];        // padded silu(conv1_n) fp32
__device__ __nv_bfloat16 g_hi [(size_t)Bb*NCH];    // silu(conv1_s) bf16 hi
__device__ __nv_bfloat16 g_lo [(size_t)Bb*NCH];    // bf16 lo
__device__ u32t  g_wph[8*9*128*8];                 // packed conv2_s weights hi
__device__ u32t  g_wpl[8*9*128*8];                 // packed conv2_s weights lo
__device__ float g_z   [(size_t)Tt*Nn];
__device__ float g_ts  [(size_t)Tt*Ss];
__device__ float g_w   [(size_t)Tt*Mm];
__device__ float g_part[(size_t)1024*32*160];
__device__ float g_gu  [32*160];
__device__ float g_vnew[Mm*Ss];
__device__ float g_d0m [(size_t)Bb*Ss*H2*W2];
__device__ float g_dec [(size_t)Bb*3*HIN*WIN];

// ---------------------------------------------------------------------------
// cp.async + f32x2 helpers
// ---------------------------------------------------------------------------
__device__ __forceinline__ void cp_async4(unsigned dst, const float* src, int sz) {
    asm volatile("cp.async.ca.shared.global [%0], [%1], 4, %2;\n"
                 :: "r"(dst), "l"(src), "r"(sz));
}
__device__ __forceinline__ void cp_async4u(unsigned dst, const float* src) {
    asm volatile("cp.async.ca.shared.global [%0], [%1], 4;\n"
                 :: "r"(dst), "l"(src));
}
__device__ __forceinline__ void cp_async16(unsigned dst, const void* src) {
    asm volatile("cp.async.cg.shared.global [%0], [%1], 16;\n"
                 :: "r"(dst), "l"(src));
}
__device__ __forceinline__ void cp_commit() {
    asm volatile("cp.async.commit_group;\n" ::: "memory");
}
__device__ __forceinline__ void cp_wait0() {
    asm volatile("cp.async.wait_group 0;\n" ::: "memory");
}

#define FMA2(d, a, b) \
    asm("fma.rn.f32x2 %0, %1, %2, %0;" : "+l"(d) : "l"(a), "l"(b))
#define PACK2(dst, v) \
    asm("mov.b64 %0, {%1, %1};" : "=l"(dst) : "f"(v))
#define UNPACK2(lo, hi, src) \
    asm("mov.b64 {%0, %1}, %2;" : "=f"(lo), "=f"(hi) : "l"(src))

__device__ __forceinline__ void fma2_row(u64* acc, float v,
                                         const ulonglong2& q0, const ulonglong2& q1,
                                         const ulonglong2& q2, const ulonglong2& q3) {
    u64 vv; PACK2(vv, v);
    FMA2(acc[0], vv, q0.x); FMA2(acc[1], vv, q0.y);
    FMA2(acc[2], vv, q1.x); FMA2(acc[3], vv, q1.y);
    FMA2(acc[4], vv, q2.x); FMA2(acc[5], vv, q2.y);
    FMA2(acc[6], vv, q3.x); FMA2(acc[7], vv, q3.y);
}

// mma.sync m16n8k16 bf16 (fp32 accumulate)
#define MMA_BF16(c, a0,a1,a2,a3, b0,b1) \
    asm volatile("mma.sync.aligned.m16n8k16.row.col.f32.bf16.bf16.f32 " \
        "{%0,%1,%2,%3}, {%4,%5,%6,%7}, {%8,%9}, {%0,%1,%2,%3};" \
        : "+f"(c[0]), "+f"(c[1]), "+f"(c[2]), "+f"(c[3]) \
        : "r"(a0), "r"(a1), "r"(a2), "r"(a3), "r"(b0), "r"(b1))

__device__ __forceinline__ u32t pk_bf16x2(float a, float b) {
    __nv_bfloat162 t = __floats2bfloat162_rn(a, b);
    return *(u32t*)&t;
}

// ---------------------------------------------------------------------------
// Border zero kernels
// ---------------------------------------------------------------------------
__global__ void zero_borders(float* buf) {
    float* p = buf + (size_t)blockIdx.x * PCH;
    int tid = threadIdx.x;
    for (int i = tid; i < PROW; i += 256) p[i] = 0.f;
    p[(tid + 1) * PROW] = 0.f;
}

__global__ void zb_nhwc(__nv_bfloat16* gh, __nv_bfloat16* gl) {
    const int b = blockIdx.x;
    u32t* h = (u32t*)(gh + (size_t)b*NCH);
    u32t* l = (u32t*)(gl + (size_t)b*NCH);
    const int tid = threadIdx.x;
    for (int i = tid; i < NR*64; i += 256) {
        h[i] = 0u; l[i] = 0u;
        h[(size_t)257*NR*64 + i] = 0u; l[(size_t)257*NR*64 + i] = 0u;
    }
    for (int i = tid; i < 256*64; i += 256) {
        int r = 1 + i/64, c2 = i%64;
        size_t o0 = ((size_t)r*NR + 0)*64 + c2;
        size_t o1 = ((size_t)r*NR + 257)*64 + c2;
        h[o0] = 0u; l[o0] = 0u; h[o1] = 0u; l[o1] = 0u;
    }
}

// ---------------------------------------------------------------------------
// conv2_s weight pre-pack (same as R13)
// ---------------------------------------------------------------------------
__global__ void wprep(const float* __restrict__ wgt,
                      u32t* __restrict__ wph, u32t* __restrict__ wpl) {
    int i = blockIdx.x*256 + threadIdx.x;
    if (i >= 8*9*128*8) return;
    int q = i & 7;
    int r = i >> 3;
    int co = r & 127; r >>= 7;
    int tap = r % 9;
    int cc  = r / 9;
    int cin = cc*16 + 2*q;
    float w0 = wgt[co*1152 + cin*9 + tap];
    float w1 = wgt[co*1152 + (cin+1)*9 + tap];
    __nv_bfloat16 h0 = __float2bfloat16_rn(w0);
    __nv_bfloat16 h1 = __float2bfloat16_rn(w1);
    float l0 = w0 - __bfloat162float(h0);
    float l1 = w1 - __bfloat162float(h1);
    wph[i] = pk_bf16x2(__bfloat162float(h0), __bfloat162float(h1));
    wpl[i] = pk_bf16x2(l0, l1);
}

// ---------------------------------------------------------------------------
// Stride-1 fused conv3x3 + bias + SiLU (CIN=3).
// OUTMODE: 2 = padded parity fp32; 3 = NHWC-padded bf16 hi/lo split.
// ---------------------------------------------------------------------------
template<int CIN, int OUTC, int OUTMODE>
__global__ void __launch_bounds__(256, 2) convfast(
    const float* __restrict__ in, const float* __restrict__ wgt,
    const float* __restrict__ bias, float* __restrict__ out,
    __nv_bfloat16* __restrict__ outH, __nv_bfloat16* __restrict__ outL,
    int Hin, int Win)
{
    constexpr int COG  = 16;
    constexpr int ITX  = 34;
    constexpr int SRS  = 36;
    constexpr int ELEMS = ITX * ITX;
    constexpr int NIT  = (ELEMS + 255) / 256;
    constexpr int PLANE = ITX * SRS;

    extern __shared__ float sIn[];
    __shared__ float sW[2][COG*9 + 8];
    __shared__ int2 tTab[NIT*256];

    const int tid = threadIdx.x;
    const int tx = tid & 7, ty = tid >> 3;
    const int groups = OUTC / COG;
    const int b = blockIdx.z / groups;
    const int cbase = (blockIdx.z % groups) * COG;
    const int X0 = blockIdx.x * 32, Y0 = blockIdx.y * 32;
    const int iy0 = Y0 - 1, ix0 = X0 - 1;
    const size_t HW = (size_t)Hin * Win;
    const float* inb = in + (size_t)b * CIN * HW;

    const int wc = tid / 9, wtap = tid - wc*9;

#pragma unroll
    for (int k = 0; k < NIT; k++) {
        int f = k*256 + tid;
        int sof = -1, gof = -1;
        if (f < ELEMS) {
            int r = f / ITX, c = f - r*ITX;
            int ih = iy0 + r, iw = ix0 + c;
            sof = r*SRS + c;
            gof = ((unsigned)ih < (unsigned)Hin && (unsigned)iw < (unsigned)Win)
                  ? (ih*Win + iw) : -1;
        }
        tTab[k*256 + tid] = make_int2(gof, sof);
    }

    const unsigned sb0 = (unsigned)__cvta_generic_to_shared(sIn);
    auto stage = [&](int buf, int cin) {
        const float* ic = inb + (size_t)cin * HW;
        const unsigned sb = sb0 + (unsigned)buf * (PLANE*4);
#pragma unroll
        for (int k = 0; k < NIT; k++) {
            int2 t = tTab[k*256 + tid];
            if (t.y >= 0)
                cp_async4(sb + (unsigned)t.y*4, ic + (t.x < 0 ? 0 : t.x),
                          t.x < 0 ? 0 : 4);
        }
        if (tid < COG*9) {
            unsigned dst = (unsigned)__cvta_generic_to_shared(
                               &sW[buf][wtap*COG + wc]);
            cp_async4u(dst, wgt + ((size_t)(cbase+wc)*CIN + cin)*9 + wtap);
        }
    };

    stage(0, 0);
    cp_commit();
    cp_wait0();
    __syncthreads();

    u64 acc2[4][8];
#pragma unroll
    for (int j = 0; j < 4; j++)
#pragma unroll
        for (int p = 0; p < 8; p++) acc2[j][p] = 0ull;

    for (int cin = 0; cin < CIN; cin++) {
        const int cur = cin & 1;
        if (cin + 1 < CIN) { stage(cur^1, cin+1); cp_commit(); }

        const float* sc  = sIn + cur*PLANE;
        const float* swp = sW[cur];
#pragma unroll
        for (int dy = 0; dy < 3; dy++) {
            const float* rp = sc + (ty + dy)*SRS + tx*4;
            float4 A = *(const float4*)rp;
            float2 Bv = *(const float2*)(rp + 4);
            float iv6[6] = {A.x, A.y, A.z, A.w, Bv.x, Bv.y};
#pragma unroll
            for (int dx = 0; dx < 3; dx++) {
                const ulonglong2* wq = (const ulonglong2*)(swp + (dy*3+dx)*COG);
                ulonglong2 q0 = wq[0], q1 = wq[1], q2 = wq[2], q3 = wq[3];
#pragma unroll
                for (int j = 0; j < 4; j++)
                    fma2_row(acc2[j], iv6[j+dx], q0, q1, q2, q3);
            }
        }
        if (cin + 1 < CIN) cp_wait0();
        __syncthreads();
    }

    float bv[COG];
#pragma unroll
    for (int c = 0; c < COG; c++) bv[c] = __ldg(bias + cbase + c);

    const int oy = Y0 + ty;
    const int x0 = X0 + tx*4;
    if (OUTMODE == 3) {
#pragma unroll
        for (int j = 0; j < 4; j++) {
            u32t hp[8], lp[8];
#pragma unroll
            for (int p = 0; p < 8; p++) {
                float flo, fhi;
                UNPACK2(flo, fhi, acc2[j][p]);
                float v0 = flo + bv[2*p];     v0 = v0 / (1.f + __expf(-v0));
                float v1 = fhi + bv[2*p+1];   v1 = v1 / (1.f + __expf(-v1));
                __nv_bfloat16 h0 = __float2bfloat16_rn(v0);
                __nv_bfloat16 h1 = __float2bfloat16_rn(v1);
                hp[p] = pk_bf16x2(v0, v1);
                lp[p] = pk_bf16x2(v0 - __bfloat162float(h0),
                                  v1 - __bfloat162float(h1));
            }
            size_t base = (((size_t)b*NR + (oy+1))*NR + (x0+j+1))*128 + cbase;
            uint4* dh = (uint4*)(outH + base);
            uint4* dl = (uint4*)(outL + base);
            dh[0] = make_uint4(hp[0],hp[1],hp[2],hp[3]);
            dh[1] = make_uint4(hp[4],hp[5],hp[6],hp[7]);
            dl[0] = make_uint4(lp[0],lp[1],lp[2],lp[3]);
            dl[1] = make_uint4(lp[4],lp[5],lp[6],lp[7]);
        }
    } else {
#pragma unroll
        for (int c = 0; c < COG; c++) {
            float vv[4];
#pragma unroll
            for (int j = 0; j < 4; j++) {
                float flo, fhi;
                UNPACK2(flo, fhi, acc2[j][c >> 1]);
                float v = ((c & 1) ? fhi : flo) + bv[c];
                vv[j] = v / (1.f + __expf(-v));
            }
            size_t rowbase = ((size_t)(b*OUTC + cbase + c)*258 + (oy+1))*PROW;
            *(float2*)(out + rowbase + 132 + (x0>>1)) = make_float2(vv[0], vv[2]);
            out[rowbase + (x0>>1) + 1] = vv[1];
            out[rowbase + (x0>>1) + 2] = vv[3];
        }
    }
}

// ---------------------------------------------------------------------------
// Stride-2 conv (fp32 FFMA2 path) — conv2_n (16->16) only.
// ---------------------------------------------------------------------------
template<int CIN, int OUTC>
__global__ void __launch_bounds__(256, 2) convfast2(
    const float* __restrict__ in, const float* __restrict__ wgt,
    const float* __restrict__ bias, float* __restrict__ out)
{
    constexpr int COG  = 16;
    constexpr int SRS  = 72;
    constexpr int ODD  = 36;
    constexpr int PLANE = 65*SRS;
    constexpr int NOPS = 65*18;

    extern __shared__ float sIn[];
    __shared__ float sW[2][COG*9 + 8];

    const int tid = threadIdx.x;
    const int tx = tid & 7, ty = tid >> 3;
    const int groups = OUTC / COG;
    const int b = blockIdx.z / groups;
    const int cbase = (blockIdx.z % groups) * COG;
    const int X0 = blockIdx.x * 32, Y0 = blockIdx.y * 32;
    const float* inb = in + (size_t)b * CIN * PCH;

    const int wc = tid / 9, wtap = tid - wc*9;

    int gofs[5]; int sofs[5];
#pragma unroll
    for (int k = 0; k < 5; k++) {
        int id = k*256 + tid;
        if (id < NOPS) {
            int row = id / 18;
            int rem = id - row*18;
            int seg = rem / 9;
            int q   = rem - seg*9;
            gofs[k] = (2*Y0 + row)*PROW + seg*132 + X0 + q*4;
            sofs[k] = (row*SRS + seg*ODD + q*4) * 4;
        } else { gofs[k] = 0; sofs[k] = -1; }
    }

    const unsigned sb0 = (unsigned)__cvta_generic_to_shared(sIn);
    auto stage = [&](int buf, int cin) {
        const float* ic = inb + (size_t)cin * PCH;
        const unsigned sb = sb0 + (unsigned)buf * (PLANE*4);
#pragma unroll
        for (int k = 0; k < 5; k++)
            if (sofs[k] >= 0) cp_async16(sb + (unsigned)sofs[k], ic + gofs[k]);
        if (tid < COG*9) {
            unsigned dst = (unsigned)__cvta_generic_to_shared(
                               &sW[buf][wtap*COG + wc]);
            cp_async4u(dst, wgt + ((size_t)(cbase+wc)*CIN + cin)*9 + wtap);
        }
    };

    stage(0, 0);
    cp_commit();
    cp_wait0();
    __syncthreads();

    u64 acc2[4][8];
#pragma unroll
    for (int j = 0; j < 4; j++)
#pragma unroll
        for (int p = 0; p < 8; p++) acc2[j][p] = 0ull;

    for (int cin = 0; cin < CIN; cin++) {
        const int cur = cin & 1;
        if (cin + 1 < CIN) { stage(cur^1, cin+1); cp_commit(); }

        const float* sc  = sIn + cur*PLANE;
        const float* swp = sW[cur];
#pragma unroll
        for (int dy = 0; dy < 3; dy++) {
            const float* rp = sc + (ty*2 + dy)*SRS;
            float4 E = *(const float4*)(rp + tx*4);
            float  e4 = rp[tx*4 + 4];
            float4 O = *(const float4*)(rp + ODD + tx*4);
            float V[3][4];
            V[0][0]=E.x; V[0][1]=E.y; V[0][2]=E.z; V[0][3]=E.w;
            V[1][0]=O.x; V[1][1]=O.y; V[1][2]=O.z; V[1][3]=O.w;
            V[2][0]=E.y; V[2][1]=E.z; V[2][2]=E.w; V[2][3]=e4;
#pragma unroll
            for (int dx = 0; dx < 3; dx++) {
                const ulonglong2* wq = (const ulonglong2*)(swp + (dy*3+dx)*COG);
                ulonglong2 q0 = wq[0], q1 = wq[1], q2 = wq[2], q3 = wq[3];
#pragma unroll
                for (int j = 0; j < 4; j++)
                    fma2_row(acc2[j], V[dx][j], q0, q1, q2, q3);
            }
        }
        if (cin + 1 < CIN) cp_wait0();
        __syncthreads();
    }

    float bv[COG];
#pragma unroll
    for (int c = 0; c < COG; c++) bv[c] = __ldg(bias + cbase + c);

    const int oy = Y0 + ty;
#pragma unroll
    for (int j = 0; j < 4; j++) {
        float vv[COG];
#pragma unroll
        for (int p = 0; p < 8; p++) {
            float flo, fhi;
            UNPACK2(flo, fhi, acc2[j][p]);
            float v0 = flo + bv[2*p],     v1 = fhi + bv[2*p+1];
            vv[2*p]   = v0 / (1.f + __expf(-v0));
            vv[2*p+1] = v1 / (1.f + __expf(-v1));
        }
        size_t t = ((size_t)b*H2 + oy)*W2 + X0 + tx*4 + j;
        float4* op = (float4*)(out + t*OUTC + cbase);
        op[0] = make_float4(vv[0],  vv[1],  vv[2],  vv[3]);
        op[1] = make_float4(vv[4],  vv[5],  vv[6],  vv[7]);
        op[2] = make_float4(vv[8],  vv[9],  vv[10], vv[11]);
        op[3] = make_float4(vv[12], vv[13], vv[14], vv[15]);
    }
}

// ---------------------------------------------------------------------------
// conv2_s token-GEMM (mma.sync m16n8k16 bf16, 3-pass).
// Block: 128 tokens (one full y row) x 128 co, 8 warps; warp = 16 tokens x
// 128 co (nt 0..15). B restaging amortized 2x vs R13 (1024 blocks).
// ---------------------------------------------------------------------------
#define APS 12
#define BPS 12
#define SA_U32 (3*258*APS)          // 9288 u32
#define SB_U32 (9*128*BPS)          // 13824 u32
#define C2_SMEM ((2*SA_U32 + 2*SB_U32)*4)   // 184896 B

__global__ void __launch_bounds__(256, 1) conv2s_mma(
    const __nv_bfloat16* __restrict__ gh, const __nv_bfloat16* __restrict__ gl,
    const u32t* __restrict__ wph, const u32t* __restrict__ wpl,
    const float* __restrict__ bias, float* __restrict__ out)
{
    extern __shared__ u32t sm32[];
    u32t* sAh = sm32;
    u32t* sAl = sAh + SA_U32;
    u32t* sBh = sAl + SA_U32;
    u32t* sBl = sBh + SB_U32;

    const int tid = threadIdx.x, lane = tid & 31, w = tid >> 5;
    const int y  = blockIdx.x;
    const int b  = blockIdx.y;

    const unsigned aH = (unsigned)__cvta_generic_to_shared(sAh);
    const unsigned aL = (unsigned)__cvta_generic_to_shared(sAl);
    const unsigned bH = (unsigned)__cvta_generic_to_shared(sBh);
    const unsigned bL = (unsigned)__cvta_generic_to_shared(sBl);

    float acc[16][4];
#pragma unroll
    for (int nt = 0; nt < 16; nt++)
#pragma unroll
        for (int r = 0; r < 4; r++) acc[nt][r] = 0.f;

    const int q = lane & 3;
    const int g = lane >> 2;
    const int mlow = 16*w + g;

    for (int cc = 0; cc < 8; cc++) {
        __syncthreads();
        // ---- stage A: 774 positions x {half, buf} = 3096 cp.async.16
        for (int i = tid; i < 3096; i += 256) {
            int pos = i >> 2; int half = (i >> 1) & 1; int buf = i & 1;
            int dy = pos / 258, pl = pos - dy*258;
            size_t gofs = (((size_t)b*NR + (2*y + dy))*NR + pl)*128
                          + cc*16 + half*8;
            const __nv_bfloat16* src = (buf ? gl : gh) + gofs;
            unsigned dst = (buf ? aL : aH) + (unsigned)(pos*APS*4 + half*16);
            cp_async16(dst, src);
        }
        // ---- stage B: (tap,co) 1152 x {half, buf} = 4608 cp.async.16
        for (int i = tid; i < 4608; i += 256) {
            int tc = i >> 2; int half = (i >> 1) & 1; int buf = i & 1;
            const u32t* src = (buf ? wpl : wph) + (cc*1152 + tc)*8 + half*4;
            unsigned dst = (buf ? bL : bH) + (unsigned)(tc*BPS*4 + half*16);
            cp_async16(dst, src);
        }
        cp_commit();
        cp_wait0();
        __syncthreads();

        // ---- compute: 9 taps x 16 n-tiles x 3 passes
#pragma unroll
        for (int dy = 0; dy < 3; dy++)
#pragma unroll
        for (int dx = 0; dx < 3; dx++) {
            const int tap = dy*3 + dx;
            const int baseA = (dy*258 + 2*mlow + dx) * APS;
            const int baseA8 = baseA + 16*APS;            // token +8
            u32t a0h = sAh[baseA + q],      a2h = sAh[baseA + q + 4];
            u32t a1h = sAh[baseA8 + q],     a3h = sAh[baseA8 + q + 4];
            u32t a0l = sAl[baseA + q],      a2l = sAl[baseA + q + 4];
            u32t a1l = sAl[baseA8 + q],     a3l = sAl[baseA8 + q + 4];
#pragma unroll
            for (int nt = 0; nt < 16; nt++) {
                int co = 8*nt + g;
                int bb = (tap*128 + co) * BPS;
                u32t bh0 = sBh[bb + q], bh1 = sBh[bb + q + 4];
                u32t bl0 = sBl[bb + q], bl1 = sBl[bb + q + 4];
                MMA_BF16(acc[nt], a0h, a1h, a2h, a3h, bh0, bh1);
                MMA_BF16(acc[nt], a0h, a1h, a2h, a3h, bl0, bl1);
                MMA_BF16(acc[nt], a0l, a1l, a2l, a3l, bh0, bh1);
            }
        }
    }

    // ---- epilogue: bias + SiLU -> token-major g_ts
    size_t t1 = ((size_t)(b*H2 + y)*W2 + mlow) * 128;
    size_t t2 = t1 + (size_t)8*128;
#pragma unroll
    for (int nt = 0; nt < 16; nt++) {
        int co = 8*nt + 2*q;
        float bv0 = __ldg(bias + co), bv1 = __ldg(bias + co + 1);
        float v0 = acc[nt][0] + bv0; v0 = v0 / (1.f + __expf(-v0));
        float v1 = acc[nt][1] + bv1; v1 = v1 / (1.f + __expf(-v1));
        float v2 = acc[nt][2] + bv0; v2 = v2 / (1.f + __expf(-v2));
        float v3 = acc[nt][3] + bv1; v3 = v3 / (1.f + __expf(-v3));
        *(float2*)(out + t1 + co) = make_float2(v0, v1);
        *(float2*)(out + t2 + co) = make_float2(v2, v3);
    }
}

// ---------------------------------------------------------------------------
// Legacy conv (final tiny 3->3 decoder conv)
// ---------------------------------------------------------------------------
template<int CIN, int OUTC, int COG>
__global__ void __launch_bounds__(256) conv3x3(
    const float* __restrict__ in, const float* __restrict__ wgt,
    const float* __restrict__ bias, float* __restrict__ out,
    int Hin, int Win)
{
    constexpr int ITD = 18;
    __shared__ float sW[COG*CIN*9];
    __shared__ float sIn[ITD*ITD];

    const int tid = threadIdx.x;
    const int groups = OUTC / COG;
    const int b  = blockIdx.z / groups;
    const int cbase = (blockIdx.z % groups) * COG;

    for (int i = tid; i < COG*CIN*9; i += 256)
        sW[i] = wgt[(size_t)cbase*CIN*9 + i];

    const int ty = tid >> 4, tx = tid & 15;
    const int oy = blockIdx.y*16 + ty;
    const int ox = blockIdx.x*16 + tx;

    float acc[COG];
#pragma unroll
    for (int c = 0; c < COG; c++) acc[c] = 0.f;

    const float* inb = in + (size_t)b * CIN * Hin * Win;
    const int iy0 = blockIdx.y*16 - 1;
    const int ix0 = blockIdx.x*16 - 1;
    const int base = ty*ITD + tx;

    for (int cin = 0; cin < CIN; cin++) {
        __syncthreads();
        const float* ic = inb + (size_t)cin * Hin * Win;
        for (int i = tid; i < ITD*ITD; i += 256) {
            int r = i / ITD, cc = i - r*ITD;
            int ih = iy0 + r, iw = ix0 + cc;
            float v = 0.f;
            if ((unsigned)ih < (unsigned)Hin && (unsigned)iw < (unsigned)Win)
                v = ic[ih*Win + iw];
            sIn[i] = v;
        }
        __syncthreads();
        const float* wp = sW + cin*9;
#pragma unroll
        for (int dy = 0; dy < 3; dy++)
#pragma unroll
            for (int dx = 0; dx < 3; dx++) {
                float iv = sIn[base + dy*ITD + dx];
#pragma unroll
                for (int c = 0; c < COG; c++)
                    acc[c] += iv * wp[c*CIN*9 + dy*3 + dx];
            }
    }

#pragma unroll
    for (int c = 0; c < COG; c++) {
        float v = acc[c] + bias[cbase + c];
        v = v / (1.f + __expf(-v));
        out[(((size_t)b*OUTC + cbase + c)*Hin + oy)*Win + ox] = v;
    }
}

// ---------------------------------------------------------------------------
// Memcell pass 1: w = softmax(z @ K^T / 4) per token.
// ---------------------------------------------------------------------------
__global__ void __launch_bounds__(256) memcell_softmax(
    const float* __restrict__ z, const float* __restrict__ ck,
    float* __restrict__ wout)
{
    __shared__ float sK[Mm*Nn];
    const int tid = threadIdx.x;
    for (int i = tid; i < Mm*Nn; i += 256) sK[i] = ck[i];
    __syncthreads();

    const int t = blockIdx.x*256 + tid;
    const float4* zp = (const float4*)(z + (size_t)t*Nn);
    float4 z0 = zp[0], z1 = zp[1], z2 = zp[2], z3 = zp[3];

    float s[Mm];
    float mx = -1e30f;
#pragma unroll
    for (int m = 0; m < Mm; m++) {
        const float* k = sK + m*Nn;
        float d = z0.x*k[0] + z0.y*k[1] + z0.z*k[2] + z0.w*k[3]
                + z1.x*k[4] + z1.y*k[5] + z1.z*k[6] + z1.w*k[7]
                + z2.x*k[8] + z2.y*k[9] + z2.z*k[10]+ z2.w*k[11]
                + z3.x*k[12]+ z3.y*k[13]+ z3.z*k[14]+ z3.w*k[15];
        d *= 0.25f;
        s[m] = d;
        mx = fmaxf(mx, d);
    }
    float sum = 0.f;
#pragma unroll
    for (int m = 0; m < Mm; m++) { s[m] = __expf(s[m]-mx); sum += s[m]; }
    float inv = 1.f / sum;
    float4* wo = (float4*)(wout + (size_t)t*Mm);
#pragma unroll
    for (int j = 0; j < Mm/4; j++) {
        float4 v; v.x = s[4*j]*inv; v.y = s[4*j+1]*inv;
        v.z = s[4*j+2]*inv; v.w = s[4*j+3]*inv;
        wo[j] = v;
    }
}

// ---------------------------------------------------------------------------
// Memcell pass 2: block partials of [G | U].
// ---------------------------------------------------------------------------
__global__ void __launch_bounds__(256) memcell_outer(
    const float* __restrict__ wmat, const float* __restrict__ ts,
    float* __restrict__ part)
{
    __shared__ float sv[8*160];
    const int tid = threadIdx.x;
    const int ti = tid >> 5;
    const int tj = tid & 31;
    float acc[4][5];
#pragma unroll
    for (int a = 0; a < 4; a++)
#pragma unroll
        for (int qq = 0; qq < 5; qq++) acc[a][qq] = 0.f;

    const int tokb = blockIdx.x * 128;
    for (int ch = 0; ch < 128; ch += 8) {
        __syncthreads();
#pragma unroll
        for (int l = 0; l < 5; l++) {
            int idx = l*256 + tid;
            int tk = idx / 160, f = idx - tk*160;
            int t = tokb + ch + tk;
            sv[tk*160 + f] = (f < 32) ? wmat[(size_t)t*32 + f]
                                      : ts[(size_t)t*128 + (f-32)];
        }
        __syncthreads();
#pragma unroll
        for (int tk = 0; tk < 8; tk++) {
            float wi[4], vj[5];
#pragma unroll
            for (int a = 0; a < 4; a++) wi[a] = sv[tk*160 + ti*4 + a];
#pragma unroll
            for (int qq = 0; qq < 5; qq++) vj[qq] = sv[tk*160 + tj*5 + qq];
#pragma unroll
            for (int a = 0; a < 4; a++)
#pragma unroll
                for (int qq = 0; qq < 5; qq++) acc[a][qq] += wi[a]*vj[qq];
        }
    }
    float* pp = part + (size_t)blockIdx.x * 5120;
#pragma unroll
    for (int a = 0; a < 4; a++)
#pragma unroll
        for (int qq = 0; qq < 5; qq++)
            pp[(ti*4+a)*160 + tj*5 + qq] = acc[a][qq];
}

__global__ void __launch_bounds__(256) reduce_partials(
    const float* __restrict__ part, float* __restrict__ gu)
{
    int cell = blockIdx.x*256 + threadIdx.x;
    float s = 0.f;
#pragma unroll 8
    for (int p = 0; p < 1024; p++) s += part[(size_t)p*5120 + cell];
    gu[cell] = s;
}

__global__ void __launch_bounds__(256) cell_update(
    const float* __restrict__ gu, const float* __restrict__ cv,
    float* __restrict__ vnew)
{
    __shared__ float sG[Mm*Mm];
    __shared__ float sV[Mm*Ss];
    const int tid = threadIdx.x;
    for (int i = tid; i < Mm*Mm; i += 256) {
        int m = i >> 5, j = i & 31;
        sG[i] = gu[m*160 + j];
    }
    for (int i = tid; i < Mm*Ss; i += 256) sV[i] = cv[i];
    __syncthreads();
    for (int k = 0; k < 16; k++) {
        int cell = k*256 + tid;
        int m = cell >> 7, s0 = cell & 127;
        float d = gu[m*160 + 32 + s0];
#pragma unroll
        for (int mp = 0; mp < Mm; mp++) d -= sG[m*32 + mp] * sV[mp*128 + s0];
        vnew[cell] = sV[cell] + ALPHA * d;
    }
}

// ---------------------------------------------------------------------------
// Memcell pass 3: t_read = W @ cell_v_new -> NCHW [B,S,H2,W2].
// ---------------------------------------------------------------------------
__global__ void __launch_bounds__(256) memcell_read(
    const float* __restrict__ wmat, const float* __restrict__ vnew,
    float* __restrict__ d0m)
{
    __shared__ float sV[Mm*Ss];
    __shared__ float sW[64*33];
    const int tid = threadIdx.x;
    for (int i = tid; i < Mm*Ss; i += 256) sV[i] = vnew[i];
    const int tbase = blockIdx.x * 64;
    for (int i = tid; i < 64*32; i += 256) {
        int tk = i >> 5, m = i & 31;
        sW[tk*33 + m] = wmat[(size_t)(tbase + tk)*32 + m];
    }
    __syncthreads();

    const int lane = tid & 31, wid = tid >> 5;
    const int cb = wid * 16;
    float a0[16], a1[16];
#pragma unroll
    for (int c = 0; c < 16; c++) { a0[c] = 0.f; a1[c] = 0.f; }

    const float* w0 = sW + lane*33;
    const float* w1 = sW + (lane + 32)*33;
#pragma unroll 4
    for (int m = 0; m < Mm; m++) {
        float x0 = w0[m], x1 = w1[m];
        const float4* vv = (const float4*)(sV + m*128 + cb);
#pragma unroll
        for (int qq = 0; qq < 4; qq++) {
            float4 v = vv[qq];
            a0[qq*4+0] += x0*v.x; a0[qq*4+1] += x0*v.y;
            a0[qq*4+2] += x0*v.z; a0[qq*4+3] += x0*v.w;
            a1[qq*4+0] += x1*v.x; a1[qq*4+1] += x1*v.y;
            a1[qq*4+2] += x1*v.z; a1[qq*4+3] += x1*v.w;
        }
    }
    const int b = tbase >> 14;
    const int rem = tbase & 16383;
    const int h = rem >> 7;
    const int wcp = rem & 127;
    size_t obase = ((size_t)b*Ss)*((size_t)H2*W2) + (size_t)h*W2 + wcp;
#pragma unroll
    for (int c = 0; c < 16; c++) {
        size_t o = obase + (size_t)(cb + c)*(H2*W2);
        d0m[o + lane]      = a0[c];
        d0m[o + 32 + lane] = a1[c];
    }
}

// ---------------------------------------------------------------------------
// ConvTranspose2d(128->3, k4, s2, p1) + bias + SiLU.  32x32 output tiles.
// ---------------------------------------------------------------------------
__global__ void __launch_bounds__(256) deconv_kernel(
    const float* __restrict__ in, const float* __restrict__ dw,
    const float* __restrict__ db, float* __restrict__ out)
{
    __shared__ float sWd[4*128*12];
    __shared__ float sIn[16*324];
    const int tid = threadIdx.x;
    for (int i = tid; i < 4*128*12; i += 256) {
        int p = i / 1536, rem = i - p*1536;
        int cin = rem / 12, rr = rem - cin*12;
        int o = rr >> 2, k = rr & 3;
        int py = p >> 1, px = p & 1;
        int ky = py + 2*(k >> 1), kx = px + 2*(k & 1);
        sWd[i] = dw[cin*48 + o*16 + ky*4 + kx];
    }

    const int b  = blockIdx.z;
    const int Y0 = blockIdx.y*32, X0 = blockIdx.x*32;
    const int ty = tid >> 4, tx = tid & 15;
    const int y0 = Y0 + ty, x0 = X0 + tx;
    const int hb = (Y0 >> 1) - 1, wb = (X0 >> 1) - 1;

    const int py = (y0 + 1) & 1, px = (x0 + 1) & 1;
    const int hs0 = ((y0 + 1 - py) >> 1) - hb;
    const int ws0 = ((x0 + 1 - px) >> 1) - wb;

    const float* wp = sWd + (py*2 + px)*1536;
    float acc[2][2][3];
#pragma unroll
    for (int a = 0; a < 2; a++)
#pragma unroll
        for (int e = 0; e < 2; e++)
#pragma unroll
            for (int o = 0; o < 3; o++) acc[a][e][o] = 0.f;

    const float* inb = in + (size_t)b * Ss * H2 * W2;

    for (int c0 = 0; c0 < Ss; c0 += 16) {
        __syncthreads();
        for (int i = tid; i < 16*324; i += 256) {
            int c = i / 324, rr = i - c*324;
            int r = rr / 18, cc = rr - r*18;
            int h = hb + r, w = wb + cc;
            float v = 0.f;
            if ((unsigned)h < (unsigned)H2 && (unsigned)w < (unsigned)W2)
                v = inb[((size_t)(c0 + c)*H2 + h)*W2 + w];
            sIn[i] = v;
        }
        __syncthreads();
#pragma unroll
        for (int c = 0; c < 16; c++) {
            const float* sc = sIn + c*324;
            const float4* w4 = (const float4*)(wp + (c0 + c)*12);
            float4 Wa = w4[0], Wb = w4[1], Wc = w4[2];
#pragma unroll
            for (int a = 0; a < 2; a++)
#pragma unroll
                for (int e = 0; e < 2; e++) {
                    int hh = hs0 + 8*a, ww = ws0 + 8*e;
                    float i00 = sc[hh*18 + ww];
                    float i01 = sc[hh*18 + ww - 1];
                    float i10 = sc[(hh-1)*18 + ww];
                    float i11 = sc[(hh-1)*18 + ww - 1];
                    acc[a][e][0] += i00*Wa.x + i01*Wa.y + i10*Wa.z + i11*Wa.w;
                    acc[a][e][1] += i00*Wb.x + i01*Wb.y + i10*Wb.z + i11*Wb.w;
                    acc[a][e][2] += i00*Wc.x + i01*Wc.y + i10*Wc.z + i11*Wc.w;
                }
        }
    }
#pragma unroll
    for (int a = 0; a < 2; a++)
#pragma unroll
        for (int e = 0; e < 2; e++)
#pragma unroll
            for (int o = 0; o < 3; o++) {
                float v = acc[a][e][o] + db[o];
                v = v / (1.f + __expf(-v));
                out[(((size_t)b*3 + o)*HIN + y0 + 16*a)*WIN + x0 + 16*e] = v;
            }
}

// ---------------------------------------------------------------------------
// Launch sequence
// ---------------------------------------------------------------------------
extern "C" void kernel_launch(void* const* d_in, const int* in_sizes, int n_in,
                              void* d_out, int out_size)
{
    const float* x      = (const float*)d_in[0];
    const float* e0n_w1 = (const float*)d_in[1];
    const float* e0n_b1 = (const float*)d_in[2];
    const float* e0n_w2 = (const float*)d_in[3];
    const float* e0n_b2 = (const float*)d_in[4];
    const float* e0s_w1 = (const float*)d_in[5];
    const float* e0s_b1 = (const float*)d_in[6];
    const float* e0s_w2 = (const float*)d_in[7];
    const float* e0s_b2 = (const float*)d_in[8];
    const float* d0_dw  = (const float*)d_in[9];
    const float* d0_db  = (const float*)d_in[10];
    const float* d0_cw  = (const float*)d_in[11];
    const float* d0_cb  = (const float*)d_in[12];
    const float* cell_k = (const float*)d_in[13];
    const float* cell_v = (const float*)d_in[14];
    float* outp = (float*)d_out;

    void *p_a1n, *p_hi, *p_lo, *p_wph, *p_wpl, *p_z, *p_ts, *p_w,
         *p_part, *p_gu, *p_vnew, *p_d0m, *p_dec;
    cudaGetSymbolAddress(&p_a1n, g_a1n);
    cudaGetSymbolAddress(&p_hi,  g_hi);
    cudaGetSymbolAddress(&p_lo,  g_lo);
    cudaGetSymbolAddress(&p_wph, g_wph);
    cudaGetSymbolAddress(&p_wpl, g_wpl);
    cudaGetSymbolAddress(&p_z,   g_z);
    cudaGetSymbolAddress(&p_ts,  g_ts);
    cudaGetSymbolAddress(&p_w,   g_w);
    cudaGetSymbolAddress(&p_part,g_part);
    cudaGetSymbolAddress(&p_gu,  g_gu);
    cudaGetSymbolAddress(&p_vnew,g_vnew);
    cudaGetSymbolAddress(&p_d0m, g_d0m);
    cudaGetSymbolAddress(&p_dec, g_dec);

    const int dsm_s1 = 2 * 34 * 36 * 4;   //  9792 B
    const int dsm_s2 = 2 * 65 * 72 * 4;   // 37440 B

    cudaFuncSetAttribute((const void*)convfast<3,16,2>,
                         cudaFuncAttributeMaxDynamicSharedMemorySize, dsm_s1);
    cudaFuncSetAttribute((const void*)convfast<3,128,3>,
                         cudaFuncAttributeMaxDynamicSharedMemorySize, dsm_s1);
    cudaFuncSetAttribute((const void*)convfast2<16,16>,
                         cudaFuncAttributeMaxDynamicSharedMemorySize, dsm_s2);
    cudaFuncSetAttribute((const void*)conv2s_mma,
                         cudaFuncAttributeMaxDynamicSharedMemorySize, C2_SMEM);

    // Prep: borders + packed weights
    zero_borders<<<Bb*Nn, 256>>>((float*)p_a1n);
    zb_nhwc<<<Bb, 256>>>((__nv_bfloat16*)p_hi, (__nv_bfloat16*)p_lo);
    wprep<<<288, 256>>>(e0s_w2, (u32t*)p_wph, (u32t*)p_wpl);

    // Encoders
    convfast<3,16,2><<<dim3(8,8,Bb),256,dsm_s1>>>(
        x, e0n_w1, e0n_b1, (float*)p_a1n, nullptr, nullptr, HIN, WIN);
    convfast<3,128,3><<<dim3(8,8,Bb*8),256,dsm_s1>>>(
        x, e0s_w1, e0s_b1, nullptr,
        (__nv_bfloat16*)p_hi, (__nv_bfloat16*)p_lo, HIN, WIN);
    convfast2<16,16><<<dim3(4,4,Bb),256,dsm_s2>>>(
        (const float*)p_a1n, e0n_w2, e0n_b2, (float*)p_z);
    conv2s_mma<<<dim3(128,Bb),256,C2_SMEM>>>(
        (const __nv_bfloat16*)p_hi, (const __nv_bfloat16*)p_lo,
        (const u32t*)p_wph, (const u32t*)p_wpl, e0s_b2, (float*)p_ts);

    // Memcell
    memcell_softmax<<<Tt/256,256>>>((const float*)p_z, cell_k, (float*)p_w);
    memcell_outer<<<1024,256>>>((const float*)p_w, (const float*)p_ts, (float*)p_part);
    reduce_partials<<<20,256>>>((const float*)p_part, (float*)p_gu);
    cell_update<<<1,256>>>((const float*)p_gu, cell_v, (float*)p_vnew);
    memcell_read<<<Tt/64,256>>>((const float*)p_w, (const float*)p_vnew, (float*)p_d0m);

    // Decoder
    deconv_kernel<<<dim3(8,8,Bb),256>>>(
        (const float*)p_d0m, d0_dw, d0_db, (float*)p_dec);
    conv3x3<3,3,3><<<dim3(16,16,Bb),256>>>(
        (const float*)p_dec, d0_cw, d0_cb, outp, HIN, WIN);
}

// round 15
// speedup vs baseline: 4.1051x; 1.2903x over previous
#include <cuda_runtime.h>
#include <cuda_bf16.h>
#include <cstdint>

// ---------------------------------------------------------------------------
// Problem constants
// ---------------------------------------------------------------------------
#define Bb   8
#define HIN  256
#define WIN  256
#define H2   128
#define W2   128
#define Nn   16
#define Mm   32
#define Ss   128
#define Tt   (Bb*H2*W2)          // 131072 tokens
#define ALPHA 1e-6f

// Padded parity-split activation layout (fp32 path, conv1_n -> conv2_n):
#define PROW 264
#define PCH  (258*PROW)

// NHWC-padded bf16 layout for conv1_s output (rows/cols padded by 1):
#define NR   258
#define NCH  ((size_t)NR*NR*128)

typedef unsigned long long u64;
typedef unsigned int u32t;

// ---------------------------------------------------------------------------
// Scratch buffers (static device globals; no cudaMalloc allowed)
// ---------------------------------------------------------------------------
__device__ float g_a1n [(size_t)Bb*Nn*PCH];        // padded silu(conv1_n) fp32
__device__ __nv_bfloat16 g_hi [(size_t)Bb*NCH];    // silu(conv1_s) bf16
__device__ u32t  g_wph[8*9*128*8];                 // packed conv2_s weights bf16
__device__ float g_z   [(size_t)Tt*Nn];
__device__ float g_ts  [(size_t)Tt*Ss];
__device__ float g_w   [(size_t)Tt*Mm];
__device__ float g_part[(size_t)1024*32*160];
__device__ float g_gu  [32*160];
__device__ float g_vnew[Mm*Ss];
__device__ float g_d0m [(size_t)Bb*Ss*H2*W2];
__device__ float g_dec [(size_t)Bb*3*HIN*WIN];

// ---------------------------------------------------------------------------
// cp.async + f32x2 helpers
// ---------------------------------------------------------------------------
__device__ __forceinline__ void cp_async4(unsigned dst, const float* src, int sz) {
    asm volatile("cp.async.ca.shared.global [%0], [%1], 4, %2;\n"
                 :: "r"(dst), "l"(src), "r"(sz));
}
__device__ __forceinline__ void cp_async4u(unsigned dst, const float* src) {
    asm volatile("cp.async.ca.shared.global [%0], [%1], 4;\n"
                 :: "r"(dst), "l"(src));
}
__device__ __forceinline__ void cp_async16(unsigned dst, const void* src) {
    asm volatile("cp.async.cg.shared.global [%0], [%1], 16;\n"
                 :: "r"(dst), "l"(src));
}
__device__ __forceinline__ void cp_commit() {
    asm volatile("cp.async.commit_group;\n" ::: "memory");
}
__device__ __forceinline__ void cp_wait0() {
    asm volatile("cp.async.wait_group 0;\n" ::: "memory");
}

#define FMA2(d, a, b) \
    asm("fma.rn.f32x2 %0, %1, %2, %0;" : "+l"(d) : "l"(a), "l"(b))
#define PACK2(dst, v) \
    asm("mov.b64 %0, {%1, %1};" : "=l"(dst) : "f"(v))
#define UNPACK2(lo, hi, src) \
    asm("mov.b64 {%0, %1}, %2;" : "=f"(lo), "=f"(hi) : "l"(src))

__device__ __forceinline__ void fma2_row(u64* acc, float v,
                                         const ulonglong2& q0, const ulonglong2& q1,
                                         const ulonglong2& q2, const ulonglong2& q3) {
    u64 vv; PACK2(vv, v);
    FMA2(acc[0], vv, q0.x); FMA2(acc[1], vv, q0.y);
    FMA2(acc[2], vv, q1.x); FMA2(acc[3], vv, q1.y);
    FMA2(acc[4], vv, q2.x); FMA2(acc[5], vv, q2.y);
    FMA2(acc[6], vv, q3.x); FMA2(acc[7], vv, q3.y);
}

// mma.sync m16n8k16 bf16 (fp32 accumulate)
#define MMA_BF16(c, a0,a1,a2,a3, b0,b1) \
    asm volatile("mma.sync.aligned.m16n8k16.row.col.f32.bf16.bf16.f32 " \
        "{%0,%1,%2,%3}, {%4,%5,%6,%7}, {%8,%9}, {%0,%1,%2,%3};" \
        : "+f"(c[0]), "+f"(c[1]), "+f"(c[2]), "+f"(c[3]) \
        : "r"(a0), "r"(a1), "r"(a2), "r"(a3), "r"(b0), "r"(b1))

__device__ __forceinline__ u32t pk_bf16x2(float a, float b) {
    __nv_bfloat162 t = __floats2bfloat162_rn(a, b);
    return *(u32t*)&t;
}

// ---------------------------------------------------------------------------
// Border zero kernels
// ---------------------------------------------------------------------------
__global__ void zero_borders(float* buf) {
    float* p = buf + (size_t)blockIdx.x * PCH;
    int tid = threadIdx.x;
    for (int i = tid; i < PROW; i += 256) p[i] = 0.f;
    p[(tid + 1) * PROW] = 0.f;
}

__global__ void zb_nhwc(__nv_bfloat16* gh) {
    const int b = blockIdx.x;
    u32t* h = (u32t*)(gh + (size_t)b*NCH);
    const int tid = threadIdx.x;
    for (int i = tid; i < NR*64; i += 256) {
        h[i] = 0u;
        h[(size_t)257*NR*64 + i] = 0u;
    }
    for (int i = tid; i < 256*64; i += 256) {
        int r = 1 + i/64, c2 = i%64;
        h[((size_t)r*NR + 0)*64 + c2] = 0u;
        h[((size_t)r*NR + 257)*64 + c2] = 0u;
    }
}

// ---------------------------------------------------------------------------
// conv2_s weight pre-pack (bf16 single precision — output is alpha-damped)
// ---------------------------------------------------------------------------
__global__ void wprep(const float* __restrict__ wgt, u32t* __restrict__ wph) {
    int i = blockIdx.x*256 + threadIdx.x;
    if (i >= 8*9*128*8) return;
    int q = i & 7;
    int r = i >> 3;
    int co = r & 127; r >>= 7;
    int tap = r % 9;
    int cc  = r / 9;
    int cin = cc*16 + 2*q;
    wph[i] = pk_bf16x2(wgt[co*1152 + cin*9 + tap],
                       wgt[co*1152 + (cin+1)*9 + tap]);
}

// ---------------------------------------------------------------------------
// Stride-1 fused conv3x3 + bias + SiLU (CIN=3).
// OUTMODE: 2 = padded parity fp32; 3 = NHWC-padded bf16.
// ---------------------------------------------------------------------------
template<int CIN, int OUTC, int OUTMODE>
__global__ void __launch_bounds__(256, 2) convfast(
    const float* __restrict__ in, const float* __restrict__ wgt,
    const float* __restrict__ bias, float* __restrict__ out,
    __nv_bfloat16* __restrict__ outH, int Hin, int Win)
{
    constexpr int COG  = 16;
    constexpr int ITX  = 34;
    constexpr int SRS  = 36;
    constexpr int ELEMS = ITX * ITX;
    constexpr int NIT  = (ELEMS + 255) / 256;
    constexpr int PLANE = ITX * SRS;

    extern __shared__ float sIn[];
    __shared__ float sW[2][COG*9 + 8];
    __shared__ int2 tTab[NIT*256];

    const int tid = threadIdx.x;
    const int tx = tid & 7, ty = tid >> 3;
    const int groups = OUTC / COG;
    const int b = blockIdx.z / groups;
    const int cbase = (blockIdx.z % groups) * COG;
    const int X0 = blockIdx.x * 32, Y0 = blockIdx.y * 32;
    const int iy0 = Y0 - 1, ix0 = X0 - 1;
    const size_t HW = (size_t)Hin * Win;
    const float* inb = in + (size_t)b * CIN * HW;

    const int wc = tid / 9, wtap = tid - wc*9;

#pragma unroll
    for (int k = 0; k < NIT; k++) {
        int f = k*256 + tid;
        int sof = -1, gof = -1;
        if (f < ELEMS) {
            int r = f / ITX, c = f - r*ITX;
            int ih = iy0 + r, iw = ix0 + c;
            sof = r*SRS + c;
            gof = ((unsigned)ih < (unsigned)Hin && (unsigned)iw < (unsigned)Win)
                  ? (ih*Win + iw) : -1;
        }
        tTab[k*256 + tid] = make_int2(gof, sof);
    }

    const unsigned sb0 = (unsigned)__cvta_generic_to_shared(sIn);
    auto stage = [&](int buf, int cin) {
        const float* ic = inb + (size_t)cin * HW;
        const unsigned sb = sb0 + (unsigned)buf * (PLANE*4);
#pragma unroll
        for (int k = 0; k < NIT; k++) {
            int2 t = tTab[k*256 + tid];
            if (t.y >= 0)
                cp_async4(sb + (unsigned)t.y*4, ic + (t.x < 0 ? 0 : t.x),
                          t.x < 0 ? 0 : 4);
        }
        if (tid < COG*9) {
            unsigned dst = (unsigned)__cvta_generic_to_shared(
                               &sW[buf][wtap*COG + wc]);
            cp_async4u(dst, wgt + ((size_t)(cbase+wc)*CIN + cin)*9 + wtap);
        }
    };

    stage(0, 0);
    cp_commit();
    cp_wait0();
    __syncthreads();

    u64 acc2[4][8];
#pragma unroll
    for (int j = 0; j < 4; j++)
#pragma unroll
        for (int p = 0; p < 8; p++) acc2[j][p] = 0ull;

    for (int cin = 0; cin < CIN; cin++) {
        const int cur = cin & 1;
        if (cin + 1 < CIN) { stage(cur^1, cin+1); cp_commit(); }

        const float* sc  = sIn + cur*PLANE;
        const float* swp = sW[cur];
#pragma unroll
        for (int dy = 0; dy < 3; dy++) {
            const float* rp = sc + (ty + dy)*SRS + tx*4;
            float4 A = *(const float4*)rp;
            float2 Bv = *(const float2*)(rp + 4);
            float iv6[6] = {A.x, A.y, A.z, A.w, Bv.x, Bv.y};
#pragma unroll
            for (int dx = 0; dx < 3; dx++) {
                const ulonglong2* wq = (const ulonglong2*)(swp + (dy*3+dx)*COG);
                ulonglong2 q0 = wq[0], q1 = wq[1], q2 = wq[2], q3 = wq[3];
#pragma unroll
                for (int j = 0; j < 4; j++)
                    fma2_row(acc2[j], iv6[j+dx], q0, q1, q2, q3);
            }
        }
        if (cin + 1 < CIN) cp_wait0();
        __syncthreads();
    }

    float bv[COG];
#pragma unroll
    for (int c = 0; c < COG; c++) bv[c] = __ldg(bias + cbase + c);

    const int oy = Y0 + ty;
    const int x0 = X0 + tx*4;
    if (OUTMODE == 3) {
#pragma unroll
        for (int j = 0; j < 4; j++) {
            u32t hp[8];
#pragma unroll
            for (int p = 0; p < 8; p++) {
                float flo, fhi;
                UNPACK2(flo, fhi, acc2[j][p]);
                float v0 = flo + bv[2*p];     v0 = v0 / (1.f + __expf(-v0));
                float v1 = fhi + bv[2*p+1];   v1 = v1 / (1.f + __expf(-v1));
                hp[p] = pk_bf16x2(v0, v1);
            }
            size_t base = (((size_t)b*NR + (oy+1))*NR + (x0+j+1))*128 + cbase;
            uint4* dh = (uint4*)(outH + base);
            dh[0] = make_uint4(hp[0],hp[1],hp[2],hp[3]);
            dh[1] = make_uint4(hp[4],hp[5],hp[6],hp[7]);
        }
    } else {
#pragma unroll
        for (int c = 0; c < COG; c++) {
            float vv[4];
#pragma unroll
            for (int j = 0; j < 4; j++) {
                float flo, fhi;
                UNPACK2(flo, fhi, acc2[j][c >> 1]);
                float v = ((c & 1) ? fhi : flo) + bv[c];
                vv[j] = v / (1.f + __expf(-v));
            }
            size_t rowbase = ((size_t)(b*OUTC + cbase + c)*258 + (oy+1))*PROW;
            *(float2*)(out + rowbase + 132 + (x0>>1)) = make_float2(vv[0], vv[2]);
            out[rowbase + (x0>>1) + 1] = vv[1];
            out[rowbase + (x0>>1) + 2] = vv[3];
        }
    }
}

// ---------------------------------------------------------------------------
// Stride-2 conv (fp32 FFMA2 path) — conv2_n (16->16) only.
// ---------------------------------------------------------------------------
template<int CIN, int OUTC>
__global__ void __launch_bounds__(256, 2) convfast2(
    const float* __restrict__ in, const float* __restrict__ wgt,
    const float* __restrict__ bias, float* __restrict__ out)
{
    constexpr int COG  = 16;
    constexpr int SRS  = 72;
    constexpr int ODD  = 36;
    constexpr int PLANE = 65*SRS;
    constexpr int NOPS = 65*18;

    extern __shared__ float sIn[];
    __shared__ float sW[2][COG*9 + 8];

    const int tid = threadIdx.x;
    const int tx = tid & 7, ty = tid >> 3;
    const int groups = OUTC / COG;
    const int b = blockIdx.z / groups;
    const int cbase = (blockIdx.z % groups) * COG;
    const int X0 = blockIdx.x * 32, Y0 = blockIdx.y * 32;
    const float* inb = in + (size_t)b * CIN * PCH;

    const int wc = tid / 9, wtap = tid - wc*9;

    int gofs[5]; int sofs[5];
#pragma unroll
    for (int k = 0; k < 5; k++) {
        int id = k*256 + tid;
        if (id < NOPS) {
            int row = id / 18;
            int rem = id - row*18;
            int seg = rem / 9;
            int q   = rem - seg*9;
            gofs[k] = (2*Y0 + row)*PROW + seg*132 + X0 + q*4;
            sofs[k] = (row*SRS + seg*ODD + q*4) * 4;
        } else { gofs[k] = 0; sofs[k] = -1; }
    }

    const unsigned sb0 = (unsigned)__cvta_generic_to_shared(sIn);
    auto stage = [&](int buf, int cin) {
        const float* ic = inb + (size_t)cin * PCH;
        const unsigned sb = sb0 + (unsigned)buf * (PLANE*4);
#pragma unroll
        for (int k = 0; k < 5; k++)
            if (sofs[k] >= 0) cp_async16(sb + (unsigned)sofs[k], ic + gofs[k]);
        if (tid < COG*9) {
            unsigned dst = (unsigned)__cvta_generic_to_shared(
                               &sW[buf][wtap*COG + wc]);
            cp_async4u(dst, wgt + ((size_t)(cbase+wc)*CIN + cin)*9 + wtap);
        }
    };

    stage(0, 0);
    cp_commit();
    cp_wait0();
    __syncthreads();

    u64 acc2[4][8];
#pragma unroll
    for (int j = 0; j < 4; j++)
#pragma unroll
        for (int p = 0; p < 8; p++) acc2[j][p] = 0ull;

    for (int cin = 0; cin < CIN; cin++) {
        const int cur = cin & 1;
        if (cin + 1 < CIN) { stage(cur^1, cin+1); cp_commit(); }

        const float* sc  = sIn + cur*PLANE;
        const float* swp = sW[cur];
#pragma unroll
        for (int dy = 0; dy < 3; dy++) {
            const float* rp = sc + (ty*2 + dy)*SRS;
            float4 E = *(const float4*)(rp + tx*4);
            float  e4 = rp[tx*4 + 4];
            float4 O = *(const float4*)(rp + ODD + tx*4);
            float V[3][4];
            V[0][0]=E.x; V[0][1]=E.y; V[0][2]=E.z; V[0][3]=E.w;
            V[1][0]=O.x; V[1][1]=O.y; V[1][2]=O.z; V[1][3]=O.w;
            V[2][0]=E.y; V[2][1]=E.z; V[2][2]=E.w; V[2][3]=e4;
#pragma unroll
            for (int dx = 0; dx < 3; dx++) {
                const ulonglong2* wq = (const ulonglong2*)(swp + (dy*3+dx)*COG);
                ulonglong2 q0 = wq[0], q1 = wq[1], q2 = wq[2], q3 = wq[3];
#pragma unroll
                for (int j = 0; j < 4; j++)
                    fma2_row(acc2[j], V[dx][j], q0, q1, q2, q3);
            }
        }
        if (cin + 1 < CIN) cp_wait0();
        __syncthreads();
    }

    float bv[COG];
#pragma unroll
    for (int c = 0; c < COG; c++) bv[c] = __ldg(bias + cbase + c);

    const int oy = Y0 + ty;
#pragma unroll
    for (int j = 0; j < 4; j++) {
        float vv[COG];
#pragma unroll
        for (int p = 0; p < 8; p++) {
            float flo, fhi;
            UNPACK2(flo, fhi, acc2[j][p]);
            float v0 = flo + bv[2*p],     v1 = fhi + bv[2*p+1];
            vv[2*p]   = v0 / (1.f + __expf(-v0));
            vv[2*p+1] = v1 / (1.f + __expf(-v1));
        }
        size_t t = ((size_t)b*H2 + oy)*W2 + X0 + tx*4 + j;
        float4* op = (float4*)(out + t*OUTC + cbase);
        op[0] = make_float4(vv[0],  vv[1],  vv[2],  vv[3]);
        op[1] = make_float4(vv[4],  vv[5],  vv[6],  vv[7]);
        op[2] = make_float4(vv[8],  vv[9],  vv[10], vv[11]);
        op[3] = make_float4(vv[12], vv[13], vv[14], vv[15]);
    }
}

// ---------------------------------------------------------------------------
// conv2_s token-GEMM (mma.sync m16n8k16 bf16, SINGLE pass — alpha-damped).
// Block: 128 tokens (one y row) x 128 co, 8 warps; warp = 16 tokens x 128 co.
// Double-buffered A+B chunks: staging overlapped with compute via cp.async.
// ---------------------------------------------------------------------------
#define APS 12
#define BPS 12
#define SA_U32 (3*258*APS)          // 9288 u32
#define SB_U32 (9*128*BPS)          // 13824 u32
#define C2_SMEM ((2*(SA_U32 + SB_U32))*4)   // 184896 B (2 pipeline buffers)

__global__ void __launch_bounds__(256, 1) conv2s_mma(
    const __nv_bfloat16* __restrict__ gh, const u32t* __restrict__ wph,
    const float* __restrict__ bias, float* __restrict__ out)
{
    extern __shared__ u32t sm32[];
    // buffer layout: [buf0: A | B][buf1: A | B]
    u32t* sA[2] = { sm32, sm32 + SA_U32 + SB_U32 };
    u32t* sB[2] = { sm32 + SA_U32, sm32 + 2*SA_U32 + SB_U32 };

    const int tid = threadIdx.x, lane = tid & 31, w = tid >> 5;
    const int y  = blockIdx.x;
    const int b  = blockIdx.y;

    float acc[16][4];
#pragma unroll
    for (int nt = 0; nt < 16; nt++)
#pragma unroll
        for (int r = 0; r < 4; r++) acc[nt][r] = 0.f;

    const int q = lane & 3;
    const int g = lane >> 2;
    const int mlow = 16*w + g;

    auto stage = [&](int buf, int cc) {
        const unsigned aB = (unsigned)__cvta_generic_to_shared(sA[buf]);
        const unsigned bB = (unsigned)__cvta_generic_to_shared(sB[buf]);
        // A: 774 positions x 2 halves = 1548 cp.async.16
        for (int i = tid; i < 1548; i += 256) {
            int pos = i >> 1; int half = i & 1;
            int dy = pos / 258, pl = pos - dy*258;
            size_t gofs = (((size_t)b*NR + (2*y + dy))*NR + pl)*128
                          + cc*16 + half*8;
            cp_async16(aB + (unsigned)(pos*APS*4 + half*16), gh + gofs);
        }
        // B: 1152 (tap,co) x 2 halves = 2304 cp.async.16
        for (int i = tid; i < 2304; i += 256) {
            int tc = i >> 1; int half = i & 1;
            cp_async16(bB + (unsigned)(tc*BPS*4 + half*16),
                       wph + (cc*1152 + tc)*8 + half*4);
        }
    };

    stage(0, 0);
    cp_commit();
    cp_wait0();
    __syncthreads();

    for (int cc = 0; cc < 8; cc++) {
        const int cur = cc & 1;
        if (cc + 1 < 8) { stage(cur^1, cc+1); cp_commit(); }

        const u32t* sAc = sA[cur];
        const u32t* sBc = sB[cur];
#pragma unroll
        for (int dy = 0; dy < 3; dy++)
#pragma unroll
        for (int dx = 0; dx < 3; dx++) {
            const int tap = dy*3 + dx;
            const int baseA = (dy*258 + 2*mlow + dx) * APS;
            const int baseA8 = baseA + 16*APS;            // token +8
            u32t a0 = sAc[baseA + q],      a2 = sAc[baseA + q + 4];
            u32t a1 = sAc[baseA8 + q],     a3 = sAc[baseA8 + q + 4];
#pragma unroll
            for (int nt = 0; nt < 16; nt++) {
                int co = 8*nt + g;
                int bb = (tap*128 + co) * BPS;
                u32t b0 = sBc[bb + q], b1 = sBc[bb + q + 4];
                MMA_BF16(acc[nt], a0, a1, a2, a3, b0, b1);
            }
        }
        if (cc + 1 < 8) { cp_wait0(); __syncthreads(); }
    }

    // ---- epilogue: bias + SiLU -> token-major g_ts
    size_t t1 = ((size_t)(b*H2 + y)*W2 + mlow) * 128;
    size_t t2 = t1 + (size_t)8*128;
#pragma unroll
    for (int nt = 0; nt < 16; nt++) {
        int co = 8*nt + 2*q;
        float bv0 = __ldg(bias + co), bv1 = __ldg(bias + co + 1);
        float v0 = acc[nt][0] + bv0; v0 = v0 / (1.f + __expf(-v0));
        float v1 = acc[nt][1] + bv1; v1 = v1 / (1.f + __expf(-v1));
        float v2 = acc[nt][2] + bv0; v2 = v2 / (1.f + __expf(-v2));
        float v3 = acc[nt][3] + bv1; v3 = v3 / (1.f + __expf(-v3));
        *(float2*)(out + t1 + co) = make_float2(v0, v1);
        *(float2*)(out + t2 + co) = make_float2(v2, v3);
    }
}

// ---------------------------------------------------------------------------
// Legacy conv (final tiny 3->3 decoder conv)
// ---------------------------------------------------------------------------
template<int CIN, int OUTC, int COG>
__global__ void __launch_bounds__(256) conv3x3(
    const float* __restrict__ in, const float* __restrict__ wgt,
    const float* __restrict__ bias, float* __restrict__ out,
    int Hin, int Win)
{
    constexpr int ITD = 18;
    __shared__ float sW[COG*CIN*9];
    __shared__ float sIn[ITD*ITD];

    const int tid = threadIdx.x;
    const int groups = OUTC / COG;
    const int b  = blockIdx.z / groups;
    const int cbase = (blockIdx.z % groups) * COG;

    for (int i = tid; i < COG*CIN*9; i += 256)
        sW[i] = wgt[(size_t)cbase*CIN*9 + i];

    const int ty = tid >> 4, tx = tid & 15;
    const int oy = blockIdx.y*16 + ty;
    const int ox = blockIdx.x*16 + tx;

    float acc[COG];
#pragma unroll
    for (int c = 0; c < COG; c++) acc[c] = 0.f;

    const float* inb = in + (size_t)b * CIN * Hin * Win;
    const int iy0 = blockIdx.y*16 - 1;
    const int ix0 = blockIdx.x*16 - 1;
    const int base = ty*ITD + tx;

    for (int cin = 0; cin < CIN; cin++) {
        __syncthreads();
        const float* ic = inb + (size_t)cin * Hin * Win;
        for (int i = tid; i < ITD*ITD; i += 256) {
            int r = i / ITD, cc = i - r*ITD;
            int ih = iy0 + r, iw = ix0 + cc;
            float v = 0.f;
            if ((unsigned)ih < (unsigned)Hin && (unsigned)iw < (unsigned)Win)
                v = ic[ih*Win + iw];
            sIn[i] = v;
        }
        __syncthreads();
        const float* wp = sW + cin*9;
#pragma unroll
        for (int dy = 0; dy < 3; dy++)
#pragma unroll
            for (int dx = 0; dx < 3; dx++) {
                float iv = sIn[base + dy*ITD + dx];
#pragma unroll
                for (int c = 0; c < COG; c++)
                    acc[c] += iv * wp[c*CIN*9 + dy*3 + dx];
            }
    }

#pragma unroll
    for (int c = 0; c < COG; c++) {
        float v = acc[c] + bias[cbase + c];
        v = v / (1.f + __expf(-v));
        out[(((size_t)b*OUTC + cbase + c)*Hin + oy)*Win + ox] = v;
    }
}

// ---------------------------------------------------------------------------
// Memcell pass 1: w = softmax(z @ K^T / 4) per token.
// ---------------------------------------------------------------------------
__global__ void __launch_bounds__(256) memcell_softmax(
    const float* __restrict__ z, const float* __restrict__ ck,
    float* __restrict__ wout)
{
    __shared__ float sK[Mm*Nn];
    const int tid = threadIdx.x;
    for (int i = tid; i < Mm*Nn; i += 256) sK[i] = ck[i];
    __syncthreads();

    const int t = blockIdx.x*256 + tid;
    const float4* zp = (const float4*)(z + (size_t)t*Nn);
    float4 z0 = zp[0], z1 = zp[1], z2 = zp[2], z3 = zp[3];

    float s[Mm];
    float mx = -1e30f;
#pragma unroll
    for (int m = 0; m < Mm; m++) {
        const float* k = sK + m*Nn;
        float d = z0.x*k[0] + z0.y*k[1] + z0.z*k[2] + z0.w*k[3]
                + z1.x*k[4] + z1.y*k[5] + z1.z*k[6] + z1.w*k[7]
                + z2.x*k[8] + z2.y*k[9] + z2.z*k[10]+ z2.w*k[11]
                + z3.x*k[12]+ z3.y*k[13]+ z3.z*k[14]+ z3.w*k[15];
        d *= 0.25f;
        s[m] = d;
        mx = fmaxf(mx, d);
    }
    float sum = 0.f;
#pragma unroll
    for (int m = 0; m < Mm; m++) { s[m] = __expf(s[m]-mx); sum += s[m]; }
    float inv = 1.f / sum;
    float4* wo = (float4*)(wout + (size_t)t*Mm);
#pragma unroll
    for (int j = 0; j < Mm/4; j++) {
        float4 v; v.x = s[4*j]*inv; v.y = s[4*j+1]*inv;
        v.z = s[4*j+2]*inv; v.w = s[4*j+3]*inv;
        wo[j] = v;
    }
}

// ---------------------------------------------------------------------------
// Memcell pass 2: block partials of [G | U].
// ---------------------------------------------------------------------------
__global__ void __launch_bounds__(256) memcell_outer(
    const float* __restrict__ wmat, const float* __restrict__ ts,
    float* __restrict__ part)
{
    __shared__ float sv[8*160];
    const int tid = threadIdx.x;
    const int ti = tid >> 5;
    const int tj = tid & 31;
    float acc[4][5];
#pragma unroll
    for (int a = 0; a < 4; a++)
#pragma unroll
        for (int qq = 0; qq < 5; qq++) acc[a][qq] = 0.f;

    const int tokb = blockIdx.x * 128;
    for (int ch = 0; ch < 128; ch += 8) {
        __syncthreads();
#pragma unroll
        for (int l = 0; l < 5; l++) {
            int idx = l*256 + tid;
            int tk = idx / 160, f = idx - tk*160;
            int t = tokb + ch + tk;
            sv[tk*160 + f] = (f < 32) ? wmat[(size_t)t*32 + f]
                                      : ts[(size_t)t*128 + (f-32)];
        }
        __syncthreads();
#pragma unroll
        for (int tk = 0; tk < 8; tk++) {
            float wi[4], vj[5];
#pragma unroll
            for (int a = 0; a < 4; a++) wi[a] = sv[tk*160 + ti*4 + a];
#pragma unroll
            for (int qq = 0; qq < 5; qq++) vj[qq] = sv[tk*160 + tj*5 + qq];
#pragma unroll
            for (int a = 0; a < 4; a++)
#pragma unroll
                for (int qq = 0; qq < 5; qq++) acc[a][qq] += wi[a]*vj[qq];
        }
    }
    float* pp = part + (size_t)blockIdx.x * 5120;
#pragma unroll
    for (int a = 0; a < 4; a++)
#pragma unroll
        for (int qq = 0; qq < 5; qq++)
            pp[(ti*4+a)*160 + tj*5 + qq] = acc[a][qq];
}

__global__ void __launch_bounds__(256) reduce_partials(
    const float* __restrict__ part, float* __restrict__ gu)
{
    int cell = blockIdx.x*256 + threadIdx.x;
    float s = 0.f;
#pragma unroll 8
    for (int p = 0; p < 1024; p++) s += part[(size_t)p*5120 + cell];
    gu[cell] = s;
}

__global__ void __launch_bounds__(256) cell_update(
    const float* __restrict__ gu, const float* __restrict__ cv,
    float* __restrict__ vnew)
{
    __shared__ float sG[Mm*Mm];
    __shared__ float sV[Mm*Ss];
    const int tid = threadIdx.x;
    for (int i = tid; i < Mm*Mm; i += 256) {
        int m = i >> 5, j = i & 31;
        sG[i] = gu[m*160 + j];
    }
    for (int i = tid; i < Mm*Ss; i += 256) sV[i] = cv[i];
    __syncthreads();
    for (int k = 0; k < 16; k++) {
        int cell = k*256 + tid;
        int m = cell >> 7, s0 = cell & 127;
        float d = gu[m*160 + 32 + s0];
#pragma unroll
        for (int mp = 0; mp < Mm; mp++) d -= sG[m*32 + mp] * sV[mp*128 + s0];
        vnew[cell] = sV[cell] + ALPHA * d;
    }
}

// ---------------------------------------------------------------------------
// Memcell pass 3: t_read = W @ cell_v_new -> NCHW [B,S,H2,W2].
// ---------------------------------------------------------------------------
__global__ void __launch_bounds__(256) memcell_read(
    const float* __restrict__ wmat, const float* __restrict__ vnew,
    float* __restrict__ d0m)
{
    __shared__ float sV[Mm*Ss];
    __shared__ float sW[64*33];
    const int tid = threadIdx.x;
    for (int i = tid; i < Mm*Ss; i += 256) sV[i] = vnew[i];
    const int tbase = blockIdx.x * 64;
    for (int i = tid; i < 64*32; i += 256) {
        int tk = i >> 5, m = i & 31;
        sW[tk*33 + m] = wmat[(size_t)(tbase + tk)*32 + m];
    }
    __syncthreads();

    const int lane = tid & 31, wid = tid >> 5;
    const int cb = wid * 16;
    float a0[16], a1[16];
#pragma unroll
    for (int c = 0; c < 16; c++) { a0[c] = 0.f; a1[c] = 0.f; }

    const float* w0 = sW + lane*33;
    const float* w1 = sW + (lane + 32)*33;
#pragma unroll 4
    for (int m = 0; m < Mm; m++) {
        float x0 = w0[m], x1 = w1[m];
        const float4* vv = (const float4*)(sV + m*128 + cb);
#pragma unroll
        for (int qq = 0; qq < 4; qq++) {
            float4 v = vv[qq];
            a0[qq*4+0] += x0*v.x; a0[qq*4+1] += x0*v.y;
            a0[qq*4+2] += x0*v.z; a0[qq*4+3] += x0*v.w;
            a1[qq*4+0] += x1*v.x; a1[qq*4+1] += x1*v.y;
            a1[qq*4+2] += x1*v.z; a1[qq*4+3] += x1*v.w;
        }
    }
    const int b = tbase >> 14;
    const int rem = tbase & 16383;
    const int h = rem >> 7;
    const int wcp = rem & 127;
    size_t obase = ((size_t)b*Ss)*((size_t)H2*W2) + (size_t)h*W2 + wcp;
#pragma unroll
    for (int c = 0; c < 16; c++) {
        size_t o = obase + (size_t)(cb + c)*(H2*W2);
        d0m[o + lane]      = a0[c];
        d0m[o + 32 + lane] = a1[c];
    }
}

// ---------------------------------------------------------------------------
// ConvTranspose2d(128->3, k4, s2, p1) + bias + SiLU.  32x32 output tiles.
// ---------------------------------------------------------------------------
__global__ void __launch_bounds__(256) deconv_kernel(
    const float* __restrict__ in, const float* __restrict__ dw,
    const float* __restrict__ db, float* __restrict__ out)
{
    __shared__ float sWd[4*128*12];
    __shared__ float sIn[16*324];
    const int tid = threadIdx.x;
    for (int i = tid; i < 4*128*12; i += 256) {
        int p = i / 1536, rem = i - p*1536;
        int cin = rem / 12, rr = rem - cin*12;
        int o = rr >> 2, k = rr & 3;
        int py = p >> 1, px = p & 1;
        int ky = py + 2*(k >> 1), kx = px + 2*(k & 1);
        sWd[i] = dw[cin*48 + o*16 + ky*4 + kx];
    }

    const int b  = blockIdx.z;
    const int Y0 = blockIdx.y*32, X0 = blockIdx.x*32;
    const int ty = tid >> 4, tx = tid & 15;
    const int y0 = Y0 + ty, x0 = X0 + tx;
    const int hb = (Y0 >> 1) - 1, wb = (X0 >> 1) - 1;

    const int py = (y0 + 1) & 1, px = (x0 + 1) & 1;
    const int hs0 = ((y0 + 1 - py) >> 1) - hb;
    const int ws0 = ((x0 + 1 - px) >> 1) - wb;

    const float* wp = sWd + (py*2 + px)*1536;
    float acc[2][2][3];
#pragma unroll
    for (int a = 0; a < 2; a++)
#pragma unroll
        for (int e = 0; e < 2; e++)
#pragma unroll
            for (int o = 0; o < 3; o++) acc[a][e][o] = 0.f;

    const float* inb = in + (size_t)b * Ss * H2 * W2;

    for (int c0 = 0; c0 < Ss; c0 += 16) {
        __syncthreads();
        for (int i = tid; i < 16*324; i += 256) {
            int c = i / 324, rr = i - c*324;
            int r = rr / 18, cc = rr - r*18;
            int h = hb + r, w = wb + cc;
            float v = 0.f;
            if ((unsigned)h < (unsigned)H2 && (unsigned)w < (unsigned)W2)
                v = inb[((size_t)(c0 + c)*H2 + h)*W2 + w];
            sIn[i] = v;
        }
        __syncthreads();
#pragma unroll
        for (int c = 0; c < 16; c++) {
            const float* sc = sIn + c*324;
            const float4* w4 = (const float4*)(wp + (c0 + c)*12);
            float4 Wa = w4[0], Wb = w4[1], Wc = w4[2];
#pragma unroll
            for (int a = 0; a < 2; a++)
#pragma unroll
                for (int e = 0; e < 2; e++) {
                    int hh = hs0 + 8*a, ww = ws0 + 8*e;
                    float i00 = sc[hh*18 + ww];
                    float i01 = sc[hh*18 + ww - 1];
                    float i10 = sc[(hh-1)*18 + ww];
                    float i11 = sc[(hh-1)*18 + ww - 1];
                    acc[a][e][0] += i00*Wa.x + i01*Wa.y + i10*Wa.z + i11*Wa.w;
                    acc[a][e][1] += i00*Wb.x + i01*Wb.y + i10*Wb.z + i11*Wb.w;
                    acc[a][e][2] += i00*Wc.x + i01*Wc.y + i10*Wc.z + i11*Wc.w;
                }
        }
    }
#pragma unroll
    for (int a = 0; a < 2; a++)
#pragma unroll
        for (int e = 0; e < 2; e++)
#pragma unroll
            for (int o = 0; o < 3; o++) {
                float v = acc[a][e][o] + db[o];
                v = v / (1.f + __expf(-v));
                out[(((size_t)b*3 + o)*HIN + y0 + 16*a)*WIN + x0 + 16*e] = v;
            }
}

// ---------------------------------------------------------------------------
// Launch sequence
// ---------------------------------------------------------------------------
extern "C" void kernel_launch(void* const* d_in, const int* in_sizes, int n_in,
                              void* d_out, int out_size)
{
    const float* x      = (const float*)d_in[0];
    const float* e0n_w1 = (const float*)d_in[1];
    const float* e0n_b1 = (const float*)d_in[2];
    const float* e0n_w2 = (const float*)d_in[3];
    const float* e0n_b2 = (const float*)d_in[4];
    const float* e0s_w1 = (const float*)d_in[5];
    const float* e0s_b1 = (const float*)d_in[6];
    const float* e0s_w2 = (const float*)d_in[7];
    const float* e0s_b2 = (const float*)d_in[8];
    const float* d0_dw  = (const float*)d_in[9];
    const float* d0_db  = (const float*)d_in[10];
    const float* d0_cw  = (const float*)d_in[11];
    const float* d0_cb  = (const float*)d_in[12];
    const float* cell_k = (const float*)d_in[13];
    const float* cell_v = (const float*)d_in[14];
    float* outp = (float*)d_out;

    void *p_a1n, *p_hi, *p_wph, *p_z, *p_ts, *p_w,
         *p_part, *p_gu, *p_vnew, *p_d0m, *p_dec;
    cudaGetSymbolAddress(&p_a1n, g_a1n);
    cudaGetSymbolAddress(&p_hi,  g_hi);
    cudaGetSymbolAddress(&p_wph, g_wph);
    cudaGetSymbolAddress(&p_z,   g_z);
    cudaGetSymbolAddress(&p_ts,  g_ts);
    cudaGetSymbolAddress(&p_w,   g_w);
    cudaGetSymbolAddress(&p_part,g_part);
    cudaGetSymbolAddress(&p_gu,  g_gu);
    cudaGetSymbolAddress(&p_vnew,g_vnew);
    cudaGetSymbolAddress(&p_d0m, g_d0m);
    cudaGetSymbolAddress(&p_dec, g_dec);

    const int dsm_s1 = 2 * 34 * 36 * 4;   //  9792 B
    const int dsm_s2 = 2 * 65 * 72 * 4;   // 37440 B

    cudaFuncSetAttribute((const void*)convfast<3,16,2>,
                         cudaFuncAttributeMaxDynamicSharedMemorySize, dsm_s1);
    cudaFuncSetAttribute((const void*)convfast<3,128,3>,
                         cudaFuncAttributeMaxDynamicSharedMemorySize, dsm_s1);
    cudaFuncSetAttribute((const void*)convfast2<16,16>,
                         cudaFuncAttributeMaxDynamicSharedMemorySize, dsm_s2);
    cudaFuncSetAttribute((const void*)conv2s_mma,
                         cudaFuncAttributeMaxDynamicSharedMemorySize, C2_SMEM);

    // Prep: borders + packed weights
    zero_borders<<<Bb*Nn, 256>>>((float*)p_a1n);
    zb_nhwc<<<Bb, 256>>>((__nv_bfloat16*)p_hi);
    wprep<<<288, 256>>>(e0s_w2, (u32t*)p_wph);

    // Encoders
    convfast<3,16,2><<<dim3(8,8,Bb),256,dsm_s1>>>(
        x, e0n_w1, e0n_b1, (float*)p_a1n, nullptr, HIN, WIN);
    convfast<3,128,3><<<dim3(8,8,Bb*8),256,dsm_s1>>>(
        x, e0s_w1, e0s_b1, nullptr, (__nv_bfloat16*)p_hi, HIN, WIN);
    convfast2<16,16><<<dim3(4,4,Bb),256,dsm_s2>>>(
        (const float*)p_a1n, e0n_w2, e0n_b2, (float*)p_z);
    conv2s_mma<<<dim3(128,Bb),256,C2_SMEM>>>(
        (const __nv_bfloat16*)p_hi, (const u32t*)p_wph, e0s_b2, (float*)p_ts);

    // Memcell
    memcell_softmax<<<Tt/256,256>>>((const float*)p_z, cell_k, (float*)p_w);
    memcell_outer<<<1024,256>>>((const float*)p_w, (const float*)p_ts, (float*)p_part);
    reduce_partials<<<20,256>>>((const float*)p_part, (float*)p_gu);
    cell_update<<<1,256>>>((const float*)p_gu, cell_v, (float*)p_vnew);
    memcell_read<<<Tt/64,256>>>((const float*)p_w, (const float*)p_vnew, (float*)p_d0m);

    // Decoder
    deconv_kernel<<<dim3(8,8,Bb),256>>>(
        (const float*)p_d0m, d0_dw, d0_db, (float*)p_dec);
    conv3x3<3,3,3><<<dim3(16,16,Bb),256>>>(
        (const float*)p_dec, d0_cw, d0_cb, outp, HIN, WIN);
}

// round 16
// speedup vs baseline: 4.1919x; 1.0211x over previous
#include <cuda_runtime.h>
#include <cuda_bf16.h>
#include <cstdint>

// ---------------------------------------------------------------------------
// Problem constants
// ---------------------------------------------------------------------------
#define Bb   8
#define HIN  256
#define WIN  256
#define H2   128
#define W2   128
#define Nn   16
#define Mm   32
#define Ss   128
#define Tt   (Bb*H2*W2)          // 131072 tokens
#define ALPHA 1e-6f

// Padded parity-split activation layout (fp32 path, conv1_n -> conv2_n):
#define PROW 264
#define PCH  (258*PROW)

// NHWC-padded bf16 layout for conv1_s output (rows/cols padded by 1):
#define NR   258
#define NCH  ((size_t)NR*NR*128)

typedef unsigned long long u64;
typedef unsigned int u32t;

// ---------------------------------------------------------------------------
// Scratch buffers (static device globals; no cudaMalloc allowed)
// ---------------------------------------------------------------------------
__device__ float g_a1n [(size_t)Bb*Nn*PCH];        // padded silu(conv1_n) fp32
__device__ __nv_bfloat16 g_hi [(size_t)Bb*NCH];    // silu(conv1_s) bf16
__device__ u32t  g_wph[8*9*128*8];                 // packed conv2_s weights bf16
__device__ u32t  g_wp1[128*16];                    // packed conv1_s weights bf16
__device__ float g_z   [(size_t)Tt*Nn];
__device__ float g_ts  [(size_t)Tt*Ss];
__device__ float g_w   [(size_t)Tt*Mm];
__device__ float g_part[(size_t)1024*32*160];
__device__ float g_gu  [32*160];
__device__ float g_vnew[Mm*Ss];
__device__ float g_d0m [(size_t)Bb*Ss*H2*W2];
__device__ float g_dec [(size_t)Bb*3*HIN*WIN];

// ---------------------------------------------------------------------------
// cp.async + f32x2 helpers
// ---------------------------------------------------------------------------
__device__ __forceinline__ void cp_async4(unsigned dst, const float* src, int sz) {
    asm volatile("cp.async.ca.shared.global [%0], [%1], 4, %2;\n"
                 :: "r"(dst), "l"(src), "r"(sz));
}
__device__ __forceinline__ void cp_async4u(unsigned dst, const float* src) {
    asm volatile("cp.async.ca.shared.global [%0], [%1], 4;\n"
                 :: "r"(dst), "l"(src));
}
__device__ __forceinline__ void cp_async16(unsigned dst, const void* src) {
    asm volatile("cp.async.cg.shared.global [%0], [%1], 16;\n"
                 :: "r"(dst), "l"(src));
}
__device__ __forceinline__ void cp_commit() {
    asm volatile("cp.async.commit_group;\n" ::: "memory");
}
__device__ __forceinline__ void cp_wait0() {
    asm volatile("cp.async.wait_group 0;\n" ::: "memory");
}

#define FMA2(d, a, b) \
    asm("fma.rn.f32x2 %0, %1, %2, %0;" : "+l"(d) : "l"(a), "l"(b))
#define PACK2(dst, v) \
    asm("mov.b64 %0, {%1, %1};" : "=l"(dst) : "f"(v))
#define UNPACK2(lo, hi, src) \
    asm("mov.b64 {%0, %1}, %2;" : "=f"(lo), "=f"(hi) : "l"(src))

__device__ __forceinline__ void fma2_row(u64* acc, float v,
                                         const ulonglong2& q0, const ulonglong2& q1,
                                         const ulonglong2& q2, const ulonglong2& q3) {
    u64 vv; PACK2(vv, v);
    FMA2(acc[0], vv, q0.x); FMA2(acc[1], vv, q0.y);
    FMA2(acc[2], vv, q1.x); FMA2(acc[3], vv, q1.y);
    FMA2(acc[4], vv, q2.x); FMA2(acc[5], vv, q2.y);
    FMA2(acc[6], vv, q3.x); FMA2(acc[7], vv, q3.y);
}

// mma.sync m16n8k16 bf16 (fp32 accumulate)
#define MMA_BF16(c, a0,a1,a2,a3, b0,b1) \
    asm volatile("mma.sync.aligned.m16n8k16.row.col.f32.bf16.bf16.f32 " \
        "{%0,%1,%2,%3}, {%4,%5,%6,%7}, {%8,%9}, {%0,%1,%2,%3};" \
        : "+f"(c[0]), "+f"(c[1]), "+f"(c[2]), "+f"(c[3]) \
        : "r"(a0), "r"(a1), "r"(a2), "r"(a3), "r"(b0), "r"(b1))

__device__ __forceinline__ u32t pk_bf16x2(float a, float b) {
    __nv_bfloat162 t = __floats2bfloat162_rn(a, b);
    return *(u32t*)&t;
}

// ---------------------------------------------------------------------------
// Border zero kernels
// ---------------------------------------------------------------------------
__global__ void zero_borders(float* buf) {
    float* p = buf + (size_t)blockIdx.x * PCH;
    int tid = threadIdx.x;
    for (int i = tid; i < PROW; i += 256) p[i] = 0.f;
    p[(tid + 1) * PROW] = 0.f;
}

__global__ void zb_nhwc(__nv_bfloat16* gh) {
    const int b = blockIdx.x;
    u32t* h = (u32t*)(gh + (size_t)b*NCH);
    const int tid = threadIdx.x;
    for (int i = tid; i < NR*64; i += 256) {
        h[i] = 0u;
        h[(size_t)257*NR*64 + i] = 0u;
    }
    for (int i = tid; i < 256*64; i += 256) {
        int r = 1 + i/64, c2 = i%64;
        h[((size_t)r*NR + 0)*64 + c2] = 0u;
        h[((size_t)r*NR + 257)*64 + c2] = 0u;
    }
}

// ---------------------------------------------------------------------------
// conv2_s weight pre-pack (bf16 — output is alpha-damped)
// ---------------------------------------------------------------------------
__global__ void wprep(const float* __restrict__ wgt, u32t* __restrict__ wph) {
    int i = blockIdx.x*256 + threadIdx.x;
    if (i >= 8*9*128*8) return;
    int q = i & 7;
    int r = i >> 3;
    int co = r & 127; r >>= 7;
    int tap = r % 9;
    int cc  = r / 9;
    int cin = cc*16 + 2*q;
    wph[i] = pk_bf16x2(wgt[co*1152 + cin*9 + tap],
                       wgt[co*1152 + (cin+1)*9 + tap]);
}

// conv1_s weight pre-pack: [co][k2], k = cin*9+tap (27 real, pad to 32).
__global__ void wprep1(const float* __restrict__ wgt, u32t* __restrict__ wp1) {
    int i = blockIdx.x*256 + threadIdx.x;
    if (i >= 128*16) return;
    int k2 = i & 15, co = i >> 4;
    int k0 = 2*k2, k1 = k0 + 1;
    float v0 = (k0 < 27) ? wgt[co*27 + k0] : 0.f;
    float v1 = (k1 < 27) ? wgt[co*27 + k1] : 0.f;
    wp1[i] = pk_bf16x2(v0, v1);
}

// ---------------------------------------------------------------------------
// conv1_s as bf16 token-GEMM (alpha-damped branch).
// Block: 128 pixels (half a row) x 128 co; 8 warps, warp = 16 tokens.
// K = 27 (cin*9+tap) padded to 32 -> 2 k-iters of m16n8k16.
// Output: silu -> bf16 NHWC-padded g_hi.
// ---------------------------------------------------------------------------
#define SAS 17     // sA token-stride in u32 (bank padded)
#define SBS 17     // sB co-stride in u32
__global__ void __launch_bounds__(256) conv1s_mma(
    const float* __restrict__ x, const u32t* __restrict__ wp1,
    const float* __restrict__ bias, __nv_bfloat16* __restrict__ outH)
{
    __shared__ float sX[3][3][132];      // [cin][dy][col], col = ix-(x0-1), 0..129
    __shared__ u32t sA[128*SAS];
    __shared__ u32t sB[128*SBS];

    const int tid = threadIdx.x, lane = tid & 31, w = tid >> 5;
    const int x0 = blockIdx.x * 128;
    const int y  = blockIdx.y;
    const int b  = blockIdx.z;

    // stage B (2048 u32)
    for (int i = tid; i < 2048; i += 256)
        sB[(i >> 4)*SBS + (i & 15)] = wp1[i];

    // stage X window: 3 cins x 3 rows x 130 cols (zero padded)
    for (int i = tid; i < 3*3*132; i += 256) {
        int cin = i / 396, r = (i / 132) % 3, c = i % 132;
        int iy = y + r - 1, ix = x0 + c - 1;
        float v = 0.f;
        if (c < 130 && (unsigned)iy < 256u && (unsigned)ix < 256u)
            v = x[(((size_t)b*3 + cin)*256 + iy)*256 + ix];
        sX[cin][r][c] = v;
    }
    __syncthreads();

    // build im2col A panel: 128 tokens x 16 u32 (k = cin*9 + dy*3 + dx)
    for (int i = tid; i < 2048; i += 256) {
        int tok = i >> 4, k2 = i & 15;
        int k0 = 2*k2, k1 = k0 + 1;
        float v0 = (k0 < 27) ? sX[k0/9][(k0%9)/3][tok + (k0%3)] : 0.f;
        float v1 = (k1 < 27) ? sX[k1/9][(k1%9)/3][tok + (k1%3)] : 0.f;
        sA[tok*SAS + k2] = pk_bf16x2(v0, v1);
    }
    __syncthreads();

    float acc[16][4];
#pragma unroll
    for (int nt = 0; nt < 16; nt++)
#pragma unroll
        for (int r = 0; r < 4; r++) acc[nt][r] = 0.f;

    const int q = lane & 3;
    const int g = lane >> 2;
    const int tok0 = 16*w + g;

#pragma unroll
    for (int kit = 0; kit < 2; kit++) {
        u32t a0 = sA[tok0*SAS + kit*8 + q];
        u32t a2 = sA[tok0*SAS + kit*8 + q + 4];
        u32t a1 = sA[(tok0+8)*SAS + kit*8 + q];
        u32t a3 = sA[(tok0+8)*SAS + kit*8 + q + 4];
#pragma unroll
        for (int nt = 0; nt < 16; nt++) {
            int co = 8*nt + g;
            u32t b0 = sB[co*SBS + kit*8 + q];
            u32t b1 = sB[co*SBS + kit*8 + q + 4];
            MMA_BF16(acc[nt], a0, a1, a2, a3, b0, b1);
        }
    }

    // epilogue: bias + SiLU -> bf16 NHWC (row y+1, col x+1 padded)
    size_t p1 = (((size_t)b*NR + (y+1))*NR + (x0 + tok0 + 1))*128;
    size_t p2 = p1 + (size_t)8*128;
#pragma unroll
    for (int nt = 0; nt < 16; nt++) {
        int co = 8*nt + 2*q;
        float bv0 = __ldg(bias + co), bv1 = __ldg(bias + co + 1);
        float v0 = acc[nt][0] + bv0; v0 = v0 / (1.f + __expf(-v0));
        float v1 = acc[nt][1] + bv1; v1 = v1 / (1.f + __expf(-v1));
        float v2 = acc[nt][2] + bv0; v2 = v2 / (1.f + __expf(-v2));
        float v3 = acc[nt][3] + bv1; v3 = v3 / (1.f + __expf(-v3));
        *(u32t*)(outH + p1 + co) = pk_bf16x2(v0, v1);
        *(u32t*)(outH + p2 + co) = pk_bf16x2(v2, v3);
    }
}

// ---------------------------------------------------------------------------
// Stride-1 fused conv3x3 + bias + SiLU (CIN=3) — conv1_n (fp32 path) only.
// ---------------------------------------------------------------------------
template<int CIN, int OUTC>
__global__ void __launch_bounds__(256, 2) convfast(
    const float* __restrict__ in, const float* __restrict__ wgt,
    const float* __restrict__ bias, float* __restrict__ out,
    int Hin, int Win)
{
    constexpr int COG  = 16;
    constexpr int ITX  = 34;
    constexpr int SRS  = 36;
    constexpr int ELEMS = ITX * ITX;
    constexpr int NIT  = (ELEMS + 255) / 256;
    constexpr int PLANE = ITX * SRS;

    extern __shared__ float sIn[];
    __shared__ float sW[2][COG*9 + 8];
    __shared__ int2 tTab[NIT*256];

    const int tid = threadIdx.x;
    const int tx = tid & 7, ty = tid >> 3;
    const int groups = OUTC / COG;
    const int b = blockIdx.z / groups;
    const int cbase = (blockIdx.z % groups) * COG;
    const int X0 = blockIdx.x * 32, Y0 = blockIdx.y * 32;
    const int iy0 = Y0 - 1, ix0 = X0 - 1;
    const size_t HW = (size_t)Hin * Win;
    const float* inb = in + (size_t)b * CIN * HW;

    const int wc = tid / 9, wtap = tid - wc*9;

#pragma unroll
    for (int k = 0; k < NIT; k++) {
        int f = k*256 + tid;
        int sof = -1, gof = -1;
        if (f < ELEMS) {
            int r = f / ITX, c = f - r*ITX;
            int ih = iy0 + r, iw = ix0 + c;
            sof = r*SRS + c;
            gof = ((unsigned)ih < (unsigned)Hin && (unsigned)iw < (unsigned)Win)
                  ? (ih*Win + iw) : -1;
        }
        tTab[k*256 + tid] = make_int2(gof, sof);
    }

    const unsigned sb0 = (unsigned)__cvta_generic_to_shared(sIn);
    auto stage = [&](int buf, int cin) {
        const float* ic = inb + (size_t)cin * HW;
        const unsigned sb = sb0 + (unsigned)buf * (PLANE*4);
#pragma unroll
        for (int k = 0; k < NIT; k++) {
            int2 t = tTab[k*256 + tid];
            if (t.y >= 0)
                cp_async4(sb + (unsigned)t.y*4, ic + (t.x < 0 ? 0 : t.x),
                          t.x < 0 ? 0 : 4);
        }
        if (tid < COG*9) {
            unsigned dst = (unsigned)__cvta_generic_to_shared(
                               &sW[buf][wtap*COG + wc]);
            cp_async4u(dst, wgt + ((size_t)(cbase+wc)*CIN + cin)*9 + wtap);
        }
    };

    stage(0, 0);
    cp_commit();
    cp_wait0();
    __syncthreads();

    u64 acc2[4][8];
#pragma unroll
    for (int j = 0; j < 4; j++)
#pragma unroll
        for (int p = 0; p < 8; p++) acc2[j][p] = 0ull;

    for (int cin = 0; cin < CIN; cin++) {
        const int cur = cin & 1;
        if (cin + 1 < CIN) { stage(cur^1, cin+1); cp_commit(); }

        const float* sc  = sIn + cur*PLANE;
        const float* swp = sW[cur];
#pragma unroll
        for (int dy = 0; dy < 3; dy++) {
            const float* rp = sc + (ty + dy)*SRS + tx*4;
            float4 A = *(const float4*)rp;
            float2 Bv = *(const float2*)(rp + 4);
            float iv6[6] = {A.x, A.y, A.z, A.w, Bv.x, Bv.y};
#pragma unroll
            for (int dx = 0; dx < 3; dx++) {
                const ulonglong2* wq = (const ulonglong2*)(swp + (dy*3+dx)*COG);
                ulonglong2 q0 = wq[0], q1 = wq[1], q2 = wq[2], q3 = wq[3];
#pragma unroll
                for (int j = 0; j < 4; j++)
                    fma2_row(acc2[j], iv6[j+dx], q0, q1, q2, q3);
            }
        }
        if (cin + 1 < CIN) cp_wait0();
        __syncthreads();
    }

    float bv[COG];
#pragma unroll
    for (int c = 0; c < COG; c++) bv[c] = __ldg(bias + cbase + c);

    const int oy = Y0 + ty;
    const int x0 = X0 + tx*4;
#pragma unroll
    for (int c = 0; c < COG; c++) {
        float vv[4];
#pragma unroll
        for (int j = 0; j < 4; j++) {
            float flo, fhi;
            UNPACK2(flo, fhi, acc2[j][c >> 1]);
            float v = ((c & 1) ? fhi : flo) + bv[c];
            vv[j] = v / (1.f + __expf(-v));
        }
        size_t rowbase = ((size_t)(b*OUTC + cbase + c)*258 + (oy+1))*PROW;
        *(float2*)(out + rowbase + 132 + (x0>>1)) = make_float2(vv[0], vv[2]);
        out[rowbase + (x0>>1) + 1] = vv[1];
        out[rowbase + (x0>>1) + 2] = vv[3];
    }
}

// ---------------------------------------------------------------------------
// Stride-2 conv (fp32 FFMA2 path) — conv2_n (16->16) only.
// ---------------------------------------------------------------------------
template<int CIN, int OUTC>
__global__ void __launch_bounds__(256, 2) convfast2(
    const float* __restrict__ in, const float* __restrict__ wgt,
    const float* __restrict__ bias, float* __restrict__ out)
{
    constexpr int COG  = 16;
    constexpr int SRS  = 72;
    constexpr int ODD  = 36;
    constexpr int PLANE = 65*SRS;
    constexpr int NOPS = 65*18;

    extern __shared__ float sIn[];
    __shared__ float sW[2][COG*9 + 8];

    const int tid = threadIdx.x;
    const int tx = tid & 7, ty = tid >> 3;
    const int groups = OUTC / COG;
    const int b = blockIdx.z / groups;
    const int cbase = (blockIdx.z % groups) * COG;
    const int X0 = blockIdx.x * 32, Y0 = blockIdx.y * 32;
    const float* inb = in + (size_t)b * CIN * PCH;

    const int wc = tid / 9, wtap = tid - wc*9;

    int gofs[5]; int sofs[5];
#pragma unroll
    for (int k = 0; k < 5; k++) {
        int id = k*256 + tid;
        if (id < NOPS) {
            int row = id / 18;
            int rem = id - row*18;
            int seg = rem / 9;
            int q   = rem - seg*9;
            gofs[k] = (2*Y0 + row)*PROW + seg*132 + X0 + q*4;
            sofs[k] = (row*SRS + seg*ODD + q*4) * 4;
        } else { gofs[k] = 0; sofs[k] = -1; }
    }

    const unsigned sb0 = (unsigned)__cvta_generic_to_shared(sIn);
    auto stage = [&](int buf, int cin) {
        const float* ic = inb + (size_t)cin * PCH;
        const unsigned sb = sb0 + (unsigned)buf * (PLANE*4);
#pragma unroll
        for (int k = 0; k < 5; k++)
            if (sofs[k] >= 0) cp_async16(sb + (unsigned)sofs[k], ic + gofs[k]);
        if (tid < COG*9) {
            unsigned dst = (unsigned)__cvta_generic_to_shared(
                               &sW[buf][wtap*COG + wc]);
            cp_async4u(dst, wgt + ((size_t)(cbase+wc)*CIN + cin)*9 + wtap);
        }
    };

    stage(0, 0);
    cp_commit();
    cp_wait0();
    __syncthreads();

    u64 acc2[4][8];
#pragma unroll
    for (int j = 0; j < 4; j++)
#pragma unroll
        for (int p = 0; p < 8; p++) acc2[j][p] = 0ull;

    for (int cin = 0; cin < CIN; cin++) {
        const int cur = cin & 1;
        if (cin + 1 < CIN) { stage(cur^1, cin+1); cp_commit(); }

        const float* sc  = sIn + cur*PLANE;
        const float* swp = sW[cur];
#pragma unroll
        for (int dy = 0; dy < 3; dy++) {
            const float* rp = sc + (ty*2 + dy)*SRS;
            float4 E = *(const float4*)(rp + tx*4);
            float  e4 = rp[tx*4 + 4];
            float4 O = *(const float4*)(rp + ODD + tx*4);
            float V[3][4];
            V[0][0]=E.x; V[0][1]=E.y; V[0][2]=E.z; V[0][3]=E.w;
            V[1][0]=O.x; V[1][1]=O.y; V[1][2]=O.z; V[1][3]=O.w;
            V[2][0]=E.y; V[2][1]=E.z; V[2][2]=E.w; V[2][3]=e4;
#pragma unroll
            for (int dx = 0; dx < 3; dx++) {
                const ulonglong2* wq = (const ulonglong2*)(swp + (dy*3+dx)*COG);
                ulonglong2 q0 = wq[0], q1 = wq[1], q2 = wq[2], q3 = wq[3];
#pragma unroll
                for (int j = 0; j < 4; j++)
                    fma2_row(acc2[j], V[dx][j], q0, q1, q2, q3);
            }
        }
        if (cin + 1 < CIN) cp_wait0();
        __syncthreads();
    }

    float bv[COG];
#pragma unroll
    for (int c = 0; c < COG; c++) bv[c] = __ldg(bias + cbase + c);

    const int oy = Y0 + ty;
#pragma unroll
    for (int j = 0; j < 4; j++) {
        float vv[COG];
#pragma unroll
        for (int p = 0; p < 8; p++) {
            float flo, fhi;
            UNPACK2(flo, fhi, acc2[j][p]);
            float v0 = flo + bv[2*p],     v1 = fhi + bv[2*p+1];
            vv[2*p]   = v0 / (1.f + __expf(-v0));
            vv[2*p+1] = v1 / (1.f + __expf(-v1));
        }
        size_t t = ((size_t)b*H2 + oy)*W2 + X0 + tx*4 + j;
        float4* op = (float4*)(out + t*OUTC + cbase);
        op[0] = make_float4(vv[0],  vv[1],  vv[2],  vv[3]);
        op[1] = make_float4(vv[4],  vv[5],  vv[6],  vv[7]);
        op[2] = make_float4(vv[8],  vv[9],  vv[10], vv[11]);
        op[3] = make_float4(vv[12], vv[13], vv[14], vv[15]);
    }
}

// ---------------------------------------------------------------------------
// conv2_s token-GEMM (mma.sync m16n8k16 bf16, single pass — alpha-damped).
// ---------------------------------------------------------------------------
#define APS 12
#define BPS 12
#define SA_U32 (3*258*APS)          // 9288 u32
#define SB_U32 (9*128*BPS)          // 13824 u32
#define C2_SMEM ((2*(SA_U32 + SB_U32))*4)   // 184896 B

__global__ void __launch_bounds__(256, 1) conv2s_mma(
    const __nv_bfloat16* __restrict__ gh, const u32t* __restrict__ wph,
    const float* __restrict__ bias, float* __restrict__ out)
{
    extern __shared__ u32t sm32[];
    u32t* sA[2] = { sm32, sm32 + SA_U32 + SB_U32 };
    u32t* sB[2] = { sm32 + SA_U32, sm32 + 2*SA_U32 + SB_U32 };

    const int tid = threadIdx.x, lane = tid & 31, w = tid >> 5;
    const int y  = blockIdx.x;
    const int b  = blockIdx.y;

    float acc[16][4];
#pragma unroll
    for (int nt = 0; nt < 16; nt++)
#pragma unroll
        for (int r = 0; r < 4; r++) acc[nt][r] = 0.f;

    const int q = lane & 3;
    const int g = lane >> 2;
    const int mlow = 16*w + g;

    auto stage = [&](int buf, int cc) {
        const unsigned aB = (unsigned)__cvta_generic_to_shared(sA[buf]);
        const unsigned bB = (unsigned)__cvta_generic_to_shared(sB[buf]);
        for (int i = tid; i < 1548; i += 256) {
            int pos = i >> 1; int half = i & 1;
            int dy = pos / 258, pl = pos - dy*258;
            size_t gofs = (((size_t)b*NR + (2*y + dy))*NR + pl)*128
                          + cc*16 + half*8;
            cp_async16(aB + (unsigned)(pos*APS*4 + half*16), gh + gofs);
        }
        for (int i = tid; i < 2304; i += 256) {
            int tc = i >> 1; int half = i & 1;
            cp_async16(bB + (unsigned)(tc*BPS*4 + half*16),
                       wph + (cc*1152 + tc)*8 + half*4);
        }
    };

    stage(0, 0);
    cp_commit();
    cp_wait0();
    __syncthreads();

    for (int cc = 0; cc < 8; cc++) {
        const int cur = cc & 1;
        if (cc + 1 < 8) { stage(cur^1, cc+1); cp_commit(); }

        const u32t* sAc = sA[cur];
        const u32t* sBc = sB[cur];
#pragma unroll
        for (int dy = 0; dy < 3; dy++)
#pragma unroll
        for (int dx = 0; dx < 3; dx++) {
            const int tap = dy*3 + dx;
            const int baseA = (dy*258 + 2*mlow + dx) * APS;
            const int baseA8 = baseA + 16*APS;
            u32t a0 = sAc[baseA + q],      a2 = sAc[baseA + q + 4];
            u32t a1 = sAc[baseA8 + q],     a3 = sAc[baseA8 + q + 4];
#pragma unroll
            for (int nt = 0; nt < 16; nt++) {
                int co = 8*nt + g;
                int bb = (tap*128 + co) * BPS;
                u32t b0 = sBc[bb + q], b1 = sBc[bb + q + 4];
                MMA_BF16(acc[nt], a0, a1, a2, a3, b0, b1);
            }
        }
        if (cc + 1 < 8) { cp_wait0(); __syncthreads(); }
    }

    size_t t1 = ((size_t)(b*H2 + y)*W2 + mlow) * 128;
    size_t t2 = t1 + (size_t)8*128;
#pragma unroll
    for (int nt = 0; nt < 16; nt++) {
        int co = 8*nt + 2*q;
        float bv0 = __ldg(bias + co), bv1 = __ldg(bias + co + 1);
        float v0 = acc[nt][0] + bv0; v0 = v0 / (1.f + __expf(-v0));
        float v1 = acc[nt][1] + bv1; v1 = v1 / (1.f + __expf(-v1));
        float v2 = acc[nt][2] + bv0; v2 = v2 / (1.f + __expf(-v2));
        float v3 = acc[nt][3] + bv1; v3 = v3 / (1.f + __expf(-v3));
        *(float2*)(out + t1 + co) = make_float2(v0, v1);
        *(float2*)(out + t2 + co) = make_float2(v2, v3);
    }
}

// ---------------------------------------------------------------------------
// Legacy conv (final tiny 3->3 decoder conv)
// ---------------------------------------------------------------------------
template<int CIN, int OUTC, int COG>
__global__ void __launch_bounds__(256) conv3x3(
    const float* __restrict__ in, const float* __restrict__ wgt,
    const float* __restrict__ bias, float* __restrict__ out,
    int Hin, int Win)
{
    constexpr int ITD = 18;
    __shared__ float sW[COG*CIN*9];
    __shared__ float sIn[ITD*ITD];

    const int tid = threadIdx.x;
    const int groups = OUTC / COG;
    const int b  = blockIdx.z / groups;
    const int cbase = (blockIdx.z % groups) * COG;

    for (int i = tid; i < COG*CIN*9; i += 256)
        sW[i] = wgt[(size_t)cbase*CIN*9 + i];

    const int ty = tid >> 4, tx = tid & 15;
    const int oy = blockIdx.y*16 + ty;
    const int ox = blockIdx.x*16 + tx;

    float acc[COG];
#pragma unroll
    for (int c = 0; c < COG; c++) acc[c] = 0.f;

    const float* inb = in + (size_t)b * CIN * Hin * Win;
    const int iy0 = blockIdx.y*16 - 1;
    const int ix0 = blockIdx.x*16 - 1;
    const int base = ty*ITD + tx;

    for (int cin = 0; cin < CIN; cin++) {
        __syncthreads();
        const float* ic = inb + (size_t)cin * Hin * Win;
        for (int i = tid; i < ITD*ITD; i += 256) {
            int r = i / ITD, cc = i - r*ITD;
            int ih = iy0 + r, iw = ix0 + cc;
            float v = 0.f;
            if ((unsigned)ih < (unsigned)Hin && (unsigned)iw < (unsigned)Win)
                v = ic[ih*Win + iw];
            sIn[i] = v;
        }
        __syncthreads();
        const float* wp = sW + cin*9;
#pragma unroll
        for (int dy = 0; dy < 3; dy++)
#pragma unroll
            for (int dx = 0; dx < 3; dx++) {
                float iv = sIn[base + dy*ITD + dx];
#pragma unroll
                for (int c = 0; c < COG; c++)
                    acc[c] += iv * wp[c*CIN*9 + dy*3 + dx];
            }
    }

#pragma unroll
    for (int c = 0; c < COG; c++) {
        float v = acc[c] + bias[cbase + c];
        v = v / (1.f + __expf(-v));
        out[(((size_t)b*OUTC + cbase + c)*Hin + oy)*Win + ox] = v;
    }
}

// ---------------------------------------------------------------------------
// Memcell pass 1: w = softmax(z @ K^T / 4) per token.
// ---------------------------------------------------------------------------
__global__ void __launch_bounds__(256) memcell_softmax(
    const float* __restrict__ z, const float* __restrict__ ck,
    float* __restrict__ wout)
{
    __shared__ float sK[Mm*Nn];
    const int tid = threadIdx.x;
    for (int i = tid; i < Mm*Nn; i += 256) sK[i] = ck[i];
    __syncthreads();

    const int t = blockIdx.x*256 + tid;
    const float4* zp = (const float4*)(z + (size_t)t*Nn);
    float4 z0 = zp[0], z1 = zp[1], z2 = zp[2], z3 = zp[3];

    float s[Mm];
    float mx = -1e30f;
#pragma unroll
    for (int m = 0; m < Mm; m++) {
        const float* k = sK + m*Nn;
        float d = z0.x*k[0] + z0.y*k[1] + z0.z*k[2] + z0.w*k[3]
                + z1.x*k[4] + z1.y*k[5] + z1.z*k[6] + z1.w*k[7]
                + z2.x*k[8] + z2.y*k[9] + z2.z*k[10]+ z2.w*k[11]
                + z3.x*k[12]+ z3.y*k[13]+ z3.z*k[14]+ z3.w*k[15];
        d *= 0.25f;
        s[m] = d;
        mx = fmaxf(mx, d);
    }
    float sum = 0.f;
#pragma unroll
    for (int m = 0; m < Mm; m++) { s[m] = __expf(s[m]-mx); sum += s[m]; }
    float inv = 1.f / sum;
    float4* wo = (float4*)(wout + (size_t)t*Mm);
#pragma unroll
    for (int j = 0; j < Mm/4; j++) {
        float4 v; v.x = s[4*j]*inv; v.y = s[4*j+1]*inv;
        v.z = s[4*j+2]*inv; v.w = s[4*j+3]*inv;
        wo[j] = v;
    }
}

// ---------------------------------------------------------------------------
// Memcell pass 2: block partials of [G | U].
// ---------------------------------------------------------------------------
__global__ void __launch_bounds__(256) memcell_outer(
    const float* __restrict__ wmat, const float* __restrict__ ts,
    float* __restrict__ part)
{
    __shared__ float sv[8*160];
    const int tid = threadIdx.x;
    const int ti = tid >> 5;
    const int tj = tid & 31;
    float acc[4][5];
#pragma unroll
    for (int a = 0; a < 4; a++)
#pragma unroll
        for (int qq = 0; qq < 5; qq++) acc[a][qq] = 0.f;

    const int tokb = blockIdx.x * 128;
    for (int ch = 0; ch < 128; ch += 8) {
        __syncthreads();
#pragma unroll
        for (int l = 0; l < 5; l++) {
            int idx = l*256 + tid;
            int tk = idx / 160, f = idx - tk*160;
            int t = tokb + ch + tk;
            sv[tk*160 + f] = (f < 32) ? wmat[(size_t)t*32 + f]
                                      : ts[(size_t)t*128 + (f-32)];
        }
        __syncthreads();
#pragma unroll
        for (int tk = 0; tk < 8; tk++) {
            float wi[4], vj[5];
#pragma unroll
            for (int a = 0; a < 4; a++) wi[a] = sv[tk*160 + ti*4 + a];
#pragma unroll
            for (int qq = 0; qq < 5; qq++) vj[qq] = sv[tk*160 + tj*5 + qq];
#pragma unroll
            for (int a = 0; a < 4; a++)
#pragma unroll
                for (int qq = 0; qq < 5; qq++) acc[a][qq] += wi[a]*vj[qq];
        }
    }
    float* pp = part + (size_t)blockIdx.x * 5120;
#pragma unroll
    for (int a = 0; a < 4; a++)
#pragma unroll
        for (int qq = 0; qq < 5; qq++)
            pp[(ti*4+a)*160 + tj*5 + qq] = acc[a][qq];
}

__global__ void __launch_bounds__(256) reduce_partials(
    const float* __restrict__ part, float* __restrict__ gu)
{
    int cell = blockIdx.x*256 + threadIdx.x;
    float s = 0.f;
#pragma unroll 8
    for (int p = 0; p < 1024; p++) s += part[(size_t)p*5120 + cell];
    gu[cell] = s;
}

__global__ void __launch_bounds__(256) cell_update(
    const float* __restrict__ gu, const float* __restrict__ cv,
    float* __restrict__ vnew)
{
    __shared__ float sG[Mm*Mm];
    __shared__ float sV[Mm*Ss];
    const int tid = threadIdx.x;
    for (int i = tid; i < Mm*Mm; i += 256) {
        int m = i >> 5, j = i & 31;
        sG[i] = gu[m*160 + j];
    }
    for (int i = tid; i < Mm*Ss; i += 256) sV[i] = cv[i];
    __syncthreads();
    for (int k = 0; k < 16; k++) {
        int cell = k*256 + tid;
        int m = cell >> 7, s0 = cell & 127;
        float d = gu[m*160 + 32 + s0];
#pragma unroll
        for (int mp = 0; mp < Mm; mp++) d -= sG[m*32 + mp] * sV[mp*128 + s0];
        vnew[cell] = sV[cell] + ALPHA * d;
    }
}

// ---------------------------------------------------------------------------
// Memcell pass 3: t_read = W @ cell_v_new -> NCHW [B,S,H2,W2].
// ---------------------------------------------------------------------------
__global__ void __launch_bounds__(256) memcell_read(
    const float* __restrict__ wmat, const float* __restrict__ vnew,
    float* __restrict__ d0m)
{
    __shared__ float sV[Mm*Ss];
    __shared__ float sW[64*33];
    const int tid = threadIdx.x;
    for (int i = tid; i < Mm*Ss; i += 256) sV[i] = vnew[i];
    const int tbase = blockIdx.x * 64;
    for (int i = tid; i < 64*32; i += 256) {
        int tk = i >> 5, m = i & 31;
        sW[tk*33 + m] = wmat[(size_t)(tbase + tk)*32 + m];
    }
    __syncthreads();

    const int lane = tid & 31, wid = tid >> 5;
    const int cb = wid * 16;
    float a0[16], a1[16];
#pragma unroll
    for (int c = 0; c < 16; c++) { a0[c] = 0.f; a1[c] = 0.f; }

    const float* w0 = sW + lane*33;
    const float* w1 = sW + (lane + 32)*33;
#pragma unroll 4
    for (int m = 0; m < Mm; m++) {
        float x0 = w0[m], x1 = w1[m];
        const float4* vv = (const float4*)(sV + m*128 + cb);
#pragma unroll
        for (int qq = 0; qq < 4; qq++) {
            float4 v = vv[qq];
            a0[qq*4+0] += x0*v.x; a0[qq*4+1] += x0*v.y;
            a0[qq*4+2] += x0*v.z; a0[qq*4+3] += x0*v.w;
            a1[qq*4+0] += x1*v.x; a1[qq*4+1] += x1*v.y;
            a1[qq*4+2] += x1*v.z; a1[qq*4+3] += x1*v.w;
        }
    }
    const int b = tbase >> 14;
    const int rem = tbase & 16383;
    const int h = rem >> 7;
    const int wcp = rem & 127;
    size_t obase = ((size_t)b*Ss)*((size_t)H2*W2) + (size_t)h*W2 + wcp;
#pragma unroll
    for (int c = 0; c < 16; c++) {
        size_t o = obase + (size_t)(cb + c)*(H2*W2);
        d0m[o + lane]      = a0[c];
        d0m[o + 32 + lane] = a1[c];
    }
}

// ---------------------------------------------------------------------------
// ConvTranspose2d(128->3, k4, s2, p1) + bias + SiLU.  32x32 output tiles.
// ---------------------------------------------------------------------------
__global__ void __launch_bounds__(256) deconv_kernel(
    const float* __restrict__ in, const float* __restrict__ dw,
    const float* __restrict__ db, float* __restrict__ out)
{
    __shared__ float sWd[4*128*12];
    __shared__ float sIn[16*324];
    const int tid = threadIdx.x;
    for (int i = tid; i < 4*128*12; i += 256) {
        int p = i / 1536, rem = i - p*1536;
        int cin = rem / 12, rr = rem - cin*12;
        int o = rr >> 2, k = rr & 3;
        int py = p >> 1, px = p & 1;
        int ky = py + 2*(k >> 1), kx = px + 2*(k & 1);
        sWd[i] = dw[cin*48 + o*16 + ky*4 + kx];
    }

    const int b  = blockIdx.z;
    const int Y0 = blockIdx.y*32, X0 = blockIdx.x*32;
    const int ty = tid >> 4, tx = tid & 15;
    const int y0 = Y0 + ty, x0 = X0 + tx;
    const int hb = (Y0 >> 1) - 1, wb = (X0 >> 1) - 1;

    const int py = (y0 + 1) & 1, px = (x0 + 1) & 1;
    const int hs0 = ((y0 + 1 - py) >> 1) - hb;
    const int ws0 = ((x0 + 1 - px) >> 1) - wb;

    const float* wp = sWd + (py*2 + px)*1536;
    float acc[2][2][3];
#pragma unroll
    for (int a = 0; a < 2; a++)
#pragma unroll
        for (int e = 0; e < 2; e++)
#pragma unroll
            for (int o = 0; o < 3; o++) acc[a][e][o] = 0.f;

    const float* inb = in + (size_t)b * Ss * H2 * W2;

    for (int c0 = 0; c0 < Ss; c0 += 16) {
        __syncthreads();
        for (int i = tid; i < 16*324; i += 256) {
            int c = i / 324, rr = i - c*324;
            int r = rr / 18, cc = rr - r*18;
            int h = hb + r, w = wb + cc;
            float v = 0.f;
            if ((unsigned)h < (unsigned)H2 && (unsigned)w < (unsigned)W2)
                v = inb[((size_t)(c0 + c)*H2 + h)*W2 + w];
            sIn[i] = v;
        }
        __syncthreads();
#pragma unroll
        for (int c = 0; c < 16; c++) {
            const float* sc = sIn + c*324;
            const float4* w4 = (const float4*)(wp + (c0 + c)*12);
            float4 Wa = w4[0], Wb = w4[1], Wc = w4[2];
#pragma unroll
            for (int a = 0; a < 2; a++)
#pragma unroll
                for (int e = 0; e < 2; e++) {
                    int hh = hs0 + 8*a, ww = ws0 + 8*e;
                    float i00 = sc[hh*18 + ww];
                    float i01 = sc[hh*18 + ww - 1];
                    float i10 = sc[(hh-1)*18 + ww];
                    float i11 = sc[(hh-1)*18 + ww - 1];
                    acc[a][e][0] += i00*Wa.x + i01*Wa.y + i10*Wa.z + i11*Wa.w;
                    acc[a][e][1] += i00*Wb.x + i01*Wb.y + i10*Wb.z + i11*Wb.w;
                    acc[a][e][2] += i00*Wc.x + i01*Wc.y + i10*Wc.z + i11*Wc.w;
                }
        }
    }
#pragma unroll
    for (int a = 0; a < 2; a++)
#pragma unroll
        for (int e = 0; e < 2; e++)
#pragma unroll
            for (int o = 0; o < 3; o++) {
                float v = acc[a][e][o] + db[o];
                v = v / (1.f + __expf(-v));
                out[(((size_t)b*3 + o)*HIN + y0 + 16*a)*WIN + x0 + 16*e] = v;
            }
}

// ---------------------------------------------------------------------------
// Launch sequence
// ---------------------------------------------------------------------------
extern "C" void kernel_launch(void* const* d_in, const int* in_sizes, int n_in,
                              void* d_out, int out_size)
{
    const float* x      = (const float*)d_in[0];
    const float* e0n_w1 = (const float*)d_in[1];
    const float* e0n_b1 = (const float*)d_in[2];
    const float* e0n_w2 = (const float*)d_in[3];
    const float* e0n_b2 = (const float*)d_in[4];
    const float* e0s_w1 = (const float*)d_in[5];
    const float* e0s_b1 = (const float*)d_in[6];
    const float* e0s_w2 = (const float*)d_in[7];
    const float* e0s_b2 = (const float*)d_in[8];
    const float* d0_dw  = (const float*)d_in[9];
    const float* d0_db  = (const float*)d_in[10];
    const float* d0_cw  = (const float*)d_in[11];
    const float* d0_cb  = (const float*)d_in[12];
    const float* cell_k = (const float*)d_in[13];
    const float* cell_v = (const float*)d_in[14];
    float* outp = (float*)d_out;

    void *p_a1n, *p_hi, *p_wph, *p_wp1, *p_z, *p_ts, *p_w,
         *p_part, *p_gu, *p_vnew, *p_d0m, *p_dec;
    cudaGetSymbolAddress(&p_a1n, g_a1n);
    cudaGetSymbolAddress(&p_hi,  g_hi);
    cudaGetSymbolAddress(&p_wph, g_wph);
    cudaGetSymbolAddress(&p_wp1, g_wp1);
    cudaGetSymbolAddress(&p_z,   g_z);
    cudaGetSymbolAddress(&p_ts,  g_ts);
    cudaGetSymbolAddress(&p_w,   g_w);
    cudaGetSymbolAddress(&p_part,g_part);
    cudaGetSymbolAddress(&p_gu,  g_gu);
    cudaGetSymbolAddress(&p_vnew,g_vnew);
    cudaGetSymbolAddress(&p_d0m, g_d0m);
    cudaGetSymbolAddress(&p_dec, g_dec);

    const int dsm_s1 = 2 * 34 * 36 * 4;   //  9792 B
    const int dsm_s2 = 2 * 65 * 72 * 4;   // 37440 B

    cudaFuncSetAttribute((const void*)convfast<3,16>,
                         cudaFuncAttributeMaxDynamicSharedMemorySize, dsm_s1);
    cudaFuncSetAttribute((const void*)convfast2<16,16>,
                         cudaFuncAttributeMaxDynamicSharedMemorySize, dsm_s2);
    cudaFuncSetAttribute((const void*)conv2s_mma,
                         cudaFuncAttributeMaxDynamicSharedMemorySize, C2_SMEM);

    // Prep: borders + packed weights
    zero_borders<<<Bb*Nn, 256>>>((float*)p_a1n);
    zb_nhwc<<<Bb, 256>>>((__nv_bfloat16*)p_hi);
    wprep<<<288, 256>>>(e0s_w2, (u32t*)p_wph);
    wprep1<<<8, 256>>>(e0s_w1, (u32t*)p_wp1);

    // Encoders
    convfast<3,16><<<dim3(8,8,Bb),256,dsm_s1>>>(
        x, e0n_w1, e0n_b1, (float*)p_a1n, HIN, WIN);
    conv1s_mma<<<dim3(2,HIN,Bb),256>>>(
        x, (const u32t*)p_wp1, e0s_b1, (__nv_bfloat16*)p_hi);
    convfast2<16,16><<<dim3(4,4,Bb),256,dsm_s2>>>(
        (const float*)p_a1n, e0n_w2, e0n_b2, (float*)p_z);
    conv2s_mma<<<dim3(128,Bb),256,C2_SMEM>>>(
        (const __nv_bfloat16*)p_hi, (const u32t*)p_wph, e0s_b2, (float*)p_ts);

    // Memcell
    memcell_softmax<<<Tt/256,256>>>((const float*)p_z, cell_k, (float*)p_w);
    memcell_outer<<<1024,256>>>((const float*)p_w, (const float*)p_ts, (float*)p_part);
    reduce_partials<<<20,256>>>((const float*)p_part, (float*)p_gu);
    cell_update<<<1,256>>>((const float*)p_gu, cell_v, (float*)p_vnew);
    memcell_read<<<Tt/64,256>>>((const float*)p_w, (const float*)p_vnew, (float*)p_d0m);

    // Decoder
    deconv_kernel<<<dim3(8,8,Bb),256>>>(
        (const float*)p_d0m, d0_dw, d0_db, (float*)p_dec);
    conv3x3<3,3,3><<<dim3(16,16,Bb),256>>>(
        (const float*)p_dec, d0_cw, d0_cb, outp, HIN, WIN);
}

// round 17
// speedup vs baseline: 4.2299x; 1.0091x over previous
#include <cuda_runtime.h>
#include <cuda_bf16.h>
#include <cstdint>

// ---------------------------------------------------------------------------
// Problem constants
// ---------------------------------------------------------------------------
#define Bb   8
#define HIN  256
#define WIN  256
#define H2   128
#define W2   128
#define Nn   16
#define Mm   32
#define Ss   128
#define Tt   (Bb*H2*W2)          // 131072 tokens
#define ALPHA 1e-6f

// Padded parity-split activation layout (fp32 path, conv1_n -> conv2_n):
#define PROW 264
#define PCH  (258*PROW)

// NHWC-padded bf16 layout for conv1_s output (rows/cols padded by 1):
#define NR   258
#define NCH  ((size_t)NR*NR*128)

typedef unsigned long long u64;
typedef unsigned int u32t;

// ---------------------------------------------------------------------------
// Scratch buffers (static device globals; no cudaMalloc allowed)
// ---------------------------------------------------------------------------
__device__ float g_a1n [(size_t)Bb*Nn*PCH];        // padded silu(conv1_n) fp32
__device__ __nv_bfloat16 g_hi [(size_t)Bb*NCH];    // silu(conv1_s) bf16
__device__ u32t  g_wph[8*9*128*8];                 // packed conv2_s weights bf16
__device__ u32t  g_wp1[128*16];                    // packed conv1_s weights bf16
__device__ float g_z   [(size_t)Tt*Nn];
__device__ __nv_bfloat16 g_tsb [(size_t)Tt*Ss];    // t_star bf16 (alpha-damped)
__device__ float g_w   [(size_t)Tt*Mm];
__device__ float g_part[(size_t)1024*32*160];
__device__ float g_gu  [32*160];
__device__ float g_vnew[Mm*Ss];
__device__ float g_d0m [(size_t)Bb*Ss*H2*W2];
__device__ float g_dec [(size_t)Bb*3*HIN*WIN];

// ---------------------------------------------------------------------------
// cp.async + f32x2 helpers
// ---------------------------------------------------------------------------
__device__ __forceinline__ void cp_async4(unsigned dst, const float* src, int sz) {
    asm volatile("cp.async.ca.shared.global [%0], [%1], 4, %2;\n"
                 :: "r"(dst), "l"(src), "r"(sz));
}
__device__ __forceinline__ void cp_async4u(unsigned dst, const float* src) {
    asm volatile("cp.async.ca.shared.global [%0], [%1], 4;\n"
                 :: "r"(dst), "l"(src));
}
__device__ __forceinline__ void cp_async16(unsigned dst, const void* src) {
    asm volatile("cp.async.cg.shared.global [%0], [%1], 16;\n"
                 :: "r"(dst), "l"(src));
}
__device__ __forceinline__ void cp_commit() {
    asm volatile("cp.async.commit_group;\n" ::: "memory");
}
__device__ __forceinline__ void cp_wait0() {
    asm volatile("cp.async.wait_group 0;\n" ::: "memory");
}

#define FMA2(d, a, b) \
    asm("fma.rn.f32x2 %0, %1, %2, %0;" : "+l"(d) : "l"(a), "l"(b))
#define PACK2(dst, v) \
    asm("mov.b64 %0, {%1, %1};" : "=l"(dst) : "f"(v))
#define UNPACK2(lo, hi, src) \
    asm("mov.b64 {%0, %1}, %2;" : "=f"(lo), "=f"(hi) : "l"(src))

__device__ __forceinline__ void fma2_row(u64* acc, float v,
                                         const ulonglong2& q0, const ulonglong2& q1,
                                         const ulonglong2& q2, const ulonglong2& q3) {
    u64 vv; PACK2(vv, v);
    FMA2(acc[0], vv, q0.x); FMA2(acc[1], vv, q0.y);
    FMA2(acc[2], vv, q1.x); FMA2(acc[3], vv, q1.y);
    FMA2(acc[4], vv, q2.x); FMA2(acc[5], vv, q2.y);
    FMA2(acc[6], vv, q3.x); FMA2(acc[7], vv, q3.y);
}

// mma.sync m16n8k16 bf16 (fp32 accumulate)
#define MMA_BF16(c, a0,a1,a2,a3, b0,b1) \
    asm volatile("mma.sync.aligned.m16n8k16.row.col.f32.bf16.bf16.f32 " \
        "{%0,%1,%2,%3}, {%4,%5,%6,%7}, {%8,%9}, {%0,%1,%2,%3};" \
        : "+f"(c[0]), "+f"(c[1]), "+f"(c[2]), "+f"(c[3]) \
        : "r"(a0), "r"(a1), "r"(a2), "r"(a3), "r"(b0), "r"(b1))

__device__ __forceinline__ u32t pk_bf16x2(float a, float b) {
    __nv_bfloat162 t = __floats2bfloat162_rn(a, b);
    return *(u32t*)&t;
}

// ---------------------------------------------------------------------------
// Border zero kernels
// ---------------------------------------------------------------------------
__global__ void zero_borders(float* buf) {
    float* p = buf + (size_t)blockIdx.x * PCH;
    int tid = threadIdx.x;
    for (int i = tid; i < PROW; i += 256) p[i] = 0.f;
    p[(tid + 1) * PROW] = 0.f;
}

__global__ void zb_nhwc(__nv_bfloat16* gh) {
    const int b = blockIdx.x;
    u32t* h = (u32t*)(gh + (size_t)b*NCH);
    const int tid = threadIdx.x;
    for (int i = tid; i < NR*64; i += 256) {
        h[i] = 0u;
        h[(size_t)257*NR*64 + i] = 0u;
    }
    for (int i = tid; i < 256*64; i += 256) {
        int r = 1 + i/64, c2 = i%64;
        h[((size_t)r*NR + 0)*64 + c2] = 0u;
        h[((size_t)r*NR + 257)*64 + c2] = 0u;
    }
}

// ---------------------------------------------------------------------------
// conv2_s weight pre-pack (bf16 — output is alpha-damped)
// ---------------------------------------------------------------------------
__global__ void wprep(const float* __restrict__ wgt, u32t* __restrict__ wph) {
    int i = blockIdx.x*256 + threadIdx.x;
    if (i >= 8*9*128*8) return;
    int q = i & 7;
    int r = i >> 3;
    int co = r & 127; r >>= 7;
    int tap = r % 9;
    int cc  = r / 9;
    int cin = cc*16 + 2*q;
    wph[i] = pk_bf16x2(wgt[co*1152 + cin*9 + tap],
                       wgt[co*1152 + (cin+1)*9 + tap]);
}

// conv1_s weight pre-pack: [co][k2], k = cin*9+tap (27 real, pad to 32).
__global__ void wprep1(const float* __restrict__ wgt, u32t* __restrict__ wp1) {
    int i = blockIdx.x*256 + threadIdx.x;
    if (i >= 128*16) return;
    int k2 = i & 15, co = i >> 4;
    int k0 = 2*k2, k1 = k0 + 1;
    float v0 = (k0 < 27) ? wgt[co*27 + k0] : 0.f;
    float v1 = (k1 < 27) ? wgt[co*27 + k1] : 0.f;
    wp1[i] = pk_bf16x2(v0, v1);
}

// ---------------------------------------------------------------------------
// conv1_s as bf16 token-GEMM (alpha-damped branch).
// Block: ONE FULL ROW (256 pixels) x 128 co; 8 warps; two 128-token
// m-segments reuse staged B / X-window / A-panel. K=27 padded to 32.
// ---------------------------------------------------------------------------
#define SAS 17     // sA token-stride in u32 (bank padded)
#define SBS 17     // sB co-stride in u32
__global__ void __launch_bounds__(256) conv1s_mma(
    const float* __restrict__ x, const u32t* __restrict__ wp1,
    const float* __restrict__ bias, __nv_bfloat16* __restrict__ outH)
{
    __shared__ float sX[3][3][264];      // [cin][dy][col], col = ix+1, 0..257
    __shared__ u32t sA[256*SAS];
    __shared__ u32t sB[128*SBS];

    const int tid = threadIdx.x, lane = tid & 31, w = tid >> 5;
    const int y  = blockIdx.x;
    const int b  = blockIdx.y;

    // stage B (2048 u32)
    for (int i = tid; i < 2048; i += 256)
        sB[(i >> 4)*SBS + (i & 15)] = wp1[i];

    // stage X window: 3 cins x 3 rows x full row (zero padded)
    for (int i = tid; i < 3*3*264; i += 256) {
        int cin = i / 792, r = (i / 264) % 3, c = i % 264;
        int iy = y + r - 1, ix = c - 1;
        float v = 0.f;
        if (c < 258 && (unsigned)iy < 256u && (unsigned)ix < 256u)
            v = x[(((size_t)b*3 + cin)*256 + iy)*256 + ix];
        sX[cin][r][c] = v;
    }
    __syncthreads();

    // build im2col A panel: 256 tokens x 16 u32 (k = cin*9 + dy*3 + dx)
    for (int i = tid; i < 4096; i += 256) {
        int tok = i >> 4, k2 = i & 15;
        int k0 = 2*k2, k1 = k0 + 1;
        float v0 = (k0 < 27) ? sX[k0/9][(k0%9)/3][tok + (k0%3)] : 0.f;
        float v1 = (k1 < 27) ? sX[k1/9][(k1%9)/3][tok + (k1%3)] : 0.f;
        sA[tok*SAS + k2] = pk_bf16x2(v0, v1);
    }
    __syncthreads();

    const int q = lane & 3;
    const int g = lane >> 2;

#pragma unroll
    for (int mseg = 0; mseg < 2; mseg++) {
        const int tok0 = mseg*128 + 16*w + g;

        float acc[16][4];
#pragma unroll
        for (int nt = 0; nt < 16; nt++)
#pragma unroll
            for (int r = 0; r < 4; r++) acc[nt][r] = 0.f;

#pragma unroll
        for (int kit = 0; kit < 2; kit++) {
            u32t a0 = sA[tok0*SAS + kit*8 + q];
            u32t a2 = sA[tok0*SAS + kit*8 + q + 4];
            u32t a1 = sA[(tok0+8)*SAS + kit*8 + q];
            u32t a3 = sA[(tok0+8)*SAS + kit*8 + q + 4];
#pragma unroll
            for (int nt = 0; nt < 16; nt++) {
                int co = 8*nt + g;
                u32t b0 = sB[co*SBS + kit*8 + q];
                u32t b1 = sB[co*SBS + kit*8 + q + 4];
                MMA_BF16(acc[nt], a0, a1, a2, a3, b0, b1);
            }
        }

        // epilogue: bias + SiLU -> bf16 NHWC (row y+1, col tok0+1 padded)
        size_t p1 = (((size_t)b*NR + (y+1))*NR + (tok0 + 1))*128;
        size_t p2 = p1 + (size_t)8*128;
#pragma unroll
        for (int nt = 0; nt < 16; nt++) {
            int co = 8*nt + 2*q;
            float bv0 = __ldg(bias + co), bv1 = __ldg(bias + co + 1);
            float v0 = acc[nt][0] + bv0; v0 = v0 / (1.f + __expf(-v0));
            float v1 = acc[nt][1] + bv1; v1 = v1 / (1.f + __expf(-v1));
            float v2 = acc[nt][2] + bv0; v2 = v2 / (1.f + __expf(-v2));
            float v3 = acc[nt][3] + bv1; v3 = v3 / (1.f + __expf(-v3));
            *(u32t*)(outH + p1 + co) = pk_bf16x2(v0, v1);
            *(u32t*)(outH + p2 + co) = pk_bf16x2(v2, v3);
        }
    }
}

// ---------------------------------------------------------------------------
// Stride-1 fused conv3x3 + bias + SiLU (CIN=3) — conv1_n (fp32 path) only.
// ---------------------------------------------------------------------------
template<int CIN, int OUTC>
__global__ void __launch_bounds__(256, 2) convfast(
    const float* __restrict__ in, const float* __restrict__ wgt,
    const float* __restrict__ bias, float* __restrict__ out,
    int Hin, int Win)
{
    constexpr int COG  = 16;
    constexpr int ITX  = 34;
    constexpr int SRS  = 36;
    constexpr int ELEMS = ITX * ITX;
    constexpr int NIT  = (ELEMS + 255) / 256;
    constexpr int PLANE = ITX * SRS;

    extern __shared__ float sIn[];
    __shared__ float sW[2][COG*9 + 8];
    __shared__ int2 tTab[NIT*256];

    const int tid = threadIdx.x;
    const int tx = tid & 7, ty = tid >> 3;
    const int groups = OUTC / COG;
    const int b = blockIdx.z / groups;
    const int cbase = (blockIdx.z % groups) * COG;
    const int X0 = blockIdx.x * 32, Y0 = blockIdx.y * 32;
    const int iy0 = Y0 - 1, ix0 = X0 - 1;
    const size_t HW = (size_t)Hin * Win;
    const float* inb = in + (size_t)b * CIN * HW;

    const int wc = tid / 9, wtap = tid - wc*9;

#pragma unroll
    for (int k = 0; k < NIT; k++) {
        int f = k*256 + tid;
        int sof = -1, gof = -1;
        if (f < ELEMS) {
            int r = f / ITX, c = f - r*ITX;
            int ih = iy0 + r, iw = ix0 + c;
            sof = r*SRS + c;
            gof = ((unsigned)ih < (unsigned)Hin && (unsigned)iw < (unsigned)Win)
                  ? (ih*Win + iw) : -1;
        }
        tTab[k*256 + tid] = make_int2(gof, sof);
    }

    const unsigned sb0 = (unsigned)__cvta_generic_to_shared(sIn);
    auto stage = [&](int buf, int cin) {
        const float* ic = inb + (size_t)cin * HW;
        const unsigned sb = sb0 + (unsigned)buf * (PLANE*4);
#pragma unroll
        for (int k = 0; k < NIT; k++) {
            int2 t = tTab[k*256 + tid];
            if (t.y >= 0)
                cp_async4(sb + (unsigned)t.y*4, ic + (t.x < 0 ? 0 : t.x),
                          t.x < 0 ? 0 : 4);
        }
        if (tid < COG*9) {
            unsigned dst = (unsigned)__cvta_generic_to_shared(
                               &sW[buf][wtap*COG + wc]);
            cp_async4u(dst, wgt + ((size_t)(cbase+wc)*CIN + cin)*9 + wtap);
        }
    };

    stage(0, 0);
    cp_commit();
    cp_wait0();
    __syncthreads();

    u64 acc2[4][8];
#pragma unroll
    for (int j = 0; j < 4; j++)
#pragma unroll
        for (int p = 0; p < 8; p++) acc2[j][p] = 0ull;

    for (int cin = 0; cin < CIN; cin++) {
        const int cur = cin & 1;
        if (cin + 1 < CIN) { stage(cur^1, cin+1); cp_commit(); }

        const float* sc  = sIn + cur*PLANE;
        const float* swp = sW[cur];
#pragma unroll
        for (int dy = 0; dy < 3; dy++) {
            const float* rp = sc + (ty + dy)*SRS + tx*4;
            float4 A = *(const float4*)rp;
            float2 Bv = *(const float2*)(rp + 4);
            float iv6[6] = {A.x, A.y, A.z, A.w, Bv.x, Bv.y};
#pragma unroll
            for (int dx = 0; dx < 3; dx++) {
                const ulonglong2* wq = (const ulonglong2*)(swp + (dy*3+dx)*COG);
                ulonglong2 q0 = wq[0], q1 = wq[1], q2 = wq[2], q3 = wq[3];
#pragma unroll
                for (int j = 0; j < 4; j++)
                    fma2_row(acc2[j], iv6[j+dx], q0, q1, q2, q3);
            }
        }
        if (cin + 1 < CIN) cp_wait0();
        __syncthreads();
    }

    float bv[COG];
#pragma unroll
    for (int c = 0; c < COG; c++) bv[c] = __ldg(bias + cbase + c);

    const int oy = Y0 + ty;
    const int x0 = X0 + tx*4;
#pragma unroll
    for (int c = 0; c < COG; c++) {
        float vv[4];
#pragma unroll
        for (int j = 0; j < 4; j++) {
            float flo, fhi;
            UNPACK2(flo, fhi, acc2[j][c >> 1]);
            float v = ((c & 1) ? fhi : flo) + bv[c];
            vv[j] = v / (1.f + __expf(-v));
        }
        size_t rowbase = ((size_t)(b*OUTC + cbase + c)*258 + (oy+1))*PROW;
        *(float2*)(out + rowbase + 132 + (x0>>1)) = make_float2(vv[0], vv[2]);
        out[rowbase + (x0>>1) + 1] = vv[1];
        out[rowbase + (x0>>1) + 2] = vv[3];
    }
}

// ---------------------------------------------------------------------------
// Stride-2 conv (fp32 FFMA2 path) — conv2_n (16->16) only.
// ---------------------------------------------------------------------------
template<int CIN, int OUTC>
__global__ void __launch_bounds__(256, 2) convfast2(
    const float* __restrict__ in, const float* __restrict__ wgt,
    const float* __restrict__ bias, float* __restrict__ out)
{
    constexpr int COG  = 16;
    constexpr int SRS  = 72;
    constexpr int ODD  = 36;
    constexpr int PLANE = 65*SRS;
    constexpr int NOPS = 65*18;

    extern __shared__ float sIn[];
    __shared__ float sW[2][COG*9 + 8];

    const int tid = threadIdx.x;
    const int tx = tid & 7, ty = tid >> 3;
    const int groups = OUTC / COG;
    const int b = blockIdx.z / groups;
    const int cbase = (blockIdx.z % groups) * COG;
    const int X0 = blockIdx.x * 32, Y0 = blockIdx.y * 32;
    const float* inb = in + (size_t)b * CIN * PCH;

    const int wc = tid / 9, wtap = tid - wc*9;

    int gofs[5]; int sofs[5];
#pragma unroll
    for (int k = 0; k < 5; k++) {
        int id = k*256 + tid;
        if (id < NOPS) {
            int row = id / 18;
            int rem = id - row*18;
            int seg = rem / 9;
            int q   = rem - seg*9;
            gofs[k] = (2*Y0 + row)*PROW + seg*132 + X0 + q*4;
            sofs[k] = (row*SRS + seg*ODD + q*4) * 4;
        } else { gofs[k] = 0; sofs[k] = -1; }
    }

    const unsigned sb0 = (unsigned)__cvta_generic_to_shared(sIn);
    auto stage = [&](int buf, int cin) {
        const float* ic = inb + (size_t)cin * PCH;
        const unsigned sb = sb0 + (unsigned)buf * (PLANE*4);
#pragma unroll
        for (int k = 0; k < 5; k++)
            if (sofs[k] >= 0) cp_async16(sb + (unsigned)sofs[k], ic + gofs[k]);
        if (tid < COG*9) {
            unsigned dst = (unsigned)__cvta_generic_to_shared(
                               &sW[buf][wtap*COG + wc]);
            cp_async4u(dst, wgt + ((size_t)(cbase+wc)*CIN + cin)*9 + wtap);
        }
    };

    stage(0, 0);
    cp_commit();
    cp_wait0();
    __syncthreads();

    u64 acc2[4][8];
#pragma unroll
    for (int j = 0; j < 4; j++)
#pragma unroll
        for (int p = 0; p < 8; p++) acc2[j][p] = 0ull;

    for (int cin = 0; cin < CIN; cin++) {
        const int cur = cin & 1;
        if (cin + 1 < CIN) { stage(cur^1, cin+1); cp_commit(); }

        const float* sc  = sIn + cur*PLANE;
        const float* swp = sW[cur];
#pragma unroll
        for (int dy = 0; dy < 3; dy++) {
            const float* rp = sc + (ty*2 + dy)*SRS;
            float4 E = *(const float4*)(rp + tx*4);
            float  e4 = rp[tx*4 + 4];
            float4 O = *(const float4*)(rp + ODD + tx*4);
            float V[3][4];
            V[0][0]=E.x; V[0][1]=E.y; V[0][2]=E.z; V[0][3]=E.w;
            V[1][0]=O.x; V[1][1]=O.y; V[1][2]=O.z; V[1][3]=O.w;
            V[2][0]=E.y; V[2][1]=E.z; V[2][2]=E.w; V[2][3]=e4;
#pragma unroll
            for (int dx = 0; dx < 3; dx++) {
                const ulonglong2* wq = (const ulonglong2*)(swp + (dy*3+dx)*COG);
                ulonglong2 q0 = wq[0], q1 = wq[1], q2 = wq[2], q3 = wq[3];
#pragma unroll
                for (int j = 0; j < 4; j++)
                    fma2_row(acc2[j], V[dx][j], q0, q1, q2, q3);
            }
        }
        if (cin + 1 < CIN) cp_wait0();
        __syncthreads();
    }

    float bv[COG];
#pragma unroll
    for (int c = 0; c < COG; c++) bv[c] = __ldg(bias + cbase + c);

    const int oy = Y0 + ty;
#pragma unroll
    for (int j = 0; j < 4; j++) {
        float vv[COG];
#pragma unroll
        for (int p = 0; p < 8; p++) {
            float flo, fhi;
            UNPACK2(flo, fhi, acc2[j][p]);
            float v0 = flo + bv[2*p],     v1 = fhi + bv[2*p+1];
            vv[2*p]   = v0 / (1.f + __expf(-v0));
            vv[2*p+1] = v1 / (1.f + __expf(-v1));
        }
        size_t t = ((size_t)b*H2 + oy)*W2 + X0 + tx*4 + j;
        float4* op = (float4*)(out + t*OUTC + cbase);
        op[0] = make_float4(vv[0],  vv[1],  vv[2],  vv[3]);
        op[1] = make_float4(vv[4],  vv[5],  vv[6],  vv[7]);
        op[2] = make_float4(vv[8],  vv[9],  vv[10], vv[11]);
        op[3] = make_float4(vv[12], vv[13], vv[14], vv[15]);
    }
}

// ---------------------------------------------------------------------------
// conv2_s token-GEMM (mma.sync m16n8k16 bf16, single pass — alpha-damped).
// Output t_star stored as bf16 (feeds only the alpha-damped U).
// ---------------------------------------------------------------------------
#define APS 12
#define BPS 12
#define SA_U32 (3*258*APS)          // 9288 u32
#define SB_U32 (9*128*BPS)          // 13824 u32
#define C2_SMEM ((2*(SA_U32 + SB_U32))*4)   // 184896 B

__global__ void __launch_bounds__(256, 1) conv2s_mma(
    const __nv_bfloat16* __restrict__ gh, const u32t* __restrict__ wph,
    const float* __restrict__ bias, __nv_bfloat16* __restrict__ out)
{
    extern __shared__ u32t sm32[];
    u32t* sA[2] = { sm32, sm32 + SA_U32 + SB_U32 };
    u32t* sB[2] = { sm32 + SA_U32, sm32 + 2*SA_U32 + SB_U32 };

    const int tid = threadIdx.x, lane = tid & 31, w = tid >> 5;
    const int y  = blockIdx.x;
    const int b  = blockIdx.y;

    float acc[16][4];
#pragma unroll
    for (int nt = 0; nt < 16; nt++)
#pragma unroll
        for (int r = 0; r < 4; r++) acc[nt][r] = 0.f;

    const int q = lane & 3;
    const int g = lane >> 2;
    const int mlow = 16*w + g;

    auto stage = [&](int buf, int cc) {
        const unsigned aB = (unsigned)__cvta_generic_to_shared(sA[buf]);
        const unsigned bB = (unsigned)__cvta_generic_to_shared(sB[buf]);
        for (int i = tid; i < 1548; i += 256) {
            int pos = i >> 1; int half = i & 1;
            int dy = pos / 258, pl = pos - dy*258;
            size_t gofs = (((size_t)b*NR + (2*y + dy))*NR + pl)*128
                          + cc*16 + half*8;
            cp_async16(aB + (unsigned)(pos*APS*4 + half*16), gh + gofs);
        }
        for (int i = tid; i < 2304; i += 256) {
            int tc = i >> 1; int half = i & 1;
            cp_async16(bB + (unsigned)(tc*BPS*4 + half*16),
                       wph + (cc*1152 + tc)*8 + half*4);
        }
    };

    stage(0, 0);
    cp_commit();
    cp_wait0();
    __syncthreads();

    for (int cc = 0; cc < 8; cc++) {
        const int cur = cc & 1;
        if (cc + 1 < 8) { stage(cur^1, cc+1); cp_commit(); }

        const u32t* sAc = sA[cur];
        const u32t* sBc = sB[cur];
#pragma unroll
        for (int dy = 0; dy < 3; dy++)
#pragma unroll
        for (int dx = 0; dx < 3; dx++) {
            const int tap = dy*3 + dx;
            const int baseA = (dy*258 + 2*mlow + dx) * APS;
            const int baseA8 = baseA + 16*APS;
            u32t a0 = sAc[baseA + q],      a2 = sAc[baseA + q + 4];
            u32t a1 = sAc[baseA8 + q],     a3 = sAc[baseA8 + q + 4];
#pragma unroll
            for (int nt = 0; nt < 16; nt++) {
                int co = 8*nt + g;
                int bb = (tap*128 + co) * BPS;
                u32t b0 = sBc[bb + q], b1 = sBc[bb + q + 4];
                MMA_BF16(acc[nt], a0, a1, a2, a3, b0, b1);
            }
        }
        if (cc + 1 < 8) { cp_wait0(); __syncthreads(); }
    }

    size_t t1 = ((size_t)(b*H2 + y)*W2 + mlow) * 128;
    size_t t2 = t1 + (size_t)8*128;
#pragma unroll
    for (int nt = 0; nt < 16; nt++) {
        int co = 8*nt + 2*q;
        float bv0 = __ldg(bias + co), bv1 = __ldg(bias + co + 1);
        float v0 = acc[nt][0] + bv0; v0 = v0 / (1.f + __expf(-v0));
        float v1 = acc[nt][1] + bv1; v1 = v1 / (1.f + __expf(-v1));
        float v2 = acc[nt][2] + bv0; v2 = v2 / (1.f + __expf(-v2));
        float v3 = acc[nt][3] + bv1; v3 = v3 / (1.f + __expf(-v3));
        *(u32t*)(out + t1 + co) = pk_bf16x2(v0, v1);
        *(u32t*)(out + t2 + co) = pk_bf16x2(v2, v3);
    }
}

// ---------------------------------------------------------------------------
// Legacy conv (final tiny 3->3 decoder conv)
// ---------------------------------------------------------------------------
template<int CIN, int OUTC, int COG>
__global__ void __launch_bounds__(256) conv3x3(
    const float* __restrict__ in, const float* __restrict__ wgt,
    const float* __restrict__ bias, float* __restrict__ out,
    int Hin, int Win)
{
    constexpr int ITD = 18;
    __shared__ float sW[COG*CIN*9];
    __shared__ float sIn[ITD*ITD];

    const int tid = threadIdx.x;
    const int groups = OUTC / COG;
    const int b  = blockIdx.z / groups;
    const int cbase = (blockIdx.z % groups) * COG;

    for (int i = tid; i < COG*CIN*9; i += 256)
        sW[i] = wgt[(size_t)cbase*CIN*9 + i];

    const int ty = tid >> 4, tx = tid & 15;
    const int oy = blockIdx.y*16 + ty;
    const int ox = blockIdx.x*16 + tx;

    float acc[COG];
#pragma unroll
    for (int c = 0; c < COG; c++) acc[c] = 0.f;

    const float* inb = in + (size_t)b * CIN * Hin * Win;
    const int iy0 = blockIdx.y*16 - 1;
    const int ix0 = blockIdx.x*16 - 1;
    const int base = ty*ITD + tx;

    for (int cin = 0; cin < CIN; cin++) {
        __syncthreads();
        const float* ic = inb + (size_t)cin * Hin * Win;
        for (int i = tid; i < ITD*ITD; i += 256) {
            int r = i / ITD, cc = i - r*ITD;
            int ih = iy0 + r, iw = ix0 + cc;
            float v = 0.f;
            if ((unsigned)ih < (unsigned)Hin && (unsigned)iw < (unsigned)Win)
                v = ic[ih*Win + iw];
            sIn[i] = v;
        }
        __syncthreads();
        const float* wp = sW + cin*9;
#pragma unroll
        for (int dy = 0; dy < 3; dy++)
#pragma unroll
            for (int dx = 0; dx < 3; dx++) {
                float iv = sIn[base + dy*ITD + dx];
#pragma unroll
                for (int c = 0; c < COG; c++)
                    acc[c] += iv * wp[c*CIN*9 + dy*3 + dx];
            }
    }

#pragma unroll
    for (int c = 0; c < COG; c++) {
        float v = acc[c] + bias[cbase + c];
        v = v / (1.f + __expf(-v));
        out[(((size_t)b*OUTC + cbase + c)*Hin + oy)*Win + ox] = v;
    }
}

// ---------------------------------------------------------------------------
// Memcell pass 1: w = softmax(z @ K^T / 4) per token.
// ---------------------------------------------------------------------------
__global__ void __launch_bounds__(256) memcell_softmax(
    const float* __restrict__ z, const float* __restrict__ ck,
    float* __restrict__ wout)
{
    __shared__ float sK[Mm*Nn];
    const int tid = threadIdx.x;
    for (int i = tid; i < Mm*Nn; i += 256) sK[i] = ck[i];
    __syncthreads();

    const int t = blockIdx.x*256 + tid;
    const float4* zp = (const float4*)(z + (size_t)t*Nn);
    float4 z0 = zp[0], z1 = zp[1], z2 = zp[2], z3 = zp[3];

    float s[Mm];
    float mx = -1e30f;
#pragma unroll
    for (int m = 0; m < Mm; m++) {
        const float* k = sK + m*Nn;
        float d = z0.x*k[0] + z0.y*k[1] + z0.z*k[2] + z0.w*k[3]
                + z1.x*k[4] + z1.y*k[5] + z1.z*k[6] + z1.w*k[7]
                + z2.x*k[8] + z2.y*k[9] + z2.z*k[10]+ z2.w*k[11]
                + z3.x*k[12]+ z3.y*k[13]+ z3.z*k[14]+ z3.w*k[15];
        d *= 0.25f;
        s[m] = d;
        mx = fmaxf(mx, d);
    }
    float sum = 0.f;
#pragma unroll
    for (int m = 0; m < Mm; m++) { s[m] = __expf(s[m]-mx); sum += s[m]; }
    float inv = 1.f / sum;
    float4* wo = (float4*)(wout + (size_t)t*Mm);
#pragma unroll
    for (int j = 0; j < Mm/4; j++) {
        float4 v; v.x = s[4*j]*inv; v.y = s[4*j+1]*inv;
        v.z = s[4*j+2]*inv; v.w = s[4*j+3]*inv;
        wo[j] = v;
    }
}

// ---------------------------------------------------------------------------
// Memcell pass 2: block partials of [G | U]. t_star read as bf16.
// ---------------------------------------------------------------------------
__global__ void __launch_bounds__(256) memcell_outer(
    const float* __restrict__ wmat, const __nv_bfloat16* __restrict__ tsb,
    float* __restrict__ part)
{
    __shared__ float sv[8*160];
    const int tid = threadIdx.x;
    const int ti = tid >> 5;
    const int tj = tid & 31;
    float acc[4][5];
#pragma unroll
    for (int a = 0; a < 4; a++)
#pragma unroll
        for (int qq = 0; qq < 5; qq++) acc[a][qq] = 0.f;

    const int tokb = blockIdx.x * 128;
    for (int ch = 0; ch < 128; ch += 8) {
        __syncthreads();
#pragma unroll
        for (int l = 0; l < 5; l++) {
            int idx = l*256 + tid;
            int tk = idx / 160, f = idx - tk*160;
            int t = tokb + ch + tk;
            sv[tk*160 + f] = (f < 32)
                ? wmat[(size_t)t*32 + f]
                : __bfloat162float(tsb[(size_t)t*128 + (f-32)]);
        }
        __syncthreads();
#pragma unroll
        for (int tk = 0; tk < 8; tk++) {
            float wi[4], vj[5];
#pragma unroll
            for (int a = 0; a < 4; a++) wi[a] = sv[tk*160 + ti*4 + a];
#pragma unroll
            for (int qq = 0; qq < 5; qq++) vj[qq] = sv[tk*160 + tj*5 + qq];
#pragma unroll
            for (int a = 0; a < 4; a++)
#pragma unroll
                for (int qq = 0; qq < 5; qq++) acc[a][qq] += wi[a]*vj[qq];
        }
    }
    float* pp = part + (size_t)blockIdx.x * 5120;
#pragma unroll
    for (int a = 0; a < 4; a++)
#pragma unroll
        for (int qq = 0; qq < 5; qq++)
            pp[(ti*4+a)*160 + tj*5 + qq] = acc[a][qq];
}

__global__ void __launch_bounds__(256) reduce_partials(
    const float* __restrict__ part, float* __restrict__ gu)
{
    int cell = blockIdx.x*256 + threadIdx.x;
    float s = 0.f;
#pragma unroll 8
    for (int p = 0; p < 1024; p++) s += part[(size_t)p*5120 + cell];
    gu[cell] = s;
}

__global__ void __launch_bounds__(256) cell_update(
    const float* __restrict__ gu, const float* __restrict__ cv,
    float* __restrict__ vnew)
{
    __shared__ float sG[Mm*Mm];
    __shared__ float sV[Mm*Ss];
    const int tid = threadIdx.x;
    for (int i = tid; i < Mm*Mm; i += 256) {
        int m = i >> 5, j = i & 31;
        sG[i] = gu[m*160 + j];
    }
    for (int i = tid; i < Mm*Ss; i += 256) sV[i] = cv[i];
    __syncthreads();
    for (int k = 0; k < 16; k++) {
        int cell = k*256 + tid;
        int m = cell >> 7, s0 = cell & 127;
        float d = gu[m*160 + 32 + s0];
#pragma unroll
        for (int mp = 0; mp < Mm; mp++) d -= sG[m*32 + mp] * sV[mp*128 + s0];
        vnew[cell] = sV[cell] + ALPHA * d;
    }
}

// ---------------------------------------------------------------------------
// Memcell pass 3: t_read = W @ cell_v_new -> NCHW [B,S,H2,W2].
// ---------------------------------------------------------------------------
__global__ void __launch_bounds__(256) memcell_read(
    const float* __restrict__ wmat, const float* __restrict__ vnew,
    float* __restrict__ d0m)
{
    __shared__ float sV[Mm*Ss];
    __shared__ float sW[64*33];
    const int tid = threadIdx.x;
    for (int i = tid; i < Mm*Ss; i += 256) sV[i] = vnew[i];
    const int tbase = blockIdx.x * 64;
    for (int i = tid; i < 64*32; i += 256) {
        int tk = i >> 5, m = i & 31;
        sW[tk*33 + m] = wmat[(size_t)(tbase + tk)*32 + m];
    }
    __syncthreads();

    const int lane = tid & 31, wid = tid >> 5;
    const int cb = wid * 16;
    float a0[16], a1[16];
#pragma unroll
    for (int c = 0; c < 16; c++) { a0[c] = 0.f; a1[c] = 0.f; }

    const float* w0 = sW + lane*33;
    const float* w1 = sW + (lane + 32)*33;
#pragma unroll 4
    for (int m = 0; m < Mm; m++) {
        float x0 = w0[m], x1 = w1[m];
        const float4* vv = (const float4*)(sV + m*128 + cb);
#pragma unroll
        for (int qq = 0; qq < 4; qq++) {
            float4 v = vv[qq];
            a0[qq*4+0] += x0*v.x; a0[qq*4+1] += x0*v.y;
            a0[qq*4+2] += x0*v.z; a0[qq*4+3] += x0*v.w;
            a1[qq*4+0] += x1*v.x; a1[qq*4+1] += x1*v.y;
            a1[qq*4+2] += x1*v.z; a1[qq*4+3] += x1*v.w;
        }
    }
    const int b = tbase >> 14;
    const int rem = tbase & 16383;
    const int h = rem >> 7;
    const int wcp = rem & 127;
    size_t obase = ((size_t)b*Ss)*((size_t)H2*W2) + (size_t)h*W2 + wcp;
#pragma unroll
    for (int c = 0; c < 16; c++) {
        size_t o = obase + (size_t)(cb + c)*(H2*W2);
        d0m[o + lane]      = a0[c];
        d0m[o + 32 + lane] = a1[c];
    }
}

// ---------------------------------------------------------------------------
// ConvTranspose2d(128->3, k4, s2, p1) + bias + SiLU.  32x32 output tiles.
// ---------------------------------------------------------------------------
__global__ void __launch_bounds__(256) deconv_kernel(
    const float* __restrict__ in, const float* __restrict__ dw,
    const float* __restrict__ db, float* __restrict__ out)
{
    __shared__ float sWd[4*128*12];
    __shared__ float sIn[16*324];
    const int tid = threadIdx.x;
    for (int i = tid; i < 4*128*12; i += 256) {
        int p = i / 1536, rem = i - p*1536;
        int cin = rem / 12, rr = rem - cin*12;
        int o = rr >> 2, k = rr & 3;
        int py = p >> 1, px = p & 1;
        int ky = py + 2*(k >> 1), kx = px + 2*(k & 1);
        sWd[i] = dw[cin*48 + o*16 + ky*4 + kx];
    }

    const int b  = blockIdx.z;
    const int Y0 = blockIdx.y*32, X0 = blockIdx.x*32;
    const int ty = tid >> 4, tx = tid & 15;
    const int y0 = Y0 + ty, x0 = X0 + tx;
    const int hb = (Y0 >> 1) - 1, wb = (X0 >> 1) - 1;

    const int py = (y0 + 1) & 1, px = (x0 + 1) & 1;
    const int hs0 = ((y0 + 1 - py) >> 1) - hb;
    const int ws0 = ((x0 + 1 - px) >> 1) - wb;

    const float* wp = sWd + (py*2 + px)*1536;
    float acc[2][2][3];
#pragma unroll
    for (int a = 0; a < 2; a++)
#pragma unroll
        for (int e = 0; e < 2; e++)
#pragma unroll
            for (int o = 0; o < 3; o++) acc[a][e][o] = 0.f;

    const float* inb = in + (size_t)b * Ss * H2 * W2;

    for (int c0 = 0; c0 < Ss; c0 += 16) {
        __syncthreads();
        for (int i = tid; i < 16*324; i += 256) {
            int c = i / 324, rr = i - c*324;
            int r = rr / 18, cc = rr - r*18;
            int h = hb + r, w = wb + cc;
            float v = 0.f;
            if ((unsigned)h < (unsigned)H2 && (unsigned)w < (unsigned)W2)
                v = inb[((size_t)(c0 + c)*H2 + h)*W2 + w];
            sIn[i] = v;
        }
        __syncthreads();
#pragma unroll
        for (int c = 0; c < 16; c++) {
            const float* sc = sIn + c*324;
            const float4* w4 = (const float4*)(wp + (c0 + c)*12);
            float4 Wa = w4[0], Wb = w4[1], Wc = w4[2];
#pragma unroll
            for (int a = 0; a < 2; a++)
#pragma unroll
                for (int e = 0; e < 2; e++) {
                    int hh = hs0 + 8*a, ww = ws0 + 8*e;
                    float i00 = sc[hh*18 + ww];
                    float i01 = sc[hh*18 + ww - 1];
                    float i10 = sc[(hh-1)*18 + ww];
                    float i11 = sc[(hh-1)*18 + ww - 1];
                    acc[a][e][0] += i00*Wa.x + i01*Wa.y + i10*Wa.z + i11*Wa.w;
                    acc[a][e][1] += i00*Wb.x + i01*Wb.y + i10*Wb.z + i11*Wb.w;
                    acc[a][e][2] += i00*Wc.x + i01*Wc.y + i10*Wc.z + i11*Wc.w;
                }
        }
    }
#pragma unroll
    for (int a = 0; a < 2; a++)
#pragma unroll
        for (int e = 0; e < 2; e++)
#pragma unroll
            for (int o = 0; o < 3; o++) {
                float v = acc[a][e][o] + db[o];
                v = v / (1.f + __expf(-v));
                out[(((size_t)b*3 + o)*HIN + y0 + 16*a)*WIN + x0 + 16*e] = v;
            }
}

// ---------------------------------------------------------------------------
// Launch sequence
// ---------------------------------------------------------------------------
extern "C" void kernel_launch(void* const* d_in, const int* in_sizes, int n_in,
                              void* d_out, int out_size)
{
    const float* x      = (const float*)d_in[0];
    const float* e0n_w1 = (const float*)d_in[1];
    const float* e0n_b1 = (const float*)d_in[2];
    const float* e0n_w2 = (const float*)d_in[3];
    const float* e0n_b2 = (const float*)d_in[4];
    const float* e0s_w1 = (const float*)d_in[5];
    const float* e0s_b1 = (const float*)d_in[6];
    const float* e0s_w2 = (const float*)d_in[7];
    const float* e0s_b2 = (const float*)d_in[8];
    const float* d0_dw  = (const float*)d_in[9];
    const float* d0_db  = (const float*)d_in[10];
    const float* d0_cw  = (const float*)d_in[11];
    const float* d0_cb  = (const float*)d_in[12];
    const float* cell_k = (const float*)d_in[13];
    const float* cell_v = (const float*)d_in[14];
    float* outp = (float*)d_out;

    void *p_a1n, *p_hi, *p_wph, *p_wp1, *p_z, *p_tsb, *p_w,
         *p_part, *p_gu, *p_vnew, *p_d0m, *p_dec;
    cudaGetSymbolAddress(&p_a1n, g_a1n);
    cudaGetSymbolAddress(&p_hi,  g_hi);
    cudaGetSymbolAddress(&p_wph, g_wph);
    cudaGetSymbolAddress(&p_wp1, g_wp1);
    cudaGetSymbolAddress(&p_z,   g_z);
    cudaGetSymbolAddress(&p_tsb, g_tsb);
    cudaGetSymbolAddress(&p_w,   g_w);
    cudaGetSymbolAddress(&p_part,g_part);
    cudaGetSymbolAddress(&p_gu,  g_gu);
    cudaGetSymbolAddress(&p_vnew,g_vnew);
    cudaGetSymbolAddress(&p_d0m, g_d0m);
    cudaGetSymbolAddress(&p_dec, g_dec);

    const int dsm_s1 = 2 * 34 * 36 * 4;   //  9792 B
    const int dsm_s2 = 2 * 65 * 72 * 4;   // 37440 B

    cudaFuncSetAttribute((const void*)convfast<3,16>,
                         cudaFuncAttributeMaxDynamicSharedMemorySize, dsm_s1);
    cudaFuncSetAttribute((const void*)convfast2<16,16>,
                         cudaFuncAttributeMaxDynamicSharedMemorySize, dsm_s2);
    cudaFuncSetAttribute((const void*)conv2s_mma,
                         cudaFuncAttributeMaxDynamicSharedMemorySize, C2_SMEM);

    // Prep: borders + packed weights
    zero_borders<<<Bb*Nn, 256>>>((float*)p_a1n);
    zb_nhwc<<<Bb, 256>>>((__nv_bfloat16*)p_hi);
    wprep<<<288, 256>>>(e0s_w2, (u32t*)p_wph);
    wprep1<<<8, 256>>>(e0s_w1, (u32t*)p_wp1);

    // Encoders
    convfast<3,16><<<dim3(8,8,Bb),256,dsm_s1>>>(
        x, e0n_w1, e0n_b1, (float*)p_a1n, HIN, WIN);
    conv1s_mma<<<dim3(HIN,Bb),256>>>(
        x, (const u32t*)p_wp1, e0s_b1, (__nv_bfloat16*)p_hi);
    convfast2<16,16><<<dim3(4,4,Bb),256,dsm_s2>>>(
        (const float*)p_a1n, e0n_w2, e0n_b2, (float*)p_z);
    conv2s_mma<<<dim3(128,Bb),256,C2_SMEM>>>(
        (const __nv_bfloat16*)p_hi, (const u32t*)p_wph, e0s_b2,
        (__nv_bfloat16*)p_tsb);

    // Memcell
    memcell_softmax<<<Tt/256,256>>>((const float*)p_z, cell_k, (float*)p_w);
    memcell_outer<<<1024,256>>>((const float*)p_w,
        (const __nv_bfloat16*)p_tsb, (float*)p_part);
    reduce_partials<<<20,256>>>((const float*)p_part, (float*)p_gu);
    cell_update<<<1,256>>>((const float*)p_gu, cell_v, (float*)p_vnew);
    memcell_read<<<Tt/64,256>>>((const float*)p_w, (const float*)p_vnew, (float*)p_d0m);

    // Decoder
    deconv_kernel<<<dim3(8,8,Bb),256>>>(
        (const float*)p_d0m, d0_dw, d0_db, (float*)p_dec);
    conv3x3<3,3,3><<<dim3(16,16,Bb),256>>>(
        (const float*)p_dec, d0_cw, d0_cb, outp, HIN, WIN);
}